// round 1
// baseline (speedup 1.0000x reference)
#include <cuda_runtime.h>
#include <math.h>

#define D_MODEL 1024
#define NHEAD   16
#define DK      64
#define DFF     4096
#define SEQ     2048
#define BATCH   2
#define ROWS    (BATCH*SEQ)          // 4096
#define EPS     1e-5f

// ---------------- scratch (no allocation allowed) ----------------
__device__ float g_Q  [(size_t)ROWS*D_MODEL];
__device__ float g_K  [(size_t)ROWS*D_MODEL];
__device__ float g_V  [(size_t)ROWS*D_MODEL];
__device__ float g_ctx[(size_t)ROWS*D_MODEL];
__device__ float g_h  [(size_t)ROWS*D_MODEL];
__device__ float g_t  [(size_t)ROWS*D_MODEL];
__device__ float g_ff [(size_t)ROWS*DFF];
__device__ float g_attn_scratch[(size_t)BATCH*NHEAD*SEQ*SEQ]; // fallback if d_out has no attn region

// ---------------- generic SGEMM: C = A[M,K] @ B[K,N] + bias, optional ReLU ----------------
// BM=BN=128, BK=16, 256 threads, 8x8 per thread, float4 everywhere.
template<bool RELU>
__global__ __launch_bounds__(256) void sgemm(
    const float* __restrict__ A, const float* __restrict__ B,
    const float* __restrict__ bias, float* __restrict__ C,
    int M, int N, int K)
{
    __shared__ float As[16][128];
    __shared__ float Bs[16][128];
    const int tid = threadIdx.x;
    const int m0 = blockIdx.y * 128;
    const int n0 = blockIdx.x * 128;
    const int tx = tid & 15;   // 0..15 -> n micro
    const int ty = tid >> 4;   // 0..15 -> m micro

    float acc[8][8];
#pragma unroll
    for (int i = 0; i < 8; i++)
#pragma unroll
        for (int j = 0; j < 8; j++) acc[i][j] = 0.f;

    for (int kk = 0; kk < K; kk += 16) {
        // A tile: 128 rows x 16 cols = 512 float4; 2 per thread; store transposed
#pragma unroll
        for (int l = 0; l < 2; l++) {
            int idx = tid + l * 256;
            int row = idx >> 2, c4 = idx & 3;
            float4 v = *(const float4*)(A + (size_t)(m0 + row) * K + kk + c4 * 4);
            As[c4 * 4 + 0][row] = v.x;
            As[c4 * 4 + 1][row] = v.y;
            As[c4 * 4 + 2][row] = v.z;
            As[c4 * 4 + 3][row] = v.w;
        }
        // B tile: 16 rows x 128 cols = 512 float4
#pragma unroll
        for (int l = 0; l < 2; l++) {
            int idx = tid + l * 256;
            int row = idx >> 5, c4 = idx & 31;
            *(float4*)(&Bs[row][c4 * 4]) =
                *(const float4*)(B + (size_t)(kk + row) * N + n0 + c4 * 4);
        }
        __syncthreads();
#pragma unroll
        for (int k = 0; k < 16; k++) {
            float4 a0 = *(const float4*)(&As[k][ty * 8]);
            float4 a1 = *(const float4*)(&As[k][ty * 8 + 4]);
            float4 b0 = *(const float4*)(&Bs[k][tx * 8]);
            float4 b1 = *(const float4*)(&Bs[k][tx * 8 + 4]);
            float a[8] = {a0.x,a0.y,a0.z,a0.w,a1.x,a1.y,a1.z,a1.w};
            float b[8] = {b0.x,b0.y,b0.z,b0.w,b1.x,b1.y,b1.z,b1.w};
#pragma unroll
            for (int i = 0; i < 8; i++)
#pragma unroll
                for (int j = 0; j < 8; j++)
                    acc[i][j] = fmaf(a[i], b[j], acc[i][j]);
        }
        __syncthreads();
    }

    float bj[8];
#pragma unroll
    for (int j = 0; j < 8; j++) bj[j] = bias[n0 + tx * 8 + j];
#pragma unroll
    for (int i = 0; i < 8; i++) {
        int m = m0 + ty * 8 + i;
        float* crow = C + (size_t)m * N + n0 + tx * 8;
        float4 o0, o1;
        float v;
        v = acc[i][0] + bj[0]; o0.x = RELU ? fmaxf(v, 0.f) : v;
        v = acc[i][1] + bj[1]; o0.y = RELU ? fmaxf(v, 0.f) : v;
        v = acc[i][2] + bj[2]; o0.z = RELU ? fmaxf(v, 0.f) : v;
        v = acc[i][3] + bj[3]; o0.w = RELU ? fmaxf(v, 0.f) : v;
        v = acc[i][4] + bj[4]; o1.x = RELU ? fmaxf(v, 0.f) : v;
        v = acc[i][5] + bj[5]; o1.y = RELU ? fmaxf(v, 0.f) : v;
        v = acc[i][6] + bj[6]; o1.z = RELU ? fmaxf(v, 0.f) : v;
        v = acc[i][7] + bj[7]; o1.w = RELU ? fmaxf(v, 0.f) : v;
        *(float4*)(crow)     = o0;
        *(float4*)(crow + 4) = o1;
    }
}

// ---------------- scores: attn_raw[b,h,i,j] = (Q_h[i,:] . K_h[j,:]) / 8, masked ----------------
__global__ __launch_bounds__(256) void scores_kernel(const int* __restrict__ mask,
                                                     float* __restrict__ attn)
{
    __shared__ float Qs[64][65];
    __shared__ float Ks[64][65];
    const int z = blockIdx.z;            // b*16 + h
    const int b = z >> 4, h = z & 15;
    const int i0 = blockIdx.y * 64;
    const int j0 = blockIdx.x * 64;
    const int tid = threadIdx.x;
    const float* Qb = g_Q + (size_t)b * SEQ * D_MODEL + h * DK;
    const float* Kb = g_K + (size_t)b * SEQ * D_MODEL + h * DK;

    for (int t = tid; t < 64 * 64; t += 256) {
        int r = t >> 6, c = t & 63;
        Qs[r][c] = Qb[(size_t)(i0 + r) * D_MODEL + c];
        Ks[r][c] = Kb[(size_t)(j0 + r) * D_MODEL + c];
    }
    __syncthreads();

    const int tx = tid & 15, ty = tid >> 4;
    float acc[4][4] = {};
#pragma unroll
    for (int k = 0; k < 64; k++) {
        float a[4], bb[4];
#pragma unroll
        for (int i = 0; i < 4; i++) a[i] = Qs[ty * 4 + i][k];
#pragma unroll
        for (int j = 0; j < 4; j++) bb[j] = Ks[tx * 4 + j][k];
#pragma unroll
        for (int i = 0; i < 4; i++)
#pragma unroll
            for (int j = 0; j < 4; j++)
                acc[i][j] = fmaf(a[i], bb[j], acc[i][j]);
    }

    float* ab = attn + (size_t)z * SEQ * SEQ;
    const int* mb = mask + b * SEQ;
#pragma unroll
    for (int i = 0; i < 4; i++) {
        int r = i0 + ty * 4 + i;
#pragma unroll
        for (int j = 0; j < 4; j++) {
            int c = j0 + tx * 4 + j;
            float v = acc[i][j] * 0.125f;     // 1/sqrt(64)
            if (mb[c] == 0) v = -1e9f;
            ab[(size_t)r * SEQ + c] = v;
        }
    }
}

// ---------------- row softmax, in place over [B*H*S, S] ----------------
__global__ __launch_bounds__(256) void softmax_kernel(float* __restrict__ attn)
{
    const size_t row = blockIdx.x;
    float* p = attn + row * SEQ;
    const int tid = threadIdx.x;
    const int lane = tid & 31, wid = tid >> 5;
    __shared__ float red[8];

    float v[8];
    float mx = -3.4e38f;
#pragma unroll
    for (int e = 0; e < 8; e++) { v[e] = p[tid + e * 256]; mx = fmaxf(mx, v[e]); }
#pragma unroll
    for (int o = 16; o > 0; o >>= 1) mx = fmaxf(mx, __shfl_xor_sync(0xffffffffu, mx, o));
    if (lane == 0) red[wid] = mx;
    __syncthreads();
    float m2 = red[0];
#pragma unroll
    for (int w = 1; w < 8; w++) m2 = fmaxf(m2, red[w]);
    __syncthreads();

    float s = 0.f;
#pragma unroll
    for (int e = 0; e < 8; e++) { v[e] = __expf(v[e] - m2); s += v[e]; }
#pragma unroll
    for (int o = 16; o > 0; o >>= 1) s += __shfl_xor_sync(0xffffffffu, s, o);
    if (lane == 0) red[wid] = s;
    __syncthreads();
    float tot = 0.f;
#pragma unroll
    for (int w = 0; w < 8; w++) tot += red[w];
    float inv = 1.0f / tot;
#pragma unroll
    for (int e = 0; e < 8; e++) p[tid + e * 256] = v[e] * inv;
}

// ---------------- ctx[b,h] = attn[b,h] @ V_h  (M=2048,N=64,K=2048) ----------------
__global__ __launch_bounds__(256) void ctx_kernel(const float* __restrict__ attn)
{
    __shared__ float Ats[64][65];   // [i][k]
    __shared__ float Vs[64][65];    // [k][n]
    const int z = blockIdx.z, b = z >> 4, h = z & 15;
    const int i0 = blockIdx.y * 64;
    const float* ab = attn + (size_t)z * SEQ * SEQ;
    const float* Vb = g_V + (size_t)b * SEQ * D_MODEL + h * DK;
    const int tid = threadIdx.x;
    const int tx = tid & 15, ty = tid >> 4;
    float acc[4][4] = {};

    for (int kk = 0; kk < SEQ; kk += 64) {
        for (int t = tid; t < 64 * 64; t += 256) {
            int r = t >> 6, c = t & 63;
            Ats[r][c] = ab[(size_t)(i0 + r) * SEQ + kk + c];
            Vs[r][c]  = Vb[(size_t)(kk + r) * D_MODEL + c];
        }
        __syncthreads();
#pragma unroll
        for (int k = 0; k < 64; k++) {
            float a[4], bb[4];
#pragma unroll
            for (int i = 0; i < 4; i++) a[i] = Ats[ty * 4 + i][k];
#pragma unroll
            for (int j = 0; j < 4; j++) bb[j] = Vs[k][tx * 4 + j];
#pragma unroll
            for (int i = 0; i < 4; i++)
#pragma unroll
                for (int j = 0; j < 4; j++)
                    acc[i][j] = fmaf(a[i], bb[j], acc[i][j]);
        }
        __syncthreads();
    }
    float* cb = g_ctx + (size_t)b * SEQ * D_MODEL + h * DK;
#pragma unroll
    for (int i = 0; i < 4; i++)
#pragma unroll
        for (int j = 0; j < 4; j++)
            cb[(size_t)(i0 + ty * 4 + i) * D_MODEL + tx * 4 + j] = acc[i][j];
}

// ---------------- out = LayerNorm(X + Y) * gamma + beta, per row of 1024 ----------------
__global__ __launch_bounds__(256) void add_ln_kernel(const float* __restrict__ X,
                                                     const float* __restrict__ Y,
                                                     const float* __restrict__ gamma,
                                                     const float* __restrict__ beta,
                                                     float* __restrict__ out)
{
    const int row = blockIdx.x;
    const int tid = threadIdx.x;
    const int lane = tid & 31, wid = tid >> 5;
    __shared__ float red[8];

    const float* xr = X + (size_t)row * D_MODEL;
    const float* yr = Y + (size_t)row * D_MODEL;
    float4 xv = *(const float4*)(xr + tid * 4);
    float4 yv = *(const float4*)(yr + tid * 4);
    float v0 = xv.x + yv.x, v1 = xv.y + yv.y, v2 = xv.z + yv.z, v3 = xv.w + yv.w;

    float s = v0 + v1 + v2 + v3;
#pragma unroll
    for (int o = 16; o > 0; o >>= 1) s += __shfl_xor_sync(0xffffffffu, s, o);
    if (lane == 0) red[wid] = s;
    __syncthreads();
    float tot = 0.f;
#pragma unroll
    for (int w = 0; w < 8; w++) tot += red[w];
    float mu = tot * (1.0f / D_MODEL);
    __syncthreads();

    float d0 = v0 - mu, d1 = v1 - mu, d2 = v2 - mu, d3 = v3 - mu;
    float sq = d0 * d0 + d1 * d1 + d2 * d2 + d3 * d3;
#pragma unroll
    for (int o = 16; o > 0; o >>= 1) sq += __shfl_xor_sync(0xffffffffu, sq, o);
    if (lane == 0) red[wid] = sq;
    __syncthreads();
    float vtot = 0.f;
#pragma unroll
    for (int w = 0; w < 8; w++) vtot += red[w];
    float inv = rsqrtf(vtot * (1.0f / D_MODEL) + EPS);

    float4 gv = *(const float4*)(gamma + tid * 4);
    float4 bv = *(const float4*)(beta + tid * 4);
    float4 o4;
    o4.x = d0 * inv * gv.x + bv.x;
    o4.y = d1 * inv * gv.y + bv.y;
    o4.z = d2 * inv * gv.z + bv.z;
    o4.w = d3 * inv * gv.w + bv.w;
    *(float4*)(out + (size_t)row * D_MODEL + tid * 4) = o4;
}

// ---------------- host ----------------
extern "C" void kernel_launch(void* const* d_in, const int* in_sizes, int n_in,
                              void* d_out, int out_size)
{
    const float* x   = (const float*)d_in[0];
    const int*   msk = (const int*)  d_in[1];
    const float* Wq  = (const float*)d_in[2];
    const float* bq  = (const float*)d_in[3];
    const float* Wk  = (const float*)d_in[4];
    const float* bk  = (const float*)d_in[5];
    const float* Wv  = (const float*)d_in[6];
    const float* bv  = (const float*)d_in[7];
    const float* Wo  = (const float*)d_in[8];
    const float* bo  = (const float*)d_in[9];
    const float* g1  = (const float*)d_in[10];
    const float* be1 = (const float*)d_in[11];
    const float* W1  = (const float*)d_in[12];
    const float* b1  = (const float*)d_in[13];
    const float* W2  = (const float*)d_in[14];
    const float* b2  = (const float*)d_in[15];
    const float* g2  = (const float*)d_in[16];
    const float* be2 = (const float*)d_in[17];

    float* out = (float*)d_out;

    void *pQ, *pK, *pV, *pCtx, *pH, *pT, *pFF, *pAttnScratch;
    cudaGetSymbolAddress(&pQ,   g_Q);
    cudaGetSymbolAddress(&pK,   g_K);
    cudaGetSymbolAddress(&pV,   g_V);
    cudaGetSymbolAddress(&pCtx, g_ctx);
    cudaGetSymbolAddress(&pH,   g_h);
    cudaGetSymbolAddress(&pT,   g_t);
    cudaGetSymbolAddress(&pFF,  g_ff);
    cudaGetSymbolAddress(&pAttnScratch, g_attn_scratch);

    const size_t OUT_ELEMS  = (size_t)ROWS * D_MODEL;                 // 4,194,304
    const size_t ATTN_ELEMS = (size_t)BATCH * NHEAD * SEQ * SEQ;      // 134,217,728
    float* attn = ((size_t)out_size >= OUT_ELEMS + ATTN_ELEMS)
                      ? out + OUT_ELEMS
                      : (float*)pAttnScratch;

    dim3 blk(256);
    dim3 gProj(D_MODEL / 128, ROWS / 128);   // (8, 32)
    dim3 gFF1 (DFF / 128,     ROWS / 128);   // (32, 32)

    // QKV projections
    sgemm<false><<<gProj, blk>>>(x, Wq, bq, (float*)pQ, ROWS, D_MODEL, D_MODEL);
    sgemm<false><<<gProj, blk>>>(x, Wk, bk, (float*)pK, ROWS, D_MODEL, D_MODEL);
    sgemm<false><<<gProj, blk>>>(x, Wv, bv, (float*)pV, ROWS, D_MODEL, D_MODEL);

    // scores (+scale +mask)
    scores_kernel<<<dim3(SEQ / 64, SEQ / 64, BATCH * NHEAD), blk>>>(msk, attn);
    // softmax in place
    softmax_kernel<<<dim3(BATCH * NHEAD * SEQ), blk>>>(attn);
    // ctx = attn @ V
    ctx_kernel<<<dim3(1, SEQ / 64, BATCH * NHEAD), blk>>>(attn);

    // output projection + residual + LN
    sgemm<false><<<gProj, blk>>>((const float*)pCtx, Wo, bo, (float*)pT, ROWS, D_MODEL, D_MODEL);
    add_ln_kernel<<<ROWS, blk>>>(x, (const float*)pT, g1, be1, (float*)pH);

    // FFN
    sgemm<true ><<<gFF1,  blk>>>((const float*)pH,  W1, b1, (float*)pFF, ROWS, DFF,     D_MODEL);
    sgemm<false><<<gProj, blk>>>((const float*)pFF, W2, b2, (float*)pT,  ROWS, D_MODEL, DFF);
    add_ln_kernel<<<ROWS, blk>>>((const float*)pH, (const float*)pT, g2, be2, out);
}

// round 4
// speedup vs baseline: 2.1249x; 2.1249x over previous
#include <cuda_runtime.h>
#include <cuda_bf16.h>
#include <math.h>

#define D_MODEL 1024
#define NHEAD   16
#define DK      64
#define DFF     4096
#define SEQ     2048
#define BATCH   2
#define ROWS    (BATCH*SEQ)
#define EPS     1e-5f
#define HZ      (BATCH*NHEAD)

// ---------------- scratch (no allocation allowed) ----------------
__device__ __align__(256) float g_V [(size_t)ROWS*D_MODEL];
__device__ __align__(256) float g_t [(size_t)ROWS*D_MODEL];
__device__ __align__(256) float g_h [(size_t)ROWS*D_MODEL];
__device__ __align__(256) float g_attn_f32[(size_t)HZ*SEQ*SEQ];  // fallback only
__device__ __align__(256) __nv_bfloat16 g_xc_h [(size_t)ROWS*D_MODEL], g_xc_l [(size_t)ROWS*D_MODEL];
__device__ __align__(256) __nv_bfloat16 g_Wqt_h[(size_t)D_MODEL*D_MODEL], g_Wqt_l[(size_t)D_MODEL*D_MODEL];
__device__ __align__(256) __nv_bfloat16 g_Wkt_h[(size_t)D_MODEL*D_MODEL], g_Wkt_l[(size_t)D_MODEL*D_MODEL];
__device__ __align__(256) __nv_bfloat16 g_Wvt_h[(size_t)D_MODEL*D_MODEL], g_Wvt_l[(size_t)D_MODEL*D_MODEL];
__device__ __align__(256) __nv_bfloat16 g_Wot_h[(size_t)D_MODEL*D_MODEL], g_Wot_l[(size_t)D_MODEL*D_MODEL];
__device__ __align__(256) __nv_bfloat16 g_W1t_h[(size_t)D_MODEL*DFF],     g_W1t_l[(size_t)D_MODEL*DFF];
__device__ __align__(256) __nv_bfloat16 g_W2t_h[(size_t)D_MODEL*DFF],     g_W2t_l[(size_t)D_MODEL*DFF];
__device__ __align__(256) __nv_bfloat16 g_Qc_h [(size_t)ROWS*D_MODEL], g_Qc_l [(size_t)ROWS*D_MODEL];
__device__ __align__(256) __nv_bfloat16 g_Kc_h [(size_t)ROWS*D_MODEL], g_Kc_l [(size_t)ROWS*D_MODEL];
__device__ __align__(256) __nv_bfloat16 g_Vt_h [(size_t)HZ*DK*SEQ],    g_Vt_l [(size_t)HZ*DK*SEQ];
__device__ __align__(256) __nv_bfloat16 g_attn_h[(size_t)HZ*SEQ*SEQ],  g_attn_l[(size_t)HZ*SEQ*SEQ];
__device__ __align__(256) __nv_bfloat16 g_ctx_h[(size_t)ROWS*D_MODEL], g_ctx_l[(size_t)ROWS*D_MODEL];
__device__ __align__(256) __nv_bfloat16 g_hc_h [(size_t)ROWS*D_MODEL], g_hc_l [(size_t)ROWS*D_MODEL];
__device__ __align__(256) __nv_bfloat16 g_ff_h [(size_t)ROWS*DFF],     g_ff_l [(size_t)ROWS*DFF];

// ---------------- helpers ----------------
__device__ __forceinline__ unsigned s2u(const void* p){
    unsigned a;
    asm("{ .reg .u64 t; cvta.to.shared.u64 t, %1; cvt.u32.u64 %0, t; }" : "=r"(a) : "l"(p));
    return a;
}
__device__ __forceinline__ void cpa(unsigned s, const void* g){
    asm volatile("cp.async.cg.shared.global [%0], [%1], 16;" :: "r"(s), "l"(g));
}
__device__ __forceinline__ void ldmx4(unsigned* r, unsigned addr){
    asm volatile("ldmatrix.sync.aligned.m8n8.x4.shared.b16 {%0,%1,%2,%3}, [%4];"
        : "=r"(r[0]), "=r"(r[1]), "=r"(r[2]), "=r"(r[3]) : "r"(addr));
}
__device__ __forceinline__ void mma16816(float* c, const unsigned* a, unsigned b0, unsigned b1){
    asm volatile("mma.sync.aligned.m16n8k16.row.col.f32.bf16.bf16.f32 "
        "{%0,%1,%2,%3}, {%4,%5,%6,%7}, {%8,%9}, {%0,%1,%2,%3};"
        : "+f"(c[0]), "+f"(c[1]), "+f"(c[2]), "+f"(c[3])
        : "r"(a[0]), "r"(a[1]), "r"(a[2]), "r"(a[3]), "r"(b0), "r"(b1));
}
__device__ __forceinline__ void split_store2(float v0, float v1,
                                             __nv_bfloat16* hi, __nv_bfloat16* lo){
    __nv_bfloat16 h0 = __float2bfloat16(v0), h1 = __float2bfloat16(v1);
    __nv_bfloat162 hp, lp;
    hp.x = h0; hp.y = h1;
    lp.x = __float2bfloat16(v0 - __bfloat162float(h0));
    lp.y = __float2bfloat16(v1 - __bfloat162float(h1));
    *(__nv_bfloat162*)hi = hp;
    *(__nv_bfloat162*)lo = lp;
}

// ================= split-bf16 HMMA GEMM =================
// D[128, BN] per CTA = A @ B^T; A[m][k], B[n][k] bf16 hi/lo; fp32 accum.
// EPI: 0 fp32+bias | 1 bf16split+bias | 2 bf16split+bias+relu | 3 fp32 scale+mask | 4 bf16split
// AOFF/BOFF/COFF: 0 -> z*stride, 1 -> head mode ((z>>4)*SEQ*D_MODEL + (z&15)*64)
template<int BN, int EPI, int AOFF, int BOFF, int COFF>
__global__ void __launch_bounds__(256) gemm_mm(
    const __nv_bfloat16* __restrict__ Ah, const __nv_bfloat16* __restrict__ Al, int lda, long long sAz,
    const __nv_bfloat16* __restrict__ Bh, const __nv_bfloat16* __restrict__ Bl, int ldb, long long sBz,
    float* __restrict__ Cf, __nv_bfloat16* __restrict__ Chi, __nv_bfloat16* __restrict__ Clo,
    long long sCz, int ldc,
    const float* __restrict__ bias, const int* __restrict__ mask, int K)
{
    constexpr int NT = BN / 16;            // n8 tiles per warp (8 or 4)
    constexpr int ABYTES = 128 * 80;       // 10240 per component
    constexpr int BBYTES = BN * 80;
    constexpr int BUFB = 2 * ABYTES + 2 * BBYTES;
    extern __shared__ __align__(128) char smem[];
    const unsigned sb = s2u(smem);
    const int tid = threadIdx.x;
    const int m0 = blockIdx.y * 128, n0 = blockIdx.x * BN, z = blockIdx.z;

    size_t ao = (AOFF == 1) ? ((size_t)(z >> 4) * SEQ * D_MODEL + (size_t)(z & 15) * DK) : (size_t)z * sAz;
    size_t bo = (BOFF == 1) ? ((size_t)(z >> 4) * SEQ * D_MODEL + (size_t)(z & 15) * DK) : (size_t)z * sBz;
    size_t co = (COFF == 1) ? ((size_t)(z >> 4) * SEQ * D_MODEL + (size_t)(z & 15) * DK) : (size_t)z * sCz;

    const int lane = tid & 31, w = tid >> 5;
    const int warp_m = w & 3, warp_n = w >> 2;

    float acc[2][NT][4];
#pragma unroll
    for (int mt = 0; mt < 2; mt++)
#pragma unroll
        for (int nt = 0; nt < NT; nt++)
#pragma unroll
            for (int e = 0; e < 4; e++) acc[mt][nt][e] = 0.f;

    const int nchunk = K >> 5;

    // -------- tile loader (cp.async, 16B chunks, 80B row pitch) --------
    auto load_tile = [&](int c, int buf) {
        unsigned sbuf = sb + buf * BUFB;
        const __nv_bfloat16* pah = Ah + ao + (size_t)m0 * lda + c * 32;
        const __nv_bfloat16* pal = Al + ao + (size_t)m0 * lda + c * 32;
#pragma unroll
        for (int i = 0; i < 2; i++) {
            int idx = tid + i * 256;         // 512 chunks: 128 rows x 4
            int row = idx >> 2, ch = idx & 3;
            unsigned so = row * 80 + ch * 16;
            cpa(sbuf + so,          pah + (size_t)row * lda + ch * 8);
            cpa(sbuf + ABYTES + so, pal + (size_t)row * lda + ch * 8);
        }
        const __nv_bfloat16* pbh = Bh + bo + (size_t)n0 * ldb + c * 32;
        const __nv_bfloat16* pbl = Bl + bo + (size_t)n0 * ldb + c * 32;
#pragma unroll
        for (int i = 0; i < BN / 64; i++) {
            int idx = tid + i * 256;         // BN rows x 4 chunks
            int row = idx >> 2, ch = idx & 3;
            unsigned so = row * 80 + ch * 16;
            cpa(sbuf + 2 * ABYTES + so,          pbh + (size_t)row * ldb + ch * 8);
            cpa(sbuf + 2 * ABYTES + BBYTES + so, pbl + (size_t)row * ldb + ch * 8);
        }
    };

    load_tile(0, 0);
    asm volatile("cp.async.commit_group;");

    for (int c = 0; c < nchunk; c++) {
        if (c + 1 < nchunk) {
            load_tile(c + 1, (c + 1) & 1);
            asm volatile("cp.async.commit_group;");
            asm volatile("cp.async.wait_group 1;");
        } else {
            asm volatile("cp.async.wait_group 0;");
        }
        __syncthreads();

        unsigned sbuf = sb + (c & 1) * BUFB;
        // ldmatrix base addresses
        unsigned sa  = sbuf + (warp_m * 32 + (lane & 15)) * 80 + (lane >> 4) * 16;
        unsigned sbb = sbuf + 2 * ABYTES
                     + (warp_n * (NT * 8) + (lane & 7) + ((lane >> 4) << 3)) * 80
                     + ((lane >> 3) & 1) * 16;
#pragma unroll
        for (int ks = 0; ks < 2; ks++) {
            unsigned ah[2][4], al[2][4];
            ldmx4(ah[0], sa + ks * 32);
            ldmx4(ah[1], sa + 16 * 80 + ks * 32);
            ldmx4(al[0], sa + ABYTES + ks * 32);
            ldmx4(al[1], sa + ABYTES + 16 * 80 + ks * 32);
#pragma unroll
            for (int p = 0; p < NT / 2; p++) {
                unsigned bh[4], bl[4];
                ldmx4(bh, sbb + p * 16 * 80 + ks * 32);
                ldmx4(bl, sbb + BBYTES + p * 16 * 80 + ks * 32);
#pragma unroll
                for (int mt = 0; mt < 2; mt++)
#pragma unroll
                    for (int t = 0; t < 2; t++) {
                        float* cc = acc[mt][2 * p + t];
                        mma16816(cc, ah[mt], bh[2 * t], bh[2 * t + 1]);
                        mma16816(cc, ah[mt], bl[2 * t], bl[2 * t + 1]);
                        mma16816(cc, al[mt], bh[2 * t], bh[2 * t + 1]);
                    }
            }
        }
        __syncthreads();
    }

    // -------- epilogue --------
    const int g = lane >> 2, q = lane & 3;
#pragma unroll
    for (int mt = 0; mt < 2; mt++) {
        int r0 = m0 + warp_m * 32 + mt * 16 + g;
#pragma unroll
        for (int nt = 0; nt < NT; nt++) {
            int col = n0 + warp_n * NT * 8 + nt * 8 + q * 2;
            float c0 = acc[mt][nt][0], c1 = acc[mt][nt][1];
            float c2 = acc[mt][nt][2], c3 = acc[mt][nt][3];
            if (EPI == 3) {
                const int* mrow = mask + (size_t)(z >> 4) * SEQ;
                int mk0 = mrow[col], mk1 = mrow[col + 1];
                float2 v0, v1;
                v0.x = mk0 ? c0 * 0.125f : -1e9f;
                v0.y = mk1 ? c1 * 0.125f : -1e9f;
                v1.x = mk0 ? c2 * 0.125f : -1e9f;
                v1.y = mk1 ? c3 * 0.125f : -1e9f;
                *(float2*)(Cf + co + (size_t)r0 * ldc + col)       = v0;
                *(float2*)(Cf + co + (size_t)(r0 + 8) * ldc + col) = v1;
            } else if (EPI == 0) {
                float b0v = bias[col], b1v = bias[col + 1];
                float2 v0, v1;
                v0.x = c0 + b0v; v0.y = c1 + b1v;
                v1.x = c2 + b0v; v1.y = c3 + b1v;
                *(float2*)(Cf + co + (size_t)r0 * ldc + col)       = v0;
                *(float2*)(Cf + co + (size_t)(r0 + 8) * ldc + col) = v1;
            } else {
                if (EPI != 4) {
                    float b0v = bias[col], b1v = bias[col + 1];
                    c0 += b0v; c1 += b1v; c2 += b0v; c3 += b1v;
                }
                if (EPI == 2) {
                    c0 = fmaxf(c0, 0.f); c1 = fmaxf(c1, 0.f);
                    c2 = fmaxf(c2, 0.f); c3 = fmaxf(c3, 0.f);
                }
                size_t o0 = co + (size_t)r0 * ldc + col;
                size_t o1 = co + (size_t)(r0 + 8) * ldc + col;
                split_store2(c0, c1, Chi + o0, Clo + o0);
                split_store2(c2, c3, Chi + o1, Clo + o1);
            }
        }
    }
}

// ---------------- fp32 -> bf16 hi/lo ----------------
__global__ void __launch_bounds__(256) split_conv(const float* __restrict__ in,
                                                  __nv_bfloat16* __restrict__ oh,
                                                  __nv_bfloat16* __restrict__ ol, int n4)
{
    int i = blockIdx.x * 256 + threadIdx.x;
    if (i >= n4) return;
    float4 v = ((const float4*)in)[i];
    __nv_bfloat16 h0 = __float2bfloat16(v.x), h1 = __float2bfloat16(v.y);
    __nv_bfloat16 h2 = __float2bfloat16(v.z), h3 = __float2bfloat16(v.w);
    __nv_bfloat162 hp0, hp1, lp0, lp1;
    hp0.x = h0; hp0.y = h1; hp1.x = h2; hp1.y = h3;
    lp0.x = __float2bfloat16(v.x - __bfloat162float(h0));
    lp0.y = __float2bfloat16(v.y - __bfloat162float(h1));
    lp1.x = __float2bfloat16(v.z - __bfloat162float(h2));
    lp1.y = __float2bfloat16(v.w - __bfloat162float(h3));
    ((__nv_bfloat162*)oh)[i * 2]     = hp0;
    ((__nv_bfloat162*)oh)[i * 2 + 1] = hp1;
    ((__nv_bfloat162*)ol)[i * 2]     = lp0;
    ((__nv_bfloat162*)ol)[i * 2 + 1] = lp1;
}

// ---------------- transpose fp32 [R][C] -> bf16 hi/lo [C][R], per-z offsets ----------------
__global__ void transp_split(const float* __restrict__ in, long long zbi, long long zhi, int ild,
                             __nv_bfloat16* __restrict__ oh, __nv_bfloat16* __restrict__ ol,
                             long long zbo, long long zho, int old_)
{
    __shared__ float t[32][33];
    int z = blockIdx.z, b = z >> 4, h = z & 15;
    const float* ip = in + (size_t)b * zbi + (size_t)h * zhi;
    size_t ob = (size_t)b * zbo + (size_t)h * zho;
    int r0 = blockIdx.y * 32, c0 = blockIdx.x * 32;
    int tx = threadIdx.x, ty = threadIdx.y;
#pragma unroll
    for (int i = 0; i < 32; i += 8) t[ty + i][tx] = ip[(size_t)(r0 + ty + i) * ild + c0 + tx];
    __syncthreads();
#pragma unroll
    for (int i = 0; i < 32; i += 8) {
        float v = t[tx][ty + i];
        __nv_bfloat16 hh = __float2bfloat16(v);
        size_t o = ob + (size_t)(c0 + ty + i) * old_ + r0 + tx;
        oh[o] = hh;
        ol[o] = __float2bfloat16(v - __bfloat162float(hh));
    }
}

// ---------------- row softmax in place + bf16 hi/lo copies ----------------
__global__ void __launch_bounds__(256) softmax_kernel(float* __restrict__ attn,
                                                      __nv_bfloat16* __restrict__ ah,
                                                      __nv_bfloat16* __restrict__ al)
{
    const size_t row = blockIdx.x;
    float* p = attn + row * SEQ;
    const int tid = threadIdx.x;
    const int lane = tid & 31, wid = tid >> 5;
    __shared__ float red[8];

    float v[8];
    float mx = -3.4e38f;
#pragma unroll
    for (int e = 0; e < 8; e++) { v[e] = p[tid + e * 256]; mx = fmaxf(mx, v[e]); }
#pragma unroll
    for (int o = 16; o > 0; o >>= 1) mx = fmaxf(mx, __shfl_xor_sync(0xffffffffu, mx, o));
    if (lane == 0) red[wid] = mx;
    __syncthreads();
    float m2 = red[0];
#pragma unroll
    for (int w = 1; w < 8; w++) m2 = fmaxf(m2, red[w]);
    __syncthreads();

    float s = 0.f;
#pragma unroll
    for (int e = 0; e < 8; e++) { v[e] = __expf(v[e] - m2); s += v[e]; }
#pragma unroll
    for (int o = 16; o > 0; o >>= 1) s += __shfl_xor_sync(0xffffffffu, s, o);
    if (lane == 0) red[wid] = s;
    __syncthreads();
    float tot = 0.f;
#pragma unroll
    for (int w = 0; w < 8; w++) tot += red[w];
    float inv = 1.0f / tot;

    size_t base = row * SEQ;
#pragma unroll
    for (int e = 0; e < 8; e++) {
        float val = v[e] * inv;
        p[tid + e * 256] = val;
        __nv_bfloat16 hh = __float2bfloat16(val);
        ah[base + tid + e * 256] = hh;
        al[base + tid + e * 256] = __float2bfloat16(val - __bfloat162float(hh));
    }
}

// ---------------- out = LayerNorm(X + Y), optional bf16 split output ----------------
template<int SPLIT>
__global__ void __launch_bounds__(256) add_ln_kernel(const float* __restrict__ X,
                                                     const float* __restrict__ Y,
                                                     const float* __restrict__ gamma,
                                                     const float* __restrict__ beta,
                                                     float* __restrict__ out,
                                                     __nv_bfloat16* __restrict__ oh,
                                                     __nv_bfloat16* __restrict__ ol)
{
    const int row = blockIdx.x;
    const int tid = threadIdx.x;
    const int lane = tid & 31, wid = tid >> 5;
    __shared__ float red[8];

    const float* xr = X + (size_t)row * D_MODEL;
    const float* yr = Y + (size_t)row * D_MODEL;
    float4 xv = *(const float4*)(xr + tid * 4);
    float4 yv = *(const float4*)(yr + tid * 4);
    float v0 = xv.x + yv.x, v1 = xv.y + yv.y, v2 = xv.z + yv.z, v3 = xv.w + yv.w;

    float s = v0 + v1 + v2 + v3;
#pragma unroll
    for (int o = 16; o > 0; o >>= 1) s += __shfl_xor_sync(0xffffffffu, s, o);
    if (lane == 0) red[wid] = s;
    __syncthreads();
    float tot = 0.f;
#pragma unroll
    for (int w = 0; w < 8; w++) tot += red[w];
    float mu = tot * (1.0f / D_MODEL);
    __syncthreads();

    float d0 = v0 - mu, d1 = v1 - mu, d2 = v2 - mu, d3 = v3 - mu;
    float sq = d0 * d0 + d1 * d1 + d2 * d2 + d3 * d3;
#pragma unroll
    for (int o = 16; o > 0; o >>= 1) sq += __shfl_xor_sync(0xffffffffu, sq, o);
    if (lane == 0) red[wid] = sq;
    __syncthreads();
    float vtot = 0.f;
#pragma unroll
    for (int w = 0; w < 8; w++) vtot += red[w];
    float inv = rsqrtf(vtot * (1.0f / D_MODEL) + EPS);

    float4 gv = *(const float4*)(gamma + tid * 4);
    float4 bv = *(const float4*)(beta + tid * 4);
    float o0 = d0 * inv * gv.x + bv.x;
    float o1 = d1 * inv * gv.y + bv.y;
    float o2 = d2 * inv * gv.z + bv.z;
    float o3 = d3 * inv * gv.w + bv.w;
    float4 o4; o4.x = o0; o4.y = o1; o4.z = o2; o4.w = o3;
    *(float4*)(out + (size_t)row * D_MODEL + tid * 4) = o4;
    if (SPLIT) {
        size_t base = (size_t)row * D_MODEL + tid * 4;
        split_store2(o0, o1, oh + base, ol + base);
        split_store2(o2, o3, oh + base + 2, ol + base + 2);
    }
}

// ---------------- host ----------------
#define GETP(var, sym) void* var; cudaGetSymbolAddress(&var, sym)
#define BF(p) ((__nv_bfloat16*)(p))

extern "C" void kernel_launch(void* const* d_in, const int* in_sizes, int n_in,
                              void* d_out, int out_size)
{
    const float* x   = (const float*)d_in[0];
    const int*   msk = (const int*)  d_in[1];
    const float* Wq  = (const float*)d_in[2];
    const float* bq  = (const float*)d_in[3];
    const float* Wk  = (const float*)d_in[4];
    const float* bk  = (const float*)d_in[5];
    const float* Wv  = (const float*)d_in[6];
    const float* bv  = (const float*)d_in[7];
    const float* Wo  = (const float*)d_in[8];
    const float* bo  = (const float*)d_in[9];
    const float* g1  = (const float*)d_in[10];
    const float* be1 = (const float*)d_in[11];
    const float* W1  = (const float*)d_in[12];
    const float* b1  = (const float*)d_in[13];
    const float* W2  = (const float*)d_in[14];
    const float* b2  = (const float*)d_in[15];
    const float* g2  = (const float*)d_in[16];
    const float* be2 = (const float*)d_in[17];
    float* out = (float*)d_out;

    GETP(pV, g_V);      GETP(pT, g_t);      GETP(pH, g_h);     GETP(pAf, g_attn_f32);
    GETP(pxh, g_xc_h);  GETP(pxl, g_xc_l);
    GETP(pWqh, g_Wqt_h); GETP(pWql, g_Wqt_l);
    GETP(pWkh, g_Wkt_h); GETP(pWkl, g_Wkt_l);
    GETP(pWvh, g_Wvt_h); GETP(pWvl, g_Wvt_l);
    GETP(pWoh, g_Wot_h); GETP(pWol, g_Wot_l);
    GETP(pW1h, g_W1t_h); GETP(pW1l, g_W1t_l);
    GETP(pW2h, g_W2t_h); GETP(pW2l, g_W2t_l);
    GETP(pQh, g_Qc_h);  GETP(pQl, g_Qc_l);
    GETP(pKh, g_Kc_h);  GETP(pKl, g_Kc_l);
    GETP(pVth, g_Vt_h); GETP(pVtl, g_Vt_l);
    GETP(pAh, g_attn_h); GETP(pAl, g_attn_l);
    GETP(pCh, g_ctx_h); GETP(pCl, g_ctx_l);
    GETP(pHh, g_hc_h);  GETP(pHl, g_hc_l);
    GETP(pFh, g_ff_h);  GETP(pFl, g_ff_l);

    const size_t OUT_ELEMS  = (size_t)ROWS * D_MODEL;
    const size_t ATTN_ELEMS = (size_t)HZ * SEQ * SEQ;
    float* attn = ((size_t)out_size >= OUT_ELEMS + ATTN_ELEMS) ? out + OUT_ELEMS : (float*)pAf;

    const int SM128 = 2 * (2 * 128 * 80 + 2 * 128 * 80);   // 81920
    const int SM64  = 2 * (2 * 128 * 80 + 2 * 64  * 80);   // 61440
    cudaFuncSetAttribute(gemm_mm<128,0,0,0,0>, cudaFuncAttributeMaxDynamicSharedMemorySize, SM128);
    cudaFuncSetAttribute(gemm_mm<128,1,0,0,0>, cudaFuncAttributeMaxDynamicSharedMemorySize, SM128);
    cudaFuncSetAttribute(gemm_mm<128,2,0,0,0>, cudaFuncAttributeMaxDynamicSharedMemorySize, SM128);
    cudaFuncSetAttribute(gemm_mm<128,3,1,1,0>, cudaFuncAttributeMaxDynamicSharedMemorySize, SM128);
    cudaFuncSetAttribute(gemm_mm<64,4,0,0,1>,  cudaFuncAttributeMaxDynamicSharedMemorySize, SM64);

    dim3 blk(256);
    dim3 tblk(32, 8);

    // conversions
    split_conv<<<ROWS * D_MODEL / 4 / 256, blk>>>(x, BF(pxh), BF(pxl), ROWS * D_MODEL / 4);
    transp_split<<<dim3(32, 32, 1), tblk>>>(Wq, 0, 0, D_MODEL, BF(pWqh), BF(pWql), 0, 0, D_MODEL);
    transp_split<<<dim3(32, 32, 1), tblk>>>(Wk, 0, 0, D_MODEL, BF(pWkh), BF(pWkl), 0, 0, D_MODEL);
    transp_split<<<dim3(32, 32, 1), tblk>>>(Wv, 0, 0, D_MODEL, BF(pWvh), BF(pWvl), 0, 0, D_MODEL);
    transp_split<<<dim3(32, 32, 1), tblk>>>(Wo, 0, 0, D_MODEL, BF(pWoh), BF(pWol), 0, 0, D_MODEL);
    transp_split<<<dim3(128, 32, 1), tblk>>>(W1, 0, 0, DFF,     BF(pW1h), BF(pW1l), 0, 0, D_MODEL);
    transp_split<<<dim3(32, 128, 1), tblk>>>(W2, 0, 0, D_MODEL, BF(pW2h), BF(pW2l), 0, 0, DFF);

    // QKV
    gemm_mm<128,1,0,0,0><<<dim3(8, 32, 1), blk, SM128>>>(
        BF(pxh), BF(pxl), D_MODEL, 0, BF(pWqh), BF(pWql), D_MODEL, 0,
        nullptr, BF(pQh), BF(pQl), 0, D_MODEL, bq, nullptr, D_MODEL);
    gemm_mm<128,1,0,0,0><<<dim3(8, 32, 1), blk, SM128>>>(
        BF(pxh), BF(pxl), D_MODEL, 0, BF(pWkh), BF(pWkl), D_MODEL, 0,
        nullptr, BF(pKh), BF(pKl), 0, D_MODEL, bk, nullptr, D_MODEL);
    gemm_mm<128,0,0,0,0><<<dim3(8, 32, 1), blk, SM128>>>(
        BF(pxh), BF(pxl), D_MODEL, 0, BF(pWvh), BF(pWvl), D_MODEL, 0,
        (float*)pV, nullptr, nullptr, 0, D_MODEL, bv, nullptr, D_MODEL);
    transp_split<<<dim3(2, 64, HZ), tblk>>>((const float*)pV, (long long)SEQ * D_MODEL, DK, D_MODEL,
                                            BF(pVth), BF(pVtl),
                                            (long long)NHEAD * DK * SEQ, (long long)DK * SEQ, SEQ);

    // attention
    gemm_mm<128,3,1,1,0><<<dim3(16, 16, HZ), blk, SM128>>>(
        BF(pQh), BF(pQl), D_MODEL, 0, BF(pKh), BF(pKl), D_MODEL, 0,
        attn, nullptr, nullptr, (long long)SEQ * SEQ, SEQ, nullptr, msk, DK);
    softmax_kernel<<<HZ * SEQ, blk>>>(attn, BF(pAh), BF(pAl));
    gemm_mm<64,4,0,0,1><<<dim3(1, 16, HZ), blk, SM64>>>(
        BF(pAh), BF(pAl), SEQ, (long long)SEQ * SEQ, BF(pVth), BF(pVtl), SEQ, (long long)DK * SEQ,
        nullptr, BF(pCh), BF(pCl), 0, D_MODEL, nullptr, nullptr, SEQ);

    // output projection + LN1
    gemm_mm<128,0,0,0,0><<<dim3(8, 32, 1), blk, SM128>>>(
        BF(pCh), BF(pCl), D_MODEL, 0, BF(pWoh), BF(pWol), D_MODEL, 0,
        (float*)pT, nullptr, nullptr, 0, D_MODEL, bo, nullptr, D_MODEL);
    add_ln_kernel<1><<<ROWS, blk>>>(x, (const float*)pT, g1, be1, (float*)pH, BF(pHh), BF(pHl));

    // FFN + LN2
    gemm_mm<128,2,0,0,0><<<dim3(32, 32, 1), blk, SM128>>>(
        BF(pHh), BF(pHl), D_MODEL, 0, BF(pW1h), BF(pW1l), D_MODEL, 0,
        nullptr, BF(pFh), BF(pFl), 0, DFF, b1, nullptr, D_MODEL);
    gemm_mm<128,0,0,0,0><<<dim3(8, 32, 1), blk, SM128>>>(
        BF(pFh), BF(pFl), DFF, 0, BF(pW2h), BF(pW2l), DFF, 0,
        (float*)pT, nullptr, nullptr, 0, D_MODEL, b2, nullptr, DFF);
    add_ln_kernel<0><<<ROWS, blk>>>((const float*)pH, (const float*)pT, g2, be2, out, nullptr, nullptr);
}

// round 5
// speedup vs baseline: 2.3225x; 1.0930x over previous
#include <cuda_runtime.h>
#include <cuda_bf16.h>
#include <math.h>

#define D_MODEL 1024
#define NHEAD   16
#define DK      64
#define DFF     4096
#define SEQ     2048
#define BATCH   2
#define ROWS    (BATCH*SEQ)
#define EPS     1e-5f
#define HZ      (BATCH*NHEAD)

// ---------------- scratch (no allocation allowed) ----------------
__device__ __align__(256) float g_V [(size_t)ROWS*D_MODEL];
__device__ __align__(256) float g_t [(size_t)ROWS*D_MODEL];
__device__ __align__(256) float g_h [(size_t)ROWS*D_MODEL];
__device__ __align__(256) float g_attn_f32[(size_t)HZ*SEQ*SEQ];  // fallback only
__device__ __align__(256) __nv_bfloat16 g_xc_h [(size_t)ROWS*D_MODEL], g_xc_l [(size_t)ROWS*D_MODEL];
__device__ __align__(256) __nv_bfloat16 g_Wqt_h[(size_t)D_MODEL*D_MODEL], g_Wqt_l[(size_t)D_MODEL*D_MODEL];
__device__ __align__(256) __nv_bfloat16 g_Wkt_h[(size_t)D_MODEL*D_MODEL], g_Wkt_l[(size_t)D_MODEL*D_MODEL];
__device__ __align__(256) __nv_bfloat16 g_Wvt_h[(size_t)D_MODEL*D_MODEL], g_Wvt_l[(size_t)D_MODEL*D_MODEL];
__device__ __align__(256) __nv_bfloat16 g_Wot_h[(size_t)D_MODEL*D_MODEL], g_Wot_l[(size_t)D_MODEL*D_MODEL];
__device__ __align__(256) __nv_bfloat16 g_W1t_h[(size_t)D_MODEL*DFF],     g_W1t_l[(size_t)D_MODEL*DFF];
__device__ __align__(256) __nv_bfloat16 g_W2t_h[(size_t)D_MODEL*DFF],     g_W2t_l[(size_t)D_MODEL*DFF];
__device__ __align__(256) __nv_bfloat16 g_Qc_h [(size_t)ROWS*D_MODEL], g_Qc_l [(size_t)ROWS*D_MODEL];
__device__ __align__(256) __nv_bfloat16 g_Kc_h [(size_t)ROWS*D_MODEL], g_Kc_l [(size_t)ROWS*D_MODEL];
__device__ __align__(256) __nv_bfloat16 g_Vt_h [(size_t)HZ*DK*SEQ],    g_Vt_l [(size_t)HZ*DK*SEQ];
__device__ __align__(256) __nv_bfloat16 g_ctx_h[(size_t)ROWS*D_MODEL], g_ctx_l[(size_t)ROWS*D_MODEL];
__device__ __align__(256) __nv_bfloat16 g_hc_h [(size_t)ROWS*D_MODEL], g_hc_l [(size_t)ROWS*D_MODEL];
__device__ __align__(256) __nv_bfloat16 g_ff_h [(size_t)ROWS*DFF],     g_ff_l [(size_t)ROWS*DFF];

// ---------------- helpers ----------------
__device__ __forceinline__ unsigned s2u(const void* p){
    unsigned a;
    asm("{ .reg .u64 t; cvta.to.shared.u64 t, %1; cvt.u32.u64 %0, t; }" : "=r"(a) : "l"(p));
    return a;
}
__device__ __forceinline__ void cpa(unsigned s, const void* g){
    asm volatile("cp.async.cg.shared.global [%0], [%1], 16;" :: "r"(s), "l"(g));
}
__device__ __forceinline__ void ldmx4(unsigned* r, unsigned addr){
    asm volatile("ldmatrix.sync.aligned.m8n8.x4.shared.b16 {%0,%1,%2,%3}, [%4];"
        : "=r"(r[0]), "=r"(r[1]), "=r"(r[2]), "=r"(r[3]) : "r"(addr));
}
__device__ __forceinline__ void mma16816(float* c, const unsigned* a, unsigned b0, unsigned b1){
    asm volatile("mma.sync.aligned.m16n8k16.row.col.f32.bf16.bf16.f32 "
        "{%0,%1,%2,%3}, {%4,%5,%6,%7}, {%8,%9}, {%0,%1,%2,%3};"
        : "+f"(c[0]), "+f"(c[1]), "+f"(c[2]), "+f"(c[3])
        : "r"(a[0]), "r"(a[1]), "r"(a[2]), "r"(a[3]), "r"(b0), "r"(b1));
}
__device__ __forceinline__ void split_store2(float v0, float v1,
                                             __nv_bfloat16* hi, __nv_bfloat16* lo){
    __nv_bfloat16 h0 = __float2bfloat16(v0), h1 = __float2bfloat16(v1);
    __nv_bfloat162 hp, lp;
    hp.x = h0; hp.y = h1;
    lp.x = __float2bfloat16(v0 - __bfloat162float(h0));
    lp.y = __float2bfloat16(v1 - __bfloat162float(h1));
    *(__nv_bfloat162*)hi = hp;
    *(__nv_bfloat162*)lo = lp;
}

// ================= split-bf16 HMMA GEMM =================
// D[128, BN] per CTA = A @ B^T; A[m][k], B[n][k] bf16 hi/lo; fp32 accum.
// EPI: 0 fp32+bias | 1 bf16split+bias | 2 bf16split+bias+relu | 3 fp32 scale+mask (smem-staged)
// AOFF/BOFF/COFF: 0 -> z*stride, 1 -> head mode
template<int BN, int EPI, int AOFF, int BOFF, int COFF>
__global__ void __launch_bounds__(256) gemm_mm(
    const __nv_bfloat16* __restrict__ Ah, const __nv_bfloat16* __restrict__ Al, int lda, long long sAz,
    const __nv_bfloat16* __restrict__ Bh, const __nv_bfloat16* __restrict__ Bl, int ldb, long long sBz,
    float* __restrict__ Cf, __nv_bfloat16* __restrict__ Chi, __nv_bfloat16* __restrict__ Clo,
    long long sCz, int ldc,
    const float* __restrict__ bias, const int* __restrict__ mask, int K)
{
    constexpr int NT = BN / 16;
    constexpr int ABYTES = 128 * 80;
    constexpr int BBYTES = BN * 80;
    constexpr int BUFB = 2 * ABYTES + 2 * BBYTES;
    extern __shared__ __align__(128) char smem[];
    const unsigned sb = s2u(smem);
    const int tid = threadIdx.x;
    const int m0 = blockIdx.y * 128, n0 = blockIdx.x * BN, z = blockIdx.z;

    size_t ao = (AOFF == 1) ? ((size_t)(z >> 4) * SEQ * D_MODEL + (size_t)(z & 15) * DK) : (size_t)z * sAz;
    size_t bo = (BOFF == 1) ? ((size_t)(z >> 4) * SEQ * D_MODEL + (size_t)(z & 15) * DK) : (size_t)z * sBz;
    size_t co = (COFF == 1) ? ((size_t)(z >> 4) * SEQ * D_MODEL + (size_t)(z & 15) * DK) : (size_t)z * sCz;

    const int lane = tid & 31, w = tid >> 5;
    const int warp_m = w & 3, warp_n = w >> 2;

    float acc[2][NT][4];
#pragma unroll
    for (int mt = 0; mt < 2; mt++)
#pragma unroll
        for (int nt = 0; nt < NT; nt++)
#pragma unroll
            for (int e = 0; e < 4; e++) acc[mt][nt][e] = 0.f;

    const int nchunk = K >> 5;

    auto load_tile = [&](int c, int buf) {
        unsigned sbuf = sb + buf * BUFB;
        const __nv_bfloat16* pah = Ah + ao + (size_t)m0 * lda + c * 32;
        const __nv_bfloat16* pal = Al + ao + (size_t)m0 * lda + c * 32;
#pragma unroll
        for (int i = 0; i < 2; i++) {
            int idx = tid + i * 256;
            int row = idx >> 2, ch = idx & 3;
            unsigned so = row * 80 + ch * 16;
            cpa(sbuf + so,          pah + (size_t)row * lda + ch * 8);
            cpa(sbuf + ABYTES + so, pal + (size_t)row * lda + ch * 8);
        }
        const __nv_bfloat16* pbh = Bh + bo + (size_t)n0 * ldb + c * 32;
        const __nv_bfloat16* pbl = Bl + bo + (size_t)n0 * ldb + c * 32;
#pragma unroll
        for (int i = 0; i < BN / 64; i++) {
            int idx = tid + i * 256;
            int row = idx >> 2, ch = idx & 3;
            unsigned so = row * 80 + ch * 16;
            cpa(sbuf + 2 * ABYTES + so,          pbh + (size_t)row * ldb + ch * 8);
            cpa(sbuf + 2 * ABYTES + BBYTES + so, pbl + (size_t)row * ldb + ch * 8);
        }
    };

    load_tile(0, 0);
    asm volatile("cp.async.commit_group;");

    for (int c = 0; c < nchunk; c++) {
        if (c + 1 < nchunk) {
            load_tile(c + 1, (c + 1) & 1);
            asm volatile("cp.async.commit_group;");
            asm volatile("cp.async.wait_group 1;");
        } else {
            asm volatile("cp.async.wait_group 0;");
        }
        __syncthreads();

        unsigned sbuf = sb + (c & 1) * BUFB;
        unsigned sa  = sbuf + (warp_m * 32 + (lane & 15)) * 80 + (lane >> 4) * 16;
        unsigned sbb = sbuf + 2 * ABYTES
                     + (warp_n * (NT * 8) + (lane & 7) + ((lane >> 4) << 3)) * 80
                     + ((lane >> 3) & 1) * 16;
#pragma unroll
        for (int ks = 0; ks < 2; ks++) {
            unsigned ah[2][4], al[2][4];
            ldmx4(ah[0], sa + ks * 32);
            ldmx4(ah[1], sa + 16 * 80 + ks * 32);
            ldmx4(al[0], sa + ABYTES + ks * 32);
            ldmx4(al[1], sa + ABYTES + 16 * 80 + ks * 32);
#pragma unroll
            for (int p = 0; p < NT / 2; p++) {
                unsigned bh[4], bl[4];
                ldmx4(bh, sbb + p * 16 * 80 + ks * 32);
                ldmx4(bl, sbb + BBYTES + p * 16 * 80 + ks * 32);
#pragma unroll
                for (int mt = 0; mt < 2; mt++)
#pragma unroll
                    for (int t = 0; t < 2; t++) {
                        float* cc = acc[mt][2 * p + t];
                        mma16816(cc, ah[mt], bh[2 * t], bh[2 * t + 1]);
                        mma16816(cc, ah[mt], bl[2 * t], bl[2 * t + 1]);
                        mma16816(cc, al[mt], bh[2 * t], bh[2 * t + 1]);
                    }
            }
        }
        __syncthreads();
    }

    // -------- epilogue --------
    const int g = lane >> 2, q = lane & 3;
    if (EPI == 3) {
        // stage fp32 tile in smem (pitch 132 words -> conflict-free), then coalesced masked writes
        float* stg = (float*)smem;
#pragma unroll
        for (int mt = 0; mt < 2; mt++) {
            int sr = warp_m * 32 + mt * 16 + g;
#pragma unroll
            for (int nt = 0; nt < NT; nt++) {
                int sc = warp_n * (NT * 8) + nt * 8 + q * 2;
                stg[sr * 132 + sc]           = acc[mt][nt][0];
                stg[sr * 132 + sc + 1]       = acc[mt][nt][1];
                stg[(sr + 8) * 132 + sc]     = acc[mt][nt][2];
                stg[(sr + 8) * 132 + sc + 1] = acc[mt][nt][3];
            }
        }
        __syncthreads();
        const int* mrow = mask + (size_t)(z >> 4) * SEQ;
#pragma unroll
        for (int i = 0; i < 16; i++) {
            int idx = tid + i * 256, row = idx >> 5, c4 = (idx & 31) * 4;
            float4 v;
            v.x = stg[row * 132 + c4];
            v.y = stg[row * 132 + c4 + 1];
            v.z = stg[row * 132 + c4 + 2];
            v.w = stg[row * 132 + c4 + 3];
            int4 mk = *(const int4*)(mrow + n0 + c4);
            v.x = mk.x ? v.x * 0.125f : -1e9f;
            v.y = mk.y ? v.y * 0.125f : -1e9f;
            v.z = mk.z ? v.z * 0.125f : -1e9f;
            v.w = mk.w ? v.w * 0.125f : -1e9f;
            *(float4*)(Cf + co + (size_t)(m0 + row) * ldc + n0 + c4) = v;
        }
        return;
    }
#pragma unroll
    for (int mt = 0; mt < 2; mt++) {
        int r0 = m0 + warp_m * 32 + mt * 16 + g;
#pragma unroll
        for (int nt = 0; nt < NT; nt++) {
            int col = n0 + warp_n * NT * 8 + nt * 8 + q * 2;
            float c0 = acc[mt][nt][0], c1 = acc[mt][nt][1];
            float c2 = acc[mt][nt][2], c3 = acc[mt][nt][3];
            if (EPI == 0) {
                float b0v = bias[col], b1v = bias[col + 1];
                float2 v0, v1;
                v0.x = c0 + b0v; v0.y = c1 + b1v;
                v1.x = c2 + b0v; v1.y = c3 + b1v;
                *(float2*)(Cf + co + (size_t)r0 * ldc + col)       = v0;
                *(float2*)(Cf + co + (size_t)(r0 + 8) * ldc + col) = v1;
            } else {
                float b0v = bias[col], b1v = bias[col + 1];
                c0 += b0v; c1 += b1v; c2 += b0v; c3 += b1v;
                if (EPI == 2) {
                    c0 = fmaxf(c0, 0.f); c1 = fmaxf(c1, 0.f);
                    c2 = fmaxf(c2, 0.f); c3 = fmaxf(c3, 0.f);
                }
                size_t o0 = co + (size_t)r0 * ldc + col;
                size_t o1 = co + (size_t)(r0 + 8) * ldc + col;
                split_store2(c0, c1, Chi + o0, Clo + o0);
                split_store2(c2, c3, Chi + o1, Clo + o1);
            }
        }
    }
}

// ================= ctx = attn(fp32, converted in-kernel) @ Vt^T =================
// A = attn[z][2048][2048] fp32; B = Vt hi/lo [z][64][2048]; C = ctx split bf16 head-mode.
__global__ void __launch_bounds__(256) ctx_mm(
    const float* __restrict__ attn,
    const __nv_bfloat16* __restrict__ Bh, const __nv_bfloat16* __restrict__ Bl,
    __nv_bfloat16* __restrict__ Chi, __nv_bfloat16* __restrict__ Clo)
{
    constexpr int NT = 4;                 // BN = 64
    constexpr int ABYTES = 128 * 80;
    constexpr int BBYTES = 64 * 80;
    constexpr int BUFB = 2 * ABYTES + 2 * BBYTES;   // 30720
    extern __shared__ __align__(128) char smem[];
    const unsigned sb = s2u(smem);
    const int tid = threadIdx.x;
    const int m0 = blockIdx.y * 128, z = blockIdx.z;
    const float* ab = attn + (size_t)z * SEQ * SEQ;
    const size_t bo = (size_t)z * DK * SEQ;
    const size_t co = (size_t)(z >> 4) * SEQ * D_MODEL + (size_t)(z & 15) * DK;

    const int lane = tid & 31, w = tid >> 5;
    const int warp_m = w & 3, warp_n = w >> 2;

    float acc[2][NT][4];
#pragma unroll
    for (int mt = 0; mt < 2; mt++)
#pragma unroll
        for (int nt = 0; nt < NT; nt++)
#pragma unroll
            for (int e = 0; e < 4; e++) acc[mt][nt][e] = 0.f;

    const int arow = tid >> 3, ac4 = tid & 7;       // A reg-load mapping (per i: +32 rows)
    float4 ra[4];
    auto loadA = [&](int c){
#pragma unroll
        for (int i = 0; i < 4; i++)
            ra[i] = *(const float4*)(ab + (size_t)(m0 + arow + i * 32) * SEQ + c * 32 + ac4 * 4);
    };
    auto storeA = [&](int buf){
        char* bp = smem + buf * BUFB;
#pragma unroll
        for (int i = 0; i < 4; i++) {
            __nv_bfloat162 h0, h1, l0, l1;
            h0.x = __float2bfloat16(ra[i].x); h0.y = __float2bfloat16(ra[i].y);
            h1.x = __float2bfloat16(ra[i].z); h1.y = __float2bfloat16(ra[i].w);
            l0.x = __float2bfloat16(ra[i].x - __bfloat162float(h0.x));
            l0.y = __float2bfloat16(ra[i].y - __bfloat162float(h0.y));
            l1.x = __float2bfloat16(ra[i].z - __bfloat162float(h1.x));
            l1.y = __float2bfloat16(ra[i].w - __bfloat162float(h1.y));
            uint2 uh, ul;
            uh.x = *(unsigned*)&h0; uh.y = *(unsigned*)&h1;
            ul.x = *(unsigned*)&l0; ul.y = *(unsigned*)&l1;
            unsigned so = (arow + i * 32) * 80 + ac4 * 8;
            *(uint2*)(bp + so)          = uh;
            *(uint2*)(bp + ABYTES + so) = ul;
        }
    };
    auto loadB = [&](int c, int buf){
        unsigned sbuf = sb + buf * BUFB + 2 * ABYTES;
        int row = tid >> 2, ch = tid & 3;           // 64 rows x 4 chunks = 256
        unsigned so = row * 80 + ch * 16;
        cpa(sbuf + so,          Bh + bo + (size_t)row * SEQ + c * 32 + ch * 8);
        cpa(sbuf + BBYTES + so, Bl + bo + (size_t)row * SEQ + c * 32 + ch * 8);
    };

    loadA(0);
    loadB(0, 0);
    asm volatile("cp.async.commit_group;");

    const int nchunk = SEQ / 32;                    // 64
    for (int c = 0; c < nchunk; c++) {
        storeA(c & 1);
        if (c + 1 < nchunk) {
            loadA(c + 1);
            loadB(c + 1, (c + 1) & 1);
            asm volatile("cp.async.commit_group;");
            asm volatile("cp.async.wait_group 1;");
        } else {
            asm volatile("cp.async.wait_group 0;");
        }
        __syncthreads();

        unsigned sbuf = sb + (c & 1) * BUFB;
        unsigned sa  = sbuf + (warp_m * 32 + (lane & 15)) * 80 + (lane >> 4) * 16;
        unsigned sbb = sbuf + 2 * ABYTES
                     + (warp_n * 32 + (lane & 7) + ((lane >> 4) << 3)) * 80
                     + ((lane >> 3) & 1) * 16;
#pragma unroll
        for (int ks = 0; ks < 2; ks++) {
            unsigned ah[2][4], al[2][4];
            ldmx4(ah[0], sa + ks * 32);
            ldmx4(ah[1], sa + 16 * 80 + ks * 32);
            ldmx4(al[0], sa + ABYTES + ks * 32);
            ldmx4(al[1], sa + ABYTES + 16 * 80 + ks * 32);
#pragma unroll
            for (int p = 0; p < NT / 2; p++) {
                unsigned bh[4], bl[4];
                ldmx4(bh, sbb + p * 16 * 80 + ks * 32);
                ldmx4(bl, sbb + BBYTES + p * 16 * 80 + ks * 32);
#pragma unroll
                for (int mt = 0; mt < 2; mt++)
#pragma unroll
                    for (int t = 0; t < 2; t++) {
                        float* cc = acc[mt][2 * p + t];
                        mma16816(cc, ah[mt], bh[2 * t], bh[2 * t + 1]);
                        mma16816(cc, ah[mt], bl[2 * t], bl[2 * t + 1]);
                        mma16816(cc, al[mt], bh[2 * t], bh[2 * t + 1]);
                    }
            }
        }
        __syncthreads();
    }

    const int g = lane >> 2, q = lane & 3;
#pragma unroll
    for (int mt = 0; mt < 2; mt++) {
        int r0 = m0 + warp_m * 32 + mt * 16 + g;
#pragma unroll
        for (int nt = 0; nt < NT; nt++) {
            int col = warp_n * 32 + nt * 8 + q * 2;
            size_t o0 = co + (size_t)r0 * D_MODEL + col;
            size_t o1 = co + (size_t)(r0 + 8) * D_MODEL + col;
            split_store2(acc[mt][nt][0], acc[mt][nt][1], Chi + o0, Clo + o0);
            split_store2(acc[mt][nt][2], acc[mt][nt][3], Chi + o1, Clo + o1);
        }
    }
}

// ---------------- fp32 -> bf16 hi/lo ----------------
__global__ void __launch_bounds__(256) split_conv(const float* __restrict__ in,
                                                  __nv_bfloat16* __restrict__ oh,
                                                  __nv_bfloat16* __restrict__ ol, int n4)
{
    int i = blockIdx.x * 256 + threadIdx.x;
    if (i >= n4) return;
    float4 v = ((const float4*)in)[i];
    __nv_bfloat16 h0 = __float2bfloat16(v.x), h1 = __float2bfloat16(v.y);
    __nv_bfloat16 h2 = __float2bfloat16(v.z), h3 = __float2bfloat16(v.w);
    __nv_bfloat162 hp0, hp1, lp0, lp1;
    hp0.x = h0; hp0.y = h1; hp1.x = h2; hp1.y = h3;
    lp0.x = __float2bfloat16(v.x - __bfloat162float(h0));
    lp0.y = __float2bfloat16(v.y - __bfloat162float(h1));
    lp1.x = __float2bfloat16(v.z - __bfloat162float(h2));
    lp1.y = __float2bfloat16(v.w - __bfloat162float(h3));
    ((__nv_bfloat162*)oh)[i * 2]     = hp0;
    ((__nv_bfloat162*)oh)[i * 2 + 1] = hp1;
    ((__nv_bfloat162*)ol)[i * 2]     = lp0;
    ((__nv_bfloat162*)ol)[i * 2 + 1] = lp1;
}

// ---------------- transpose fp32 [R][C] -> bf16 hi/lo [C][R], per-z offsets ----------------
__global__ void transp_split(const float* __restrict__ in, long long zbi, long long zhi, int ild,
                             __nv_bfloat16* __restrict__ oh, __nv_bfloat16* __restrict__ ol,
                             long long zbo, long long zho, int old_)
{
    __shared__ float t[32][33];
    int z = blockIdx.z, b = z >> 4, h = z & 15;
    const float* ip = in + (size_t)b * zbi + (size_t)h * zhi;
    size_t ob = (size_t)b * zbo + (size_t)h * zho;
    int r0 = blockIdx.y * 32, c0 = blockIdx.x * 32;
    int tx = threadIdx.x, ty = threadIdx.y;
#pragma unroll
    for (int i = 0; i < 32; i += 8) t[ty + i][tx] = ip[(size_t)(r0 + ty + i) * ild + c0 + tx];
    __syncthreads();
#pragma unroll
    for (int i = 0; i < 32; i += 8) {
        float v = t[tx][ty + i];
        __nv_bfloat16 hh = __float2bfloat16(v);
        size_t o = ob + (size_t)(c0 + ty + i) * old_ + r0 + tx;
        oh[o] = hh;
        ol[o] = __float2bfloat16(v - __bfloat162float(hh));
    }
}

// ---------------- row softmax in place (fp32 only) ----------------
__global__ void __launch_bounds__(256) softmax_kernel(float* __restrict__ attn)
{
    const size_t row = blockIdx.x;
    float* p = attn + row * SEQ;
    const int tid = threadIdx.x;
    const int lane = tid & 31, wid = tid >> 5;
    __shared__ float red[8];

    float v[8];
    float mx = -3.4e38f;
#pragma unroll
    for (int e = 0; e < 8; e++) { v[e] = p[tid + e * 256]; mx = fmaxf(mx, v[e]); }
#pragma unroll
    for (int o = 16; o > 0; o >>= 1) mx = fmaxf(mx, __shfl_xor_sync(0xffffffffu, mx, o));
    if (lane == 0) red[wid] = mx;
    __syncthreads();
    float m2 = red[0];
#pragma unroll
    for (int w = 1; w < 8; w++) m2 = fmaxf(m2, red[w]);
    __syncthreads();

    float s = 0.f;
#pragma unroll
    for (int e = 0; e < 8; e++) { v[e] = __expf(v[e] - m2); s += v[e]; }
#pragma unroll
    for (int o = 16; o > 0; o >>= 1) s += __shfl_xor_sync(0xffffffffu, s, o);
    if (lane == 0) red[wid] = s;
    __syncthreads();
    float tot = 0.f;
#pragma unroll
    for (int w = 0; w < 8; w++) tot += red[w];
    float inv = 1.0f / tot;
#pragma unroll
    for (int e = 0; e < 8; e++) p[tid + e * 256] = v[e] * inv;
}

// ---------------- out = LayerNorm(X + Y), optional bf16 split output ----------------
template<int SPLIT>
__global__ void __launch_bounds__(256) add_ln_kernel(const float* __restrict__ X,
                                                     const float* __restrict__ Y,
                                                     const float* __restrict__ gamma,
                                                     const float* __restrict__ beta,
                                                     float* __restrict__ out,
                                                     __nv_bfloat16* __restrict__ oh,
                                                     __nv_bfloat16* __restrict__ ol)
{
    const int row = blockIdx.x;
    const int tid = threadIdx.x;
    const int lane = tid & 31, wid = tid >> 5;
    __shared__ float red[8];

    const float* xr = X + (size_t)row * D_MODEL;
    const float* yr = Y + (size_t)row * D_MODEL;
    float4 xv = *(const float4*)(xr + tid * 4);
    float4 yv = *(const float4*)(yr + tid * 4);
    float v0 = xv.x + yv.x, v1 = xv.y + yv.y, v2 = xv.z + yv.z, v3 = xv.w + yv.w;

    float s = v0 + v1 + v2 + v3;
#pragma unroll
    for (int o = 16; o > 0; o >>= 1) s += __shfl_xor_sync(0xffffffffu, s, o);
    if (lane == 0) red[wid] = s;
    __syncthreads();
    float tot = 0.f;
#pragma unroll
    for (int w = 0; w < 8; w++) tot += red[w];
    float mu = tot * (1.0f / D_MODEL);
    __syncthreads();

    float d0 = v0 - mu, d1 = v1 - mu, d2 = v2 - mu, d3 = v3 - mu;
    float sq = d0 * d0 + d1 * d1 + d2 * d2 + d3 * d3;
#pragma unroll
    for (int o = 16; o > 0; o >>= 1) sq += __shfl_xor_sync(0xffffffffu, sq, o);
    if (lane == 0) red[wid] = sq;
    __syncthreads();
    float vtot = 0.f;
#pragma unroll
    for (int w = 0; w < 8; w++) vtot += red[w];
    float inv = rsqrtf(vtot * (1.0f / D_MODEL) + EPS);

    float4 gv = *(const float4*)(gamma + tid * 4);
    float4 bv = *(const float4*)(beta + tid * 4);
    float o0 = d0 * inv * gv.x + bv.x;
    float o1 = d1 * inv * gv.y + bv.y;
    float o2 = d2 * inv * gv.z + bv.z;
    float o3 = d3 * inv * gv.w + bv.w;
    float4 o4; o4.x = o0; o4.y = o1; o4.z = o2; o4.w = o3;
    *(float4*)(out + (size_t)row * D_MODEL + tid * 4) = o4;
    if (SPLIT) {
        size_t base = (size_t)row * D_MODEL + tid * 4;
        split_store2(o0, o1, oh + base, ol + base);
        split_store2(o2, o3, oh + base + 2, ol + base + 2);
    }
}

// ---------------- host ----------------
#define GETP(var, sym) void* var; cudaGetSymbolAddress(&var, sym)
#define BF(p) ((__nv_bfloat16*)(p))

extern "C" void kernel_launch(void* const* d_in, const int* in_sizes, int n_in,
                              void* d_out, int out_size)
{
    const float* x   = (const float*)d_in[0];
    const int*   msk = (const int*)  d_in[1];
    const float* Wq  = (const float*)d_in[2];
    const float* bq  = (const float*)d_in[3];
    const float* Wk  = (const float*)d_in[4];
    const float* bk  = (const float*)d_in[5];
    const float* Wv  = (const float*)d_in[6];
    const float* bv  = (const float*)d_in[7];
    const float* Wo  = (const float*)d_in[8];
    const float* bo  = (const float*)d_in[9];
    const float* g1  = (const float*)d_in[10];
    const float* be1 = (const float*)d_in[11];
    const float* W1  = (const float*)d_in[12];
    const float* b1  = (const float*)d_in[13];
    const float* W2  = (const float*)d_in[14];
    const float* b2  = (const float*)d_in[15];
    const float* g2  = (const float*)d_in[16];
    const float* be2 = (const float*)d_in[17];
    float* out = (float*)d_out;

    GETP(pV, g_V);      GETP(pT, g_t);      GETP(pH, g_h);     GETP(pAf, g_attn_f32);
    GETP(pxh, g_xc_h);  GETP(pxl, g_xc_l);
    GETP(pWqh, g_Wqt_h); GETP(pWql, g_Wqt_l);
    GETP(pWkh, g_Wkt_h); GETP(pWkl, g_Wkt_l);
    GETP(pWvh, g_Wvt_h); GETP(pWvl, g_Wvt_l);
    GETP(pWoh, g_Wot_h); GETP(pWol, g_Wot_l);
    GETP(pW1h, g_W1t_h); GETP(pW1l, g_W1t_l);
    GETP(pW2h, g_W2t_h); GETP(pW2l, g_W2t_l);
    GETP(pQh, g_Qc_h);  GETP(pQl, g_Qc_l);
    GETP(pKh, g_Kc_h);  GETP(pKl, g_Kc_l);
    GETP(pVth, g_Vt_h); GETP(pVtl, g_Vt_l);
    GETP(pCh, g_ctx_h); GETP(pCl, g_ctx_l);
    GETP(pHh, g_hc_h);  GETP(pHl, g_hc_l);
    GETP(pFh, g_ff_h);  GETP(pFl, g_ff_l);

    const size_t OUT_ELEMS  = (size_t)ROWS * D_MODEL;
    const size_t ATTN_ELEMS = (size_t)HZ * SEQ * SEQ;
    float* attn = ((size_t)out_size >= OUT_ELEMS + ATTN_ELEMS) ? out + OUT_ELEMS : (float*)pAf;

    const int SM128 = 2 * (2 * 128 * 80 + 2 * 128 * 80);    // 81920 (>= 67584 staging)
    const int SMCTX = 2 * (2 * 128 * 80 + 2 * 64 * 80);     // 61440
    cudaFuncSetAttribute(gemm_mm<128,0,0,0,0>, cudaFuncAttributeMaxDynamicSharedMemorySize, SM128);
    cudaFuncSetAttribute(gemm_mm<128,1,0,0,0>, cudaFuncAttributeMaxDynamicSharedMemorySize, SM128);
    cudaFuncSetAttribute(gemm_mm<128,2,0,0,0>, cudaFuncAttributeMaxDynamicSharedMemorySize, SM128);
    cudaFuncSetAttribute(gemm_mm<128,3,1,1,0>, cudaFuncAttributeMaxDynamicSharedMemorySize, SM128);
    cudaFuncSetAttribute(ctx_mm,               cudaFuncAttributeMaxDynamicSharedMemorySize, SMCTX);

    dim3 blk(256);
    dim3 tblk(32, 8);

    // conversions (attention weights only; W1/W2 moved later so s=5 profiles a dense GEMM)
    split_conv<<<ROWS * D_MODEL / 4 / 256, blk>>>(x, BF(pxh), BF(pxl), ROWS * D_MODEL / 4);
    transp_split<<<dim3(32, 32, 1), tblk>>>(Wq, 0, 0, D_MODEL, BF(pWqh), BF(pWql), 0, 0, D_MODEL);
    transp_split<<<dim3(32, 32, 1), tblk>>>(Wk, 0, 0, D_MODEL, BF(pWkh), BF(pWkl), 0, 0, D_MODEL);
    transp_split<<<dim3(32, 32, 1), tblk>>>(Wv, 0, 0, D_MODEL, BF(pWvh), BF(pWvl), 0, 0, D_MODEL);
    transp_split<<<dim3(32, 32, 1), tblk>>>(Wo, 0, 0, D_MODEL, BF(pWoh), BF(pWol), 0, 0, D_MODEL);

    // QKV  (launch index 5 = Q projection -> ncu target)
    gemm_mm<128,1,0,0,0><<<dim3(8, 32, 1), blk, SM128>>>(
        BF(pxh), BF(pxl), D_MODEL, 0, BF(pWqh), BF(pWql), D_MODEL, 0,
        nullptr, BF(pQh), BF(pQl), 0, D_MODEL, bq, nullptr, D_MODEL);
    gemm_mm<128,1,0,0,0><<<dim3(8, 32, 1), blk, SM128>>>(
        BF(pxh), BF(pxl), D_MODEL, 0, BF(pWkh), BF(pWkl), D_MODEL, 0,
        nullptr, BF(pKh), BF(pKl), 0, D_MODEL, bk, nullptr, D_MODEL);
    gemm_mm<128,0,0,0,0><<<dim3(8, 32, 1), blk, SM128>>>(
        BF(pxh), BF(pxl), D_MODEL, 0, BF(pWvh), BF(pWvl), D_MODEL, 0,
        (float*)pV, nullptr, nullptr, 0, D_MODEL, bv, nullptr, D_MODEL);
    transp_split<<<dim3(2, 64, HZ), tblk>>>((const float*)pV, (long long)SEQ * D_MODEL, DK, D_MODEL,
                                            BF(pVth), BF(pVtl),
                                            (long long)NHEAD * DK * SEQ, (long long)DK * SEQ, SEQ);

    // attention
    gemm_mm<128,3,1,1,0><<<dim3(16, 16, HZ), blk, SM128>>>(
        BF(pQh), BF(pQl), D_MODEL, 0, BF(pKh), BF(pKl), D_MODEL, 0,
        attn, nullptr, nullptr, (long long)SEQ * SEQ, SEQ, nullptr, msk, DK);
    softmax_kernel<<<HZ * SEQ, blk>>>(attn);
    ctx_mm<<<dim3(1, 16, HZ), blk, SMCTX>>>(attn, BF(pVth), BF(pVtl), BF(pCh), BF(pCl));

    // output projection + LN1
    gemm_mm<128,0,0,0,0><<<dim3(8, 32, 1), blk, SM128>>>(
        BF(pCh), BF(pCl), D_MODEL, 0, BF(pWoh), BF(pWol), D_MODEL, 0,
        (float*)pT, nullptr, nullptr, 0, D_MODEL, bo, nullptr, D_MODEL);
    add_ln_kernel<1><<<ROWS, blk>>>(x, (const float*)pT, g1, be1, (float*)pH, BF(pHh), BF(pHl));

    // FFN weights + FFN + LN2
    transp_split<<<dim3(128, 32, 1), tblk>>>(W1, 0, 0, DFF,     BF(pW1h), BF(pW1l), 0, 0, D_MODEL);
    transp_split<<<dim3(32, 128, 1), tblk>>>(W2, 0, 0, D_MODEL, BF(pW2h), BF(pW2l), 0, 0, DFF);
    gemm_mm<128,2,0,0,0><<<dim3(32, 32, 1), blk, SM128>>>(
        BF(pHh), BF(pHl), D_MODEL, 0, BF(pW1h), BF(pW1l), D_MODEL, 0,
        nullptr, BF(pFh), BF(pFl), 0, DFF, b1, nullptr, D_MODEL);
    gemm_mm<128,0,0,0,0><<<dim3(8, 32, 1), blk, SM128>>>(
        BF(pFh), BF(pFl), DFF, 0, BF(pW2h), BF(pW2l), DFF, 0,
        (float*)pT, nullptr, nullptr, 0, D_MODEL, b2, nullptr, DFF);
    add_ln_kernel<0><<<ROWS, blk>>>((const float*)pH, (const float*)pT, g2, be2, out, nullptr, nullptr);
}

// round 6
// speedup vs baseline: 2.3671x; 1.0192x over previous
#include <cuda_runtime.h>
#include <cuda_bf16.h>
#include <math.h>

#define D_MODEL 1024
#define NHEAD   16
#define DK      64
#define DFF     4096
#define SEQ     2048
#define BATCH   2
#define ROWS    (BATCH*SEQ)
#define EPS     1e-5f
#define HZ      (BATCH*NHEAD)
#define QKV3    3072

// ---------------- scratch (no allocation allowed) ----------------
__device__ __align__(256) float g_t [(size_t)ROWS*D_MODEL];
__device__ __align__(256) float g_h [(size_t)ROWS*D_MODEL];
__device__ __align__(256) float g_attn_f32[(size_t)HZ*SEQ*SEQ];  // fallback only
__device__ __align__(256) __nv_bfloat16 g_xc_h [(size_t)ROWS*D_MODEL], g_xc_l [(size_t)ROWS*D_MODEL];
__device__ __align__(256) __nv_bfloat16 g_Wqkv_h[(size_t)QKV3*D_MODEL], g_Wqkv_l[(size_t)QKV3*D_MODEL]; // [3072][1024] transposed
__device__ __align__(256) __nv_bfloat16 g_Wot_h[(size_t)D_MODEL*D_MODEL], g_Wot_l[(size_t)D_MODEL*D_MODEL];
__device__ __align__(256) __nv_bfloat16 g_W1t_h[(size_t)D_MODEL*DFF],     g_W1t_l[(size_t)D_MODEL*DFF];
__device__ __align__(256) __nv_bfloat16 g_W2t_h[(size_t)D_MODEL*DFF],     g_W2t_l[(size_t)D_MODEL*DFF];
__device__ __align__(256) __nv_bfloat16 g_qkv_h[(size_t)ROWS*QKV3], g_qkv_l[(size_t)ROWS*QKV3];  // Q|K|V split
__device__ __align__(256) __nv_bfloat16 g_Vt_h [(size_t)HZ*DK*SEQ],    g_Vt_l [(size_t)HZ*DK*SEQ];
__device__ __align__(256) __nv_bfloat16 g_ctx_h[(size_t)ROWS*D_MODEL], g_ctx_l[(size_t)ROWS*D_MODEL];
__device__ __align__(256) __nv_bfloat16 g_hc_h [(size_t)ROWS*D_MODEL], g_hc_l [(size_t)ROWS*D_MODEL];
__device__ __align__(256) __nv_bfloat16 g_ff_h [(size_t)ROWS*DFF],     g_ff_l [(size_t)ROWS*DFF];

// ---------------- helpers ----------------
__device__ __forceinline__ unsigned s2u(const void* p){
    unsigned a;
    asm("{ .reg .u64 t; cvta.to.shared.u64 t, %1; cvt.u32.u64 %0, t; }" : "=r"(a) : "l"(p));
    return a;
}
__device__ __forceinline__ void cpa(unsigned s, const void* g){
    asm volatile("cp.async.cg.shared.global [%0], [%1], 16;" :: "r"(s), "l"(g));
}
__device__ __forceinline__ void ldmx4(unsigned* r, unsigned addr){
    asm volatile("ldmatrix.sync.aligned.m8n8.x4.shared.b16 {%0,%1,%2,%3}, [%4];"
        : "=r"(r[0]), "=r"(r[1]), "=r"(r[2]), "=r"(r[3]) : "r"(addr));
}
__device__ __forceinline__ void mma16816(float* c, const unsigned* a, unsigned b0, unsigned b1){
    asm volatile("mma.sync.aligned.m16n8k16.row.col.f32.bf16.bf16.f32 "
        "{%0,%1,%2,%3}, {%4,%5,%6,%7}, {%8,%9}, {%0,%1,%2,%3};"
        : "+f"(c[0]), "+f"(c[1]), "+f"(c[2]), "+f"(c[3])
        : "r"(a[0]), "r"(a[1]), "r"(a[2]), "r"(a[3]), "r"(b0), "r"(b1));
}
__device__ __forceinline__ void split_store2(float v0, float v1,
                                             __nv_bfloat16* hi, __nv_bfloat16* lo){
    __nv_bfloat16 h0 = __float2bfloat16(v0), h1 = __float2bfloat16(v1);
    __nv_bfloat162 hp, lp;
    hp.x = h0; hp.y = h1;
    lp.x = __float2bfloat16(v0 - __bfloat162float(h0));
    lp.y = __float2bfloat16(v1 - __bfloat162float(h1));
    *(__nv_bfloat162*)hi = hp;
    *(__nv_bfloat162*)lo = lp;
}

// ================= split-bf16 HMMA GEMM =================
// D[128, BN] per CTA = A @ B^T; A[m][k], B[n][k] bf16 hi/lo; fp32 accum.
// EPI: 0 fp32+bias | 2 bf16split+bias+relu | 3 fp32 +mask (smem-staged, scale prefolded)
//      5 bf16split, 3-segment bias (QKV; q-bias scaled by 0.125)
// AOFF/BOFF/COFF: 0 -> z*stride, 1 -> head mode ((z>>4)*SEQ*ld + (z&15)*64 + s?z)
template<int BN, int EPI, int AOFF, int BOFF, int COFF>
__global__ void __launch_bounds__(256) gemm_mm(
    const __nv_bfloat16* __restrict__ Ah, const __nv_bfloat16* __restrict__ Al, int lda, long long sAz,
    const __nv_bfloat16* __restrict__ Bh, const __nv_bfloat16* __restrict__ Bl, int ldb, long long sBz,
    float* __restrict__ Cf, __nv_bfloat16* __restrict__ Chi, __nv_bfloat16* __restrict__ Clo,
    long long sCz, int ldc,
    const float* __restrict__ bias, const float* __restrict__ bias2, const float* __restrict__ bias3,
    const int* __restrict__ mask, int K)
{
    constexpr int NT = BN / 16;
    constexpr int ABYTES = 128 * 80;
    constexpr int BBYTES = BN * 80;
    constexpr int BUFB = 2 * ABYTES + 2 * BBYTES;
    extern __shared__ __align__(128) char smem[];
    const unsigned sb = s2u(smem);
    const int tid = threadIdx.x;
    const int m0 = blockIdx.y * 128, n0 = blockIdx.x * BN, z = blockIdx.z;

    size_t ao = (AOFF == 1) ? ((size_t)(z >> 4) * SEQ * lda + (size_t)(z & 15) * DK + (size_t)sAz)
                            : (size_t)z * sAz;
    size_t bo = (BOFF == 1) ? ((size_t)(z >> 4) * SEQ * ldb + (size_t)(z & 15) * DK + (size_t)sBz)
                            : (size_t)z * sBz;
    size_t co = (COFF == 1) ? ((size_t)(z >> 4) * SEQ * ldc + (size_t)(z & 15) * DK)
                            : (size_t)z * sCz;

    const int lane = tid & 31, w = tid >> 5;
    const int warp_m = w & 3, warp_n = w >> 2;

    float acc[2][NT][4];
#pragma unroll
    for (int mt = 0; mt < 2; mt++)
#pragma unroll
        for (int nt = 0; nt < NT; nt++)
#pragma unroll
            for (int e = 0; e < 4; e++) acc[mt][nt][e] = 0.f;

    const int nchunk = K >> 5;

    auto load_tile = [&](int c, int buf) {
        unsigned sbuf = sb + buf * BUFB;
        const __nv_bfloat16* pah = Ah + ao + (size_t)m0 * lda + c * 32;
        const __nv_bfloat16* pal = Al + ao + (size_t)m0 * lda + c * 32;
#pragma unroll
        for (int i = 0; i < 2; i++) {
            int idx = tid + i * 256;
            int row = idx >> 2, ch = idx & 3;
            unsigned so = row * 80 + ch * 16;
            cpa(sbuf + so,          pah + (size_t)row * lda + ch * 8);
            cpa(sbuf + ABYTES + so, pal + (size_t)row * lda + ch * 8);
        }
        const __nv_bfloat16* pbh = Bh + bo + (size_t)n0 * ldb + c * 32;
        const __nv_bfloat16* pbl = Bl + bo + (size_t)n0 * ldb + c * 32;
#pragma unroll
        for (int i = 0; i < BN / 64; i++) {
            int idx = tid + i * 256;
            int row = idx >> 2, ch = idx & 3;
            unsigned so = row * 80 + ch * 16;
            cpa(sbuf + 2 * ABYTES + so,          pbh + (size_t)row * ldb + ch * 8);
            cpa(sbuf + 2 * ABYTES + BBYTES + so, pbl + (size_t)row * ldb + ch * 8);
        }
    };

    load_tile(0, 0);
    asm volatile("cp.async.commit_group;");

    for (int c = 0; c < nchunk; c++) {
        if (c + 1 < nchunk) {
            load_tile(c + 1, (c + 1) & 1);
            asm volatile("cp.async.commit_group;");
            asm volatile("cp.async.wait_group 1;");
        } else {
            asm volatile("cp.async.wait_group 0;");
        }
        __syncthreads();

        unsigned sbuf = sb + (c & 1) * BUFB;
        unsigned sa  = sbuf + (warp_m * 32 + (lane & 15)) * 80 + (lane >> 4) * 16;
        unsigned sbb = sbuf + 2 * ABYTES
                     + (warp_n * (NT * 8) + (lane & 7) + ((lane >> 4) << 3)) * 80
                     + ((lane >> 3) & 1) * 16;
#pragma unroll
        for (int ks = 0; ks < 2; ks++) {
            unsigned ah[2][4], al[2][4];
            ldmx4(ah[0], sa + ks * 32);
            ldmx4(ah[1], sa + 16 * 80 + ks * 32);
            ldmx4(al[0], sa + ABYTES + ks * 32);
            ldmx4(al[1], sa + ABYTES + 16 * 80 + ks * 32);
#pragma unroll
            for (int p = 0; p < NT / 2; p++) {
                unsigned bh[4], bl[4];
                ldmx4(bh, sbb + p * 16 * 80 + ks * 32);
                ldmx4(bl, sbb + BBYTES + p * 16 * 80 + ks * 32);
#pragma unroll
                for (int mt = 0; mt < 2; mt++)
#pragma unroll
                    for (int t = 0; t < 2; t++) {
                        float* cc = acc[mt][2 * p + t];
                        mma16816(cc, ah[mt], bh[2 * t], bh[2 * t + 1]);
                        mma16816(cc, ah[mt], bl[2 * t], bl[2 * t + 1]);
                        mma16816(cc, al[mt], bh[2 * t], bh[2 * t + 1]);
                    }
            }
        }
        __syncthreads();
    }

    // -------- epilogue --------
    const int g = lane >> 2, q = lane & 3;
    if (EPI == 3) {
        float* stg = (float*)smem;
#pragma unroll
        for (int mt = 0; mt < 2; mt++) {
            int sr = warp_m * 32 + mt * 16 + g;
#pragma unroll
            for (int nt = 0; nt < NT; nt++) {
                int sc = warp_n * (NT * 8) + nt * 8 + q * 2;
                stg[sr * 132 + sc]           = acc[mt][nt][0];
                stg[sr * 132 + sc + 1]       = acc[mt][nt][1];
                stg[(sr + 8) * 132 + sc]     = acc[mt][nt][2];
                stg[(sr + 8) * 132 + sc + 1] = acc[mt][nt][3];
            }
        }
        __syncthreads();
        const int* mrow = mask + (size_t)(z >> 4) * SEQ;
#pragma unroll
        for (int i = 0; i < 16; i++) {
            int idx = tid + i * 256, row = idx >> 5, c4 = (idx & 31) * 4;
            float4 v;
            v.x = stg[row * 132 + c4];
            v.y = stg[row * 132 + c4 + 1];
            v.z = stg[row * 132 + c4 + 2];
            v.w = stg[row * 132 + c4 + 3];
            int4 mk = *(const int4*)(mrow + n0 + c4);
            v.x = mk.x ? v.x : -1e9f;
            v.y = mk.y ? v.y : -1e9f;
            v.z = mk.z ? v.z : -1e9f;
            v.w = mk.w ? v.w : -1e9f;
            *(float4*)(Cf + co + (size_t)(m0 + row) * ldc + n0 + c4) = v;
        }
        return;
    }
#pragma unroll
    for (int mt = 0; mt < 2; mt++) {
        int r0 = m0 + warp_m * 32 + mt * 16 + g;
#pragma unroll
        for (int nt = 0; nt < NT; nt++) {
            int col = n0 + warp_n * NT * 8 + nt * 8 + q * 2;
            float c0 = acc[mt][nt][0], c1 = acc[mt][nt][1];
            float c2 = acc[mt][nt][2], c3 = acc[mt][nt][3];
            if (EPI == 0) {
                float b0v = bias[col], b1v = bias[col + 1];
                float2 v0, v1;
                v0.x = c0 + b0v; v0.y = c1 + b1v;
                v1.x = c2 + b0v; v1.y = c3 + b1v;
                *(float2*)(Cf + co + (size_t)r0 * ldc + col)       = v0;
                *(float2*)(Cf + co + (size_t)(r0 + 8) * ldc + col) = v1;
            } else {
                float b0v, b1v;
                if (EPI == 5) {
                    int seg = col >> 10, cc = col & 1023;
                    const float* bp = (seg == 0) ? bias : ((seg == 1) ? bias2 : bias3);
                    float sc = (seg == 0) ? 0.125f : 1.0f;
                    b0v = bp[cc] * sc; b1v = bp[cc + 1] * sc;
                } else {
                    b0v = bias[col]; b1v = bias[col + 1];
                }
                c0 += b0v; c1 += b1v; c2 += b0v; c3 += b1v;
                if (EPI == 2) {
                    c0 = fmaxf(c0, 0.f); c1 = fmaxf(c1, 0.f);
                    c2 = fmaxf(c2, 0.f); c3 = fmaxf(c3, 0.f);
                }
                size_t o0 = co + (size_t)r0 * ldc + col;
                size_t o1 = co + (size_t)(r0 + 8) * ldc + col;
                split_store2(c0, c1, Chi + o0, Clo + o0);
                split_store2(c2, c3, Chi + o1, Clo + o1);
            }
        }
    }
}

// ================= ctx = attn(fp32, converted in-kernel) @ Vt^T =================
__global__ void __launch_bounds__(256) ctx_mm(
    const float* __restrict__ attn,
    const __nv_bfloat16* __restrict__ Bh, const __nv_bfloat16* __restrict__ Bl,
    __nv_bfloat16* __restrict__ Chi, __nv_bfloat16* __restrict__ Clo)
{
    constexpr int NT = 4;
    constexpr int ABYTES = 128 * 80;
    constexpr int BBYTES = 64 * 80;
    constexpr int BUFB = 2 * ABYTES + 2 * BBYTES;
    extern __shared__ __align__(128) char smem[];
    const unsigned sb = s2u(smem);
    const int tid = threadIdx.x;
    const int m0 = blockIdx.y * 128, z = blockIdx.z;
    const float* ab = attn + (size_t)z * SEQ * SEQ;
    const size_t bo = (size_t)z * DK * SEQ;
    const size_t co = (size_t)(z >> 4) * SEQ * D_MODEL + (size_t)(z & 15) * DK;

    const int lane = tid & 31, w = tid >> 5;
    const int warp_m = w & 3, warp_n = w >> 2;

    float acc[2][NT][4];
#pragma unroll
    for (int mt = 0; mt < 2; mt++)
#pragma unroll
        for (int nt = 0; nt < NT; nt++)
#pragma unroll
            for (int e = 0; e < 4; e++) acc[mt][nt][e] = 0.f;

    const int arow = tid >> 3, ac4 = tid & 7;
    float4 ra[4];
    auto loadA = [&](int c){
#pragma unroll
        for (int i = 0; i < 4; i++)
            ra[i] = *(const float4*)(ab + (size_t)(m0 + arow + i * 32) * SEQ + c * 32 + ac4 * 4);
    };
    auto storeA = [&](int buf){
        char* bp = smem + buf * BUFB;
#pragma unroll
        for (int i = 0; i < 4; i++) {
            __nv_bfloat162 h0, h1, l0, l1;
            h0.x = __float2bfloat16(ra[i].x); h0.y = __float2bfloat16(ra[i].y);
            h1.x = __float2bfloat16(ra[i].z); h1.y = __float2bfloat16(ra[i].w);
            l0.x = __float2bfloat16(ra[i].x - __bfloat162float(h0.x));
            l0.y = __float2bfloat16(ra[i].y - __bfloat162float(h0.y));
            l1.x = __float2bfloat16(ra[i].z - __bfloat162float(h1.x));
            l1.y = __float2bfloat16(ra[i].w - __bfloat162float(h1.y));
            uint2 uh, ul;
            uh.x = *(unsigned*)&h0; uh.y = *(unsigned*)&h1;
            ul.x = *(unsigned*)&l0; ul.y = *(unsigned*)&l1;
            unsigned so = (arow + i * 32) * 80 + ac4 * 8;
            *(uint2*)(bp + so)          = uh;
            *(uint2*)(bp + ABYTES + so) = ul;
        }
    };
    auto loadB = [&](int c, int buf){
        unsigned sbuf = sb + buf * BUFB + 2 * ABYTES;
        int row = tid >> 2, ch = tid & 3;
        unsigned so = row * 80 + ch * 16;
        cpa(sbuf + so,          Bh + bo + (size_t)row * SEQ + c * 32 + ch * 8);
        cpa(sbuf + BBYTES + so, Bl + bo + (size_t)row * SEQ + c * 32 + ch * 8);
    };

    loadA(0);
    loadB(0, 0);
    asm volatile("cp.async.commit_group;");

    const int nchunk = SEQ / 32;
    for (int c = 0; c < nchunk; c++) {
        storeA(c & 1);
        if (c + 1 < nchunk) {
            loadA(c + 1);
            loadB(c + 1, (c + 1) & 1);
            asm volatile("cp.async.commit_group;");
            asm volatile("cp.async.wait_group 1;");
        } else {
            asm volatile("cp.async.wait_group 0;");
        }
        __syncthreads();

        unsigned sbuf = sb + (c & 1) * BUFB;
        unsigned sa  = sbuf + (warp_m * 32 + (lane & 15)) * 80 + (lane >> 4) * 16;
        unsigned sbb = sbuf + 2 * ABYTES
                     + (warp_n * 32 + (lane & 7) + ((lane >> 4) << 3)) * 80
                     + ((lane >> 3) & 1) * 16;
#pragma unroll
        for (int ks = 0; ks < 2; ks++) {
            unsigned ah[2][4], al[2][4];
            ldmx4(ah[0], sa + ks * 32);
            ldmx4(ah[1], sa + 16 * 80 + ks * 32);
            ldmx4(al[0], sa + ABYTES + ks * 32);
            ldmx4(al[1], sa + ABYTES + 16 * 80 + ks * 32);
#pragma unroll
            for (int p = 0; p < NT / 2; p++) {
                unsigned bh[4], bl[4];
                ldmx4(bh, sbb + p * 16 * 80 + ks * 32);
                ldmx4(bl, sbb + BBYTES + p * 16 * 80 + ks * 32);
#pragma unroll
                for (int mt = 0; mt < 2; mt++)
#pragma unroll
                    for (int t = 0; t < 2; t++) {
                        float* cc = acc[mt][2 * p + t];
                        mma16816(cc, ah[mt], bh[2 * t], bh[2 * t + 1]);
                        mma16816(cc, ah[mt], bl[2 * t], bl[2 * t + 1]);
                        mma16816(cc, al[mt], bh[2 * t], bh[2 * t + 1]);
                    }
            }
        }
        __syncthreads();
    }

    const int g = lane >> 2, q = lane & 3;
#pragma unroll
    for (int mt = 0; mt < 2; mt++) {
        int r0 = m0 + warp_m * 32 + mt * 16 + g;
#pragma unroll
        for (int nt = 0; nt < NT; nt++) {
            int col = warp_n * 32 + nt * 8 + q * 2;
            size_t o0 = co + (size_t)r0 * D_MODEL + col;
            size_t o1 = co + (size_t)(r0 + 8) * D_MODEL + col;
            split_store2(acc[mt][nt][0], acc[mt][nt][1], Chi + o0, Clo + o0);
            split_store2(acc[mt][nt][2], acc[mt][nt][3], Chi + o1, Clo + o1);
        }
    }
}

// ---------------- fp32 -> bf16 hi/lo ----------------
__global__ void __launch_bounds__(256) split_conv(const float* __restrict__ in,
                                                  __nv_bfloat16* __restrict__ oh,
                                                  __nv_bfloat16* __restrict__ ol, int n4)
{
    int i = blockIdx.x * 256 + threadIdx.x;
    if (i >= n4) return;
    float4 v = ((const float4*)in)[i];
    __nv_bfloat16 h0 = __float2bfloat16(v.x), h1 = __float2bfloat16(v.y);
    __nv_bfloat16 h2 = __float2bfloat16(v.z), h3 = __float2bfloat16(v.w);
    __nv_bfloat162 hp0, hp1, lp0, lp1;
    hp0.x = h0; hp0.y = h1; hp1.x = h2; hp1.y = h3;
    lp0.x = __float2bfloat16(v.x - __bfloat162float(h0));
    lp0.y = __float2bfloat16(v.y - __bfloat162float(h1));
    lp1.x = __float2bfloat16(v.z - __bfloat162float(h2));
    lp1.y = __float2bfloat16(v.w - __bfloat162float(h3));
    ((__nv_bfloat162*)oh)[i * 2]     = hp0;
    ((__nv_bfloat162*)oh)[i * 2 + 1] = hp1;
    ((__nv_bfloat162*)ol)[i * 2]     = lp0;
    ((__nv_bfloat162*)ol)[i * 2 + 1] = lp1;
}

// ---------------- transpose fp32 [R][C] -> bf16 hi/lo [C][R], with scale ----------------
__global__ void transp_split(const float* __restrict__ in, int ild,
                             __nv_bfloat16* __restrict__ oh, __nv_bfloat16* __restrict__ ol,
                             int old_, float scale)
{
    __shared__ float t[32][33];
    const float* ip = in;
    int r0 = blockIdx.y * 32, c0 = blockIdx.x * 32;
    int tx = threadIdx.x, ty = threadIdx.y;
#pragma unroll
    for (int i = 0; i < 32; i += 8) t[ty + i][tx] = ip[(size_t)(r0 + ty + i) * ild + c0 + tx] * scale;
    __syncthreads();
#pragma unroll
    for (int i = 0; i < 32; i += 8) {
        float v = t[tx][ty + i];
        __nv_bfloat16 hh = __float2bfloat16(v);
        size_t o = (size_t)(c0 + ty + i) * old_ + r0 + tx;
        oh[o] = hh;
        ol[o] = __float2bfloat16(v - __bfloat162float(hh));
    }
}

// ---------------- per-head V transpose from split-bf16 QKV ----------------
// in: qkv hi/lo [4096][3072], V at cols 2048+h*64; out: Vt [z][64][2048] hi/lo
__global__ void transp_v(const __nv_bfloat16* __restrict__ ih, const __nv_bfloat16* __restrict__ il,
                         __nv_bfloat16* __restrict__ oh, __nv_bfloat16* __restrict__ ol)
{
    __shared__ __nv_bfloat16 th[32][33], tl[32][33];
    int z = blockIdx.z, b = z >> 4, h = z & 15;
    const size_t ib = (size_t)b * SEQ * QKV3 + 2048 + (size_t)h * DK;
    const size_t ob = (size_t)z * DK * SEQ;
    int r0 = blockIdx.y * 32, c0 = blockIdx.x * 32;   // r: seq pos, c: dk idx
    int tx = threadIdx.x, ty = threadIdx.y;
#pragma unroll
    for (int i = 0; i < 32; i += 8) {
        size_t o = ib + (size_t)(r0 + ty + i) * QKV3 + c0 + tx;
        th[ty + i][tx] = ih[o];
        tl[ty + i][tx] = il[o];
    }
    __syncthreads();
#pragma unroll
    for (int i = 0; i < 32; i += 8) {
        size_t o = ob + (size_t)(c0 + ty + i) * SEQ + r0 + tx;
        oh[o] = th[tx][ty + i];
        ol[o] = tl[tx][ty + i];
    }
}

// ---------------- row softmax in place (fp32 only) ----------------
__global__ void __launch_bounds__(256) softmax_kernel(float* __restrict__ attn)
{
    const size_t row = blockIdx.x;
    float* p = attn + row * SEQ;
    const int tid = threadIdx.x;
    const int lane = tid & 31, wid = tid >> 5;
    __shared__ float red[8];

    float v[8];
    float mx = -3.4e38f;
#pragma unroll
    for (int e = 0; e < 8; e++) { v[e] = p[tid + e * 256]; mx = fmaxf(mx, v[e]); }
#pragma unroll
    for (int o = 16; o > 0; o >>= 1) mx = fmaxf(mx, __shfl_xor_sync(0xffffffffu, mx, o));
    if (lane == 0) red[wid] = mx;
    __syncthreads();
    float m2 = red[0];
#pragma unroll
    for (int w = 1; w < 8; w++) m2 = fmaxf(m2, red[w]);
    __syncthreads();

    float s = 0.f;
#pragma unroll
    for (int e = 0; e < 8; e++) { v[e] = __expf(v[e] - m2); s += v[e]; }
#pragma unroll
    for (int o = 16; o > 0; o >>= 1) s += __shfl_xor_sync(0xffffffffu, s, o);
    if (lane == 0) red[wid] = s;
    __syncthreads();
    float tot = 0.f;
#pragma unroll
    for (int w = 0; w < 8; w++) tot += red[w];
    float inv = 1.0f / tot;
#pragma unroll
    for (int e = 0; e < 8; e++) p[tid + e * 256] = v[e] * inv;
}

// ---------------- out = LayerNorm(X + Y), optional bf16 split output ----------------
template<int SPLIT>
__global__ void __launch_bounds__(256) add_ln_kernel(const float* __restrict__ X,
                                                     const float* __restrict__ Y,
                                                     const float* __restrict__ gamma,
                                                     const float* __restrict__ beta,
                                                     float* __restrict__ out,
                                                     __nv_bfloat16* __restrict__ oh,
                                                     __nv_bfloat16* __restrict__ ol)
{
    const int row = blockIdx.x;
    const int tid = threadIdx.x;
    const int lane = tid & 31, wid = tid >> 5;
    __shared__ float red[8];

    const float* xr = X + (size_t)row * D_MODEL;
    const float* yr = Y + (size_t)row * D_MODEL;
    float4 xv = *(const float4*)(xr + tid * 4);
    float4 yv = *(const float4*)(yr + tid * 4);
    float v0 = xv.x + yv.x, v1 = xv.y + yv.y, v2 = xv.z + yv.z, v3 = xv.w + yv.w;

    float s = v0 + v1 + v2 + v3;
#pragma unroll
    for (int o = 16; o > 0; o >>= 1) s += __shfl_xor_sync(0xffffffffu, s, o);
    if (lane == 0) red[wid] = s;
    __syncthreads();
    float tot = 0.f;
#pragma unroll
    for (int w = 0; w < 8; w++) tot += red[w];
    float mu = tot * (1.0f / D_MODEL);
    __syncthreads();

    float d0 = v0 - mu, d1 = v1 - mu, d2 = v2 - mu, d3 = v3 - mu;
    float sq = d0 * d0 + d1 * d1 + d2 * d2 + d3 * d3;
#pragma unroll
    for (int o = 16; o > 0; o >>= 1) sq += __shfl_xor_sync(0xffffffffu, sq, o);
    if (lane == 0) red[wid] = sq;
    __syncthreads();
    float vtot = 0.f;
#pragma unroll
    for (int w = 0; w < 8; w++) vtot += red[w];
    float inv = rsqrtf(vtot * (1.0f / D_MODEL) + EPS);

    float4 gv = *(const float4*)(gamma + tid * 4);
    float4 bv = *(const float4*)(beta + tid * 4);
    float o0 = d0 * inv * gv.x + bv.x;
    float o1 = d1 * inv * gv.y + bv.y;
    float o2 = d2 * inv * gv.z + bv.z;
    float o3 = d3 * inv * gv.w + bv.w;
    float4 o4; o4.x = o0; o4.y = o1; o4.z = o2; o4.w = o3;
    *(float4*)(out + (size_t)row * D_MODEL + tid * 4) = o4;
    if (SPLIT) {
        size_t base = (size_t)row * D_MODEL + tid * 4;
        split_store2(o0, o1, oh + base, ol + base);
        split_store2(o2, o3, oh + base + 2, ol + base + 2);
    }
}

// ---------------- host ----------------
#define GETP(var, sym) void* var; cudaGetSymbolAddress(&var, sym)
#define BF(p) ((__nv_bfloat16*)(p))

extern "C" void kernel_launch(void* const* d_in, const int* in_sizes, int n_in,
                              void* d_out, int out_size)
{
    const float* x   = (const float*)d_in[0];
    const int*   msk = (const int*)  d_in[1];
    const float* Wq  = (const float*)d_in[2];
    const float* bq  = (const float*)d_in[3];
    const float* Wk  = (const float*)d_in[4];
    const float* bk  = (const float*)d_in[5];
    const float* Wv  = (const float*)d_in[6];
    const float* bv  = (const float*)d_in[7];
    const float* Wo  = (const float*)d_in[8];
    const float* bo  = (const float*)d_in[9];
    const float* g1  = (const float*)d_in[10];
    const float* be1 = (const float*)d_in[11];
    const float* W1  = (const float*)d_in[12];
    const float* b1  = (const float*)d_in[13];
    const float* W2  = (const float*)d_in[14];
    const float* b2  = (const float*)d_in[15];
    const float* g2  = (const float*)d_in[16];
    const float* be2 = (const float*)d_in[17];
    float* out = (float*)d_out;

    GETP(pT, g_t);      GETP(pH, g_h);     GETP(pAf, g_attn_f32);
    GETP(pxh, g_xc_h);  GETP(pxl, g_xc_l);
    GETP(pWh, g_Wqkv_h); GETP(pWl, g_Wqkv_l);
    GETP(pWoh, g_Wot_h); GETP(pWol, g_Wot_l);
    GETP(pW1h, g_W1t_h); GETP(pW1l, g_W1t_l);
    GETP(pW2h, g_W2t_h); GETP(pW2l, g_W2t_l);
    GETP(pQKVh, g_qkv_h); GETP(pQKVl, g_qkv_l);
    GETP(pVth, g_Vt_h); GETP(pVtl, g_Vt_l);
    GETP(pCh, g_ctx_h); GETP(pCl, g_ctx_l);
    GETP(pHh, g_hc_h);  GETP(pHl, g_hc_l);
    GETP(pFh, g_ff_h);  GETP(pFl, g_ff_l);

    const size_t OUT_ELEMS  = (size_t)ROWS * D_MODEL;
    const size_t ATTN_ELEMS = (size_t)HZ * SEQ * SEQ;
    float* attn = ((size_t)out_size >= OUT_ELEMS + ATTN_ELEMS) ? out + OUT_ELEMS : (float*)pAf;

    const int SM128 = 2 * (2 * 128 * 80 + 2 * 128 * 80);    // 81920
    const int SMCTX = 2 * (2 * 128 * 80 + 2 * 64 * 80);     // 61440
    cudaFuncSetAttribute(gemm_mm<128,0,0,0,0>, cudaFuncAttributeMaxDynamicSharedMemorySize, SM128);
    cudaFuncSetAttribute(gemm_mm<128,2,0,0,0>, cudaFuncAttributeMaxDynamicSharedMemorySize, SM128);
    cudaFuncSetAttribute(gemm_mm<128,3,1,1,0>, cudaFuncAttributeMaxDynamicSharedMemorySize, SM128);
    cudaFuncSetAttribute(gemm_mm<128,5,0,0,0>, cudaFuncAttributeMaxDynamicSharedMemorySize, SM128);
    cudaFuncSetAttribute(ctx_mm,               cudaFuncAttributeMaxDynamicSharedMemorySize, SMCTX);

    dim3 blk(256);
    dim3 tblk(32, 8);

    // 0: x -> split
    split_conv<<<ROWS * D_MODEL / 4 / 256, blk>>>(x, BF(pxh), BF(pxl), ROWS * D_MODEL / 4);
    // 1-3: Wq (x0.125), Wk, Wv -> concat transposed split [3072][1024]
    transp_split<<<dim3(32, 32), tblk>>>(Wq, D_MODEL, BF(pWh), BF(pWl), D_MODEL, 0.125f);
    transp_split<<<dim3(32, 32), tblk>>>(Wk, D_MODEL, BF(pWh) + (size_t)1024 * D_MODEL,
                                         BF(pWl) + (size_t)1024 * D_MODEL, D_MODEL, 1.0f);
    transp_split<<<dim3(32, 32), tblk>>>(Wv, D_MODEL, BF(pWh) + (size_t)2048 * D_MODEL,
                                         BF(pWl) + (size_t)2048 * D_MODEL, D_MODEL, 1.0f);
    // 4: fused QKV GEMM  [4096,1024]@[1024,3072] -> split bf16 (ncu target A)
    gemm_mm<128,5,0,0,0><<<dim3(QKV3 / 128, 32, 1), blk, SM128>>>(
        BF(pxh), BF(pxl), D_MODEL, 0, BF(pWh), BF(pWl), D_MODEL, 0,
        nullptr, BF(pQKVh), BF(pQKVl), 0, QKV3, bq, bk, bv, nullptr, D_MODEL);
    // 5: scores GEMM (ncu target B)
    gemm_mm<128,3,1,1,0><<<dim3(16, 16, HZ), blk, SM128>>>(
        BF(pQKVh), BF(pQKVl), QKV3, 0, BF(pQKVh), BF(pQKVl), QKV3, 1024,
        attn, nullptr, nullptr, (long long)SEQ * SEQ, SEQ, nullptr, nullptr, nullptr, msk, DK);
    // 6: softmax
    softmax_kernel<<<HZ * SEQ, blk>>>(attn);
    // 7: Wo transpose, 8: V per-head transpose
    transp_split<<<dim3(32, 32), tblk>>>(Wo, D_MODEL, BF(pWoh), BF(pWol), D_MODEL, 1.0f);
    transp_v<<<dim3(2, 64, HZ), tblk>>>(BF(pQKVh), BF(pQKVl), BF(pVth), BF(pVtl));
    // 9: ctx
    ctx_mm<<<dim3(1, 16, HZ), blk, SMCTX>>>(attn, BF(pVth), BF(pVtl), BF(pCh), BF(pCl));
    // 10: O-proj, 11: LN1
    gemm_mm<128,0,0,0,0><<<dim3(8, 32, 1), blk, SM128>>>(
        BF(pCh), BF(pCl), D_MODEL, 0, BF(pWoh), BF(pWol), D_MODEL, 0,
        (float*)pT, nullptr, nullptr, 0, D_MODEL, bo, nullptr, nullptr, nullptr, D_MODEL);
    add_ln_kernel<1><<<ROWS, blk>>>(x, (const float*)pT, g1, be1, (float*)pH, BF(pHh), BF(pHl));
    // 12-13: FFN weights
    transp_split<<<dim3(128, 32), tblk>>>(W1, DFF,     BF(pW1h), BF(pW1l), D_MODEL, 1.0f);
    transp_split<<<dim3(32, 128), tblk>>>(W2, D_MODEL, BF(pW2h), BF(pW2l), DFF, 1.0f);
    // 14-16: FFN + LN2
    gemm_mm<128,2,0,0,0><<<dim3(32, 32, 1), blk, SM128>>>(
        BF(pHh), BF(pHl), D_MODEL, 0, BF(pW1h), BF(pW1l), D_MODEL, 0,
        nullptr, BF(pFh), BF(pFl), 0, DFF, b1, nullptr, nullptr, nullptr, D_MODEL);
    gemm_mm<128,0,0,0,0><<<dim3(8, 32, 1), blk, SM128>>>(
        BF(pFh), BF(pFl), DFF, 0, BF(pW2h), BF(pW2l), DFF, 0,
        (float*)pT, nullptr, nullptr, 0, D_MODEL, b2, nullptr, nullptr, nullptr, DFF);
    add_ln_kernel<0><<<ROWS, blk>>>((const float*)pH, (const float*)pT, g2, be2, out, nullptr, nullptr);
}

// round 7
// speedup vs baseline: 2.7528x; 1.1629x over previous
#include <cuda_runtime.h>
#include <cuda_fp16.h>
#include <math.h>

#define D_MODEL 1024
#define NHEAD   16
#define DK      64
#define DFF     4096
#define SEQ     2048
#define BATCH   2
#define ROWS    (BATCH*SEQ)
#define EPS     1e-5f
#define HZ      (BATCH*NHEAD)
#define QKV3    3072

// ---------------- scratch (no allocation allowed) ----------------
__device__ __align__(256) float g_t [(size_t)ROWS*D_MODEL];
__device__ __align__(256) float g_h [(size_t)ROWS*D_MODEL];
__device__ __align__(256) float g_attn_f32[(size_t)HZ*SEQ*SEQ];  // fallback only
__device__ __align__(256) float2 g_stats[(size_t)HZ*16*SEQ];     // per-tile (m, s)
__device__ __align__(256) float2 g_MS[(size_t)HZ*SEQ];           // per-row (M, 1/S)
__device__ __align__(256) __half g_xc_h [(size_t)ROWS*D_MODEL], g_xc_l [(size_t)ROWS*D_MODEL];
__device__ __align__(256) __half g_Wqkv_h[(size_t)QKV3*D_MODEL], g_Wqkv_l[(size_t)QKV3*D_MODEL];
__device__ __align__(256) __half g_Wot_h[(size_t)D_MODEL*D_MODEL], g_Wot_l[(size_t)D_MODEL*D_MODEL];
__device__ __align__(256) __half g_W1t_h[(size_t)D_MODEL*DFF],     g_W1t_l[(size_t)D_MODEL*DFF];
__device__ __align__(256) __half g_W2t_h[(size_t)D_MODEL*DFF],     g_W2t_l[(size_t)D_MODEL*DFF];
__device__ __align__(256) __half g_qkv_h[(size_t)ROWS*QKV3], g_qkv_l[(size_t)ROWS*QKV3];
__device__ __align__(256) __half g_Vt_h [(size_t)HZ*DK*SEQ],  g_Vt_l [(size_t)HZ*DK*SEQ];
__device__ __align__(256) __half g_ctx_h[(size_t)ROWS*D_MODEL], g_ctx_l[(size_t)ROWS*D_MODEL];
__device__ __align__(256) __half g_hc_h [(size_t)ROWS*D_MODEL];
__device__ __align__(256) __half g_ff_h [(size_t)ROWS*DFF];

// ---------------- helpers ----------------
__device__ __forceinline__ unsigned s2u(const void* p){
    unsigned a;
    asm("{ .reg .u64 t; cvta.to.shared.u64 t, %1; cvt.u32.u64 %0, t; }" : "=r"(a) : "l"(p));
    return a;
}
__device__ __forceinline__ void cpa(unsigned s, const void* g){
    asm volatile("cp.async.cg.shared.global [%0], [%1], 16;" :: "r"(s), "l"(g));
}
__device__ __forceinline__ void ldmx4(unsigned* r, unsigned addr){
    asm volatile("ldmatrix.sync.aligned.m8n8.x4.shared.b16 {%0,%1,%2,%3}, [%4];"
        : "=r"(r[0]), "=r"(r[1]), "=r"(r[2]), "=r"(r[3]) : "r"(addr));
}
__device__ __forceinline__ void mma16816(float* c, const unsigned* a, unsigned b0, unsigned b1){
    asm volatile("mma.sync.aligned.m16n8k16.row.col.f32.f16.f16.f32 "
        "{%0,%1,%2,%3}, {%4,%5,%6,%7}, {%8,%9}, {%0,%1,%2,%3};"
        : "+f"(c[0]), "+f"(c[1]), "+f"(c[2]), "+f"(c[3])
        : "r"(a[0]), "r"(a[1]), "r"(a[2]), "r"(a[3]), "r"(b0), "r"(b1));
}
__device__ __forceinline__ void split_h(float v0, float v1, __half* hi, __half* lo){
    __half h0 = __float2half_rn(v0), h1 = __float2half_rn(v1);
    *(__half2*)hi = __halves2half2(h0, h1);
    if (lo)
        *(__half2*)lo = __halves2half2(__float2half_rn(v0 - __half2float(h0)),
                                       __float2half_rn(v1 - __half2float(h1)));
}

// ================= split-fp16 HMMA GEMM =================
// EPI: 0 fp32+bias | 2 f16+bias+relu (hi only) | 3 fp32+mask+row-stats (scores) | 5 f16split 3-seg bias (QKV)
// TERMS: 3 = Ah*Bh + Ah*Bl + Al*Bh ; 2 = Ah*Bh + Ah*Bl (A single fp16)
template<int BN, int EPI, int AOFF, int BOFF, int COFF, int TERMS>
__global__ void __launch_bounds__(256) gemm_mm(
    const __half* __restrict__ Ah, const __half* __restrict__ Al, int lda, long long sAz,
    const __half* __restrict__ Bh, const __half* __restrict__ Bl, int ldb, long long sBz,
    float* __restrict__ Cf, __half* __restrict__ Chi, __half* __restrict__ Clo,
    long long sCz, int ldc,
    const float* __restrict__ bias, const float* __restrict__ bias2, const float* __restrict__ bias3,
    const int* __restrict__ mask, float2* __restrict__ stats, int K)
{
    constexpr int NT = BN / 16;
    constexpr int ABYTES = 128 * 80;
    constexpr int ASZ = (TERMS == 3 ? 2 : 1) * ABYTES;
    constexpr int BBYTES = BN * 80;
    constexpr int BUFB = ASZ + 2 * BBYTES;
    extern __shared__ __align__(128) char smem[];
    const unsigned sb = s2u(smem);
    const int tid = threadIdx.x;
    const int m0 = blockIdx.y * 128, n0 = blockIdx.x * BN, z = blockIdx.z;

    size_t ao = (AOFF == 1) ? ((size_t)(z >> 4) * SEQ * lda + (size_t)(z & 15) * DK + (size_t)sAz)
                            : (size_t)z * sAz;
    size_t bo = (BOFF == 1) ? ((size_t)(z >> 4) * SEQ * ldb + (size_t)(z & 15) * DK + (size_t)sBz)
                            : (size_t)z * sBz;
    size_t co = (COFF == 1) ? ((size_t)(z >> 4) * SEQ * ldc + (size_t)(z & 15) * DK)
                            : (size_t)z * sCz;

    const int lane = tid & 31, w = tid >> 5;
    const int warp_m = w & 3, warp_n = w >> 2;

    float acc[2][NT][4];
#pragma unroll
    for (int mt = 0; mt < 2; mt++)
#pragma unroll
        for (int nt = 0; nt < NT; nt++)
#pragma unroll
            for (int e = 0; e < 4; e++) acc[mt][nt][e] = 0.f;

    const int nchunk = K >> 5;

    auto load_tile = [&](int c, int buf) {
        unsigned sbuf = sb + buf * BUFB;
        const __half* pah = Ah + ao + (size_t)m0 * lda + c * 32;
        const __half* pal = (TERMS == 3) ? (Al + ao + (size_t)m0 * lda + c * 32) : nullptr;
#pragma unroll
        for (int i = 0; i < 2; i++) {
            int idx = tid + i * 256;
            int row = idx >> 2, ch = idx & 3;
            unsigned so = row * 80 + ch * 16;
            cpa(sbuf + so, pah + (size_t)row * lda + ch * 8);
            if (TERMS == 3) cpa(sbuf + ABYTES + so, pal + (size_t)row * lda + ch * 8);
        }
        const __half* pbh = Bh + bo + (size_t)n0 * ldb + c * 32;
        const __half* pbl = Bl + bo + (size_t)n0 * ldb + c * 32;
#pragma unroll
        for (int i = 0; i < BN / 64; i++) {
            int idx = tid + i * 256;
            int row = idx >> 2, ch = idx & 3;
            unsigned so = row * 80 + ch * 16;
            cpa(sbuf + ASZ + so,          pbh + (size_t)row * ldb + ch * 8);
            cpa(sbuf + ASZ + BBYTES + so, pbl + (size_t)row * ldb + ch * 8);
        }
    };

    load_tile(0, 0);
    asm volatile("cp.async.commit_group;");

    for (int c = 0; c < nchunk; c++) {
        if (c + 1 < nchunk) {
            load_tile(c + 1, (c + 1) & 1);
            asm volatile("cp.async.commit_group;");
            asm volatile("cp.async.wait_group 1;");
        } else {
            asm volatile("cp.async.wait_group 0;");
        }
        __syncthreads();

        unsigned sbuf = sb + (c & 1) * BUFB;
        unsigned sa  = sbuf + (warp_m * 32 + (lane & 15)) * 80 + (lane >> 4) * 16;
        unsigned sbb = sbuf + ASZ
                     + (warp_n * (NT * 8) + (lane & 7) + ((lane >> 4) << 3)) * 80
                     + ((lane >> 3) & 1) * 16;
#pragma unroll
        for (int ks = 0; ks < 2; ks++) {
            unsigned ah[2][4], al[2][4];
            ldmx4(ah[0], sa + ks * 32);
            ldmx4(ah[1], sa + 16 * 80 + ks * 32);
            if (TERMS == 3) {
                ldmx4(al[0], sa + ABYTES + ks * 32);
                ldmx4(al[1], sa + ABYTES + 16 * 80 + ks * 32);
            }
#pragma unroll
            for (int p = 0; p < NT / 2; p++) {
                unsigned bh[4], bl[4];
                ldmx4(bh, sbb + p * 16 * 80 + ks * 32);
                ldmx4(bl, sbb + BBYTES + p * 16 * 80 + ks * 32);
#pragma unroll
                for (int mt = 0; mt < 2; mt++)
#pragma unroll
                    for (int t = 0; t < 2; t++) {
                        float* cc = acc[mt][2 * p + t];
                        mma16816(cc, ah[mt], bh[2 * t], bh[2 * t + 1]);
                        mma16816(cc, ah[mt], bl[2 * t], bl[2 * t + 1]);
                        if (TERMS == 3) mma16816(cc, al[mt], bh[2 * t], bh[2 * t + 1]);
                    }
            }
        }
        __syncthreads();
    }

    // -------- epilogue --------
    const int g = lane >> 2, q = lane & 3;
    if (EPI == 3) {
        float* stg = (float*)smem;
#pragma unroll
        for (int mt = 0; mt < 2; mt++) {
            int sr = warp_m * 32 + mt * 16 + g;
#pragma unroll
            for (int nt = 0; nt < NT; nt++) {
                int sc = warp_n * (NT * 8) + nt * 8 + q * 2;
                stg[sr * 132 + sc]           = acc[mt][nt][0];
                stg[sr * 132 + sc + 1]       = acc[mt][nt][1];
                stg[(sr + 8) * 132 + sc]     = acc[mt][nt][2];
                stg[(sr + 8) * 132 + sc + 1] = acc[mt][nt][3];
            }
        }
        __syncthreads();
        const int* mrow = mask + (size_t)(z >> 4) * SEQ;
        // coalesced masked raw writes
#pragma unroll
        for (int i = 0; i < 16; i++) {
            int idx = tid + i * 256, row = idx >> 5, c4 = (idx & 31) * 4;
            float4 v;
            v.x = stg[row * 132 + c4];
            v.y = stg[row * 132 + c4 + 1];
            v.z = stg[row * 132 + c4 + 2];
            v.w = stg[row * 132 + c4 + 3];
            int4 mk = *(const int4*)(mrow + n0 + c4);
            v.x = mk.x ? v.x : -1e9f;
            v.y = mk.y ? v.y : -1e9f;
            v.z = mk.z ? v.z : -1e9f;
            v.w = mk.w ? v.w : -1e9f;
            *(float4*)(Cf + co + (size_t)(m0 + row) * ldc + n0 + c4) = v;
        }
        // per-tile row stats (2 threads per row, masked)
        {
            int row = tid >> 1, half = tid & 1;
            float m = -3.4e38f;
#pragma unroll 8
            for (int c2 = 0; c2 < 64; c2++) {
                float xv = stg[row * 132 + half * 64 + c2];
                if (mrow[n0 + half * 64 + c2] == 0) xv = -1e9f;
                m = fmaxf(m, xv);
            }
            float m2 = fmaxf(m, __shfl_xor_sync(0xffffffffu, m, 1));
            float s = 0.f;
#pragma unroll 8
            for (int c2 = 0; c2 < 64; c2++) {
                float xv = stg[row * 132 + half * 64 + c2];
                if (mrow[n0 + half * 64 + c2] == 0) xv = -1e9f;
                s += __expf(xv - m2);
            }
            s += __shfl_xor_sync(0xffffffffu, s, 1);
            if (half == 0)
                stats[((size_t)z * 16 + blockIdx.x) * SEQ + m0 + row] = make_float2(m2, s);
        }
        return;
    }
#pragma unroll
    for (int mt = 0; mt < 2; mt++) {
        int r0 = m0 + warp_m * 32 + mt * 16 + g;
#pragma unroll
        for (int nt = 0; nt < NT; nt++) {
            int col = n0 + warp_n * NT * 8 + nt * 8 + q * 2;
            float c0 = acc[mt][nt][0], c1 = acc[mt][nt][1];
            float c2 = acc[mt][nt][2], c3 = acc[mt][nt][3];
            if (EPI == 0) {
                float b0v = bias[col], b1v = bias[col + 1];
                float2 v0, v1;
                v0.x = c0 + b0v; v0.y = c1 + b1v;
                v1.x = c2 + b0v; v1.y = c3 + b1v;
                *(float2*)(Cf + co + (size_t)r0 * ldc + col)       = v0;
                *(float2*)(Cf + co + (size_t)(r0 + 8) * ldc + col) = v1;
            } else {
                float b0v, b1v;
                if (EPI == 5) {
                    int seg = col >> 10, cc = col & 1023;
                    const float* bp = (seg == 0) ? bias : ((seg == 1) ? bias2 : bias3);
                    float sc = (seg == 0) ? 0.125f : 1.0f;
                    b0v = bp[cc] * sc; b1v = bp[cc + 1] * sc;
                } else {
                    b0v = bias[col]; b1v = bias[col + 1];
                }
                c0 += b0v; c1 += b1v; c2 += b0v; c3 += b1v;
                if (EPI == 2) {
                    c0 = fmaxf(c0, 0.f); c1 = fmaxf(c1, 0.f);
                    c2 = fmaxf(c2, 0.f); c3 = fmaxf(c3, 0.f);
                }
                size_t o0 = co + (size_t)r0 * ldc + col;
                size_t o1 = co + (size_t)(r0 + 8) * ldc + col;
                split_h(c0, c1, Chi + o0, Clo ? Clo + o0 : nullptr);
                split_h(c2, c3, Chi + o1, Clo ? Clo + o1 : nullptr);
            }
        }
    }
}

// ---------------- merge per-tile stats -> per-row (M, 1/S) ----------------
__global__ void __launch_bounds__(256) merge_stats(const float2* __restrict__ stats,
                                                   float2* __restrict__ MS)
{
    int idx = blockIdx.x * 256 + threadIdx.x;     // HZ*SEQ total
    int z = idx >> 11, r = idx & 2047;
    float2 t[16];
    float M = -3.4e38f;
#pragma unroll
    for (int jt = 0; jt < 16; jt++) {
        t[jt] = stats[((size_t)z * 16 + jt) * SEQ + r];
        M = fmaxf(M, t[jt].x);
    }
    float S = 0.f;
#pragma unroll
    for (int jt = 0; jt < 16; jt++) S += t[jt].y * __expf(t[jt].x - M);
    MS[(size_t)z * SEQ + r] = make_float2(M, 1.0f / S);
}

// ================= ctx: normalize raw scores in-place + GEMM with Vt =================
__global__ void __launch_bounds__(256) ctx_mm(
    float* __restrict__ attn, const float2* __restrict__ MS,
    const __half* __restrict__ Bh, const __half* __restrict__ Bl,
    __half* __restrict__ Chi, __half* __restrict__ Clo)
{
    constexpr int NT = 4;
    constexpr int ABYTES = 128 * 80;
    constexpr int BBYTES = 64 * 80;
    constexpr int BUFB = 2 * ABYTES + 2 * BBYTES;
    extern __shared__ __align__(128) char smem[];
    const unsigned sb = s2u(smem);
    const int tid = threadIdx.x;
    const int m0 = blockIdx.y * 128, z = blockIdx.z;
    float* ab = attn + (size_t)z * SEQ * SEQ;
    const size_t bo = (size_t)z * DK * SEQ;
    const size_t co = (size_t)(z >> 4) * SEQ * D_MODEL + (size_t)(z & 15) * DK;

    const int lane = tid & 31, w = tid >> 5;
    const int warp_m = w & 3, warp_n = w >> 2;

    float acc[2][NT][4];
#pragma unroll
    for (int mt = 0; mt < 2; mt++)
#pragma unroll
        for (int nt = 0; nt < NT; nt++)
#pragma unroll
            for (int e = 0; e < 4; e++) acc[mt][nt][e] = 0.f;

    const int arow = tid >> 3, ac4 = tid & 7;
    float2 ms[4];
#pragma unroll
    for (int i = 0; i < 4; i++) ms[i] = MS[(size_t)z * SEQ + m0 + arow + i * 32];

    float4 ra[4];
    auto loadA = [&](int c){
#pragma unroll
        for (int i = 0; i < 4; i++)
            ra[i] = *(const float4*)(ab + (size_t)(m0 + arow + i * 32) * SEQ + c * 32 + ac4 * 4);
    };
    auto storeA = [&](int c, int buf){
        char* bp = smem + buf * BUFB;
#pragma unroll
        for (int i = 0; i < 4; i++) {
            float4 p;
            p.x = __expf(ra[i].x - ms[i].x) * ms[i].y;
            p.y = __expf(ra[i].y - ms[i].x) * ms[i].y;
            p.z = __expf(ra[i].z - ms[i].x) * ms[i].y;
            p.w = __expf(ra[i].w - ms[i].x) * ms[i].y;
            *(float4*)(ab + (size_t)(m0 + arow + i * 32) * SEQ + c * 32 + ac4 * 4) = p;
            __half2 h0 = __halves2half2(__float2half_rn(p.x), __float2half_rn(p.y));
            __half2 h1 = __halves2half2(__float2half_rn(p.z), __float2half_rn(p.w));
            __half2 l0 = __halves2half2(__float2half_rn(p.x - __low2float(h0)),
                                        __float2half_rn(p.y - __high2float(h0)));
            __half2 l1 = __halves2half2(__float2half_rn(p.z - __low2float(h1)),
                                        __float2half_rn(p.w - __high2float(h1)));
            uint2 uh, ul;
            uh.x = *(unsigned*)&h0; uh.y = *(unsigned*)&h1;
            ul.x = *(unsigned*)&l0; ul.y = *(unsigned*)&l1;
            unsigned so = (arow + i * 32) * 80 + ac4 * 8;
            *(uint2*)(bp + so)          = uh;
            *(uint2*)(bp + ABYTES + so) = ul;
        }
    };
    auto loadB = [&](int c, int buf){
        unsigned sbuf = sb + buf * BUFB + 2 * ABYTES;
        int row = tid >> 2, ch = tid & 3;
        unsigned so = row * 80 + ch * 16;
        cpa(sbuf + so,          Bh + bo + (size_t)row * SEQ + c * 32 + ch * 8);
        cpa(sbuf + BBYTES + so, Bl + bo + (size_t)row * SEQ + c * 32 + ch * 8);
    };

    loadA(0);
    loadB(0, 0);
    asm volatile("cp.async.commit_group;");

    const int nchunk = SEQ / 32;
    for (int c = 0; c < nchunk; c++) {
        storeA(c, c & 1);
        if (c + 1 < nchunk) {
            loadA(c + 1);
            loadB(c + 1, (c + 1) & 1);
            asm volatile("cp.async.commit_group;");
            asm volatile("cp.async.wait_group 1;");
        } else {
            asm volatile("cp.async.wait_group 0;");
        }
        __syncthreads();

        unsigned sbuf = sb + (c & 1) * BUFB;
        unsigned sa  = sbuf + (warp_m * 32 + (lane & 15)) * 80 + (lane >> 4) * 16;
        unsigned sbb = sbuf + 2 * ABYTES
                     + (warp_n * 32 + (lane & 7) + ((lane >> 4) << 3)) * 80
                     + ((lane >> 3) & 1) * 16;
#pragma unroll
        for (int ks = 0; ks < 2; ks++) {
            unsigned ah[2][4], al[2][4];
            ldmx4(ah[0], sa + ks * 32);
            ldmx4(ah[1], sa + 16 * 80 + ks * 32);
            ldmx4(al[0], sa + ABYTES + ks * 32);
            ldmx4(al[1], sa + ABYTES + 16 * 80 + ks * 32);
#pragma unroll
            for (int p = 0; p < NT / 2; p++) {
                unsigned bh[4], bl[4];
                ldmx4(bh, sbb + p * 16 * 80 + ks * 32);
                ldmx4(bl, sbb + BBYTES + p * 16 * 80 + ks * 32);
#pragma unroll
                for (int mt = 0; mt < 2; mt++)
#pragma unroll
                    for (int t = 0; t < 2; t++) {
                        float* cc = acc[mt][2 * p + t];
                        mma16816(cc, ah[mt], bh[2 * t], bh[2 * t + 1]);
                        mma16816(cc, ah[mt], bl[2 * t], bl[2 * t + 1]);
                        mma16816(cc, al[mt], bh[2 * t], bh[2 * t + 1]);
                    }
            }
        }
        __syncthreads();
    }

    const int g = lane >> 2, q = lane & 3;
#pragma unroll
    for (int mt = 0; mt < 2; mt++) {
        int r0 = m0 + warp_m * 32 + mt * 16 + g;
#pragma unroll
        for (int nt = 0; nt < NT; nt++) {
            int col = warp_n * 32 + nt * 8 + q * 2;
            size_t o0 = co + (size_t)r0 * D_MODEL + col;
            size_t o1 = co + (size_t)(r0 + 8) * D_MODEL + col;
            split_h(acc[mt][nt][0], acc[mt][nt][1], Chi + o0, Clo + o0);
            split_h(acc[mt][nt][2], acc[mt][nt][3], Chi + o1, Clo + o1);
        }
    }
}

// ---------------- fp32 -> fp16 hi/lo ----------------
__global__ void __launch_bounds__(256) split_conv(const float* __restrict__ in,
                                                  __half* __restrict__ oh,
                                                  __half* __restrict__ ol, int n4)
{
    int i = blockIdx.x * 256 + threadIdx.x;
    if (i >= n4) return;
    float4 v = ((const float4*)in)[i];
    __half h0 = __float2half_rn(v.x), h1 = __float2half_rn(v.y);
    __half h2 = __float2half_rn(v.z), h3 = __float2half_rn(v.w);
    ((__half2*)oh)[i * 2]     = __halves2half2(h0, h1);
    ((__half2*)oh)[i * 2 + 1] = __halves2half2(h2, h3);
    ((__half2*)ol)[i * 2]     = __halves2half2(__float2half_rn(v.x - __half2float(h0)),
                                               __float2half_rn(v.y - __half2float(h1)));
    ((__half2*)ol)[i * 2 + 1] = __halves2half2(__float2half_rn(v.z - __half2float(h2)),
                                               __float2half_rn(v.w - __half2float(h3)));
}

// ---------------- transpose fp32 [R][C] -> fp16 hi/lo [C][R], with scale ----------------
__global__ void transp_split(const float* __restrict__ in, int ild,
                             __half* __restrict__ oh, __half* __restrict__ ol,
                             int old_, float scale)
{
    __shared__ float t[32][33];
    int r0 = blockIdx.y * 32, c0 = blockIdx.x * 32;
    int tx = threadIdx.x, ty = threadIdx.y;
#pragma unroll
    for (int i = 0; i < 32; i += 8) t[ty + i][tx] = in[(size_t)(r0 + ty + i) * ild + c0 + tx] * scale;
    __syncthreads();
#pragma unroll
    for (int i = 0; i < 32; i += 8) {
        float v = t[tx][ty + i];
        __half hh = __float2half_rn(v);
        size_t o = (size_t)(c0 + ty + i) * old_ + r0 + tx;
        oh[o] = hh;
        ol[o] = __float2half_rn(v - __half2float(hh));
    }
}

// ---------------- fused QKV weight transpose (z selects Wq/Wk/Wv) ----------------
__global__ void transp_w3(const float* __restrict__ Wq, const float* __restrict__ Wk,
                          const float* __restrict__ Wv,
                          __half* __restrict__ oh, __half* __restrict__ ol)
{
    __shared__ float t[32][33];
    int z = blockIdx.z;
    const float* in = (z == 0) ? Wq : (z == 1) ? Wk : Wv;
    float scale = (z == 0) ? 0.125f : 1.0f;
    size_t ob = (size_t)z * D_MODEL * D_MODEL;
    int r0 = blockIdx.y * 32, c0 = blockIdx.x * 32;
    int tx = threadIdx.x, ty = threadIdx.y;
#pragma unroll
    for (int i = 0; i < 32; i += 8) t[ty + i][tx] = in[(size_t)(r0 + ty + i) * D_MODEL + c0 + tx] * scale;
    __syncthreads();
#pragma unroll
    for (int i = 0; i < 32; i += 8) {
        float v = t[tx][ty + i];
        __half hh = __float2half_rn(v);
        size_t o = ob + (size_t)(c0 + ty + i) * D_MODEL + r0 + tx;
        oh[o] = hh;
        ol[o] = __float2half_rn(v - __half2float(hh));
    }
}

// ---------------- per-head V transpose from split-fp16 QKV ----------------
__global__ void transp_v(const __half* __restrict__ ih, const __half* __restrict__ il,
                         __half* __restrict__ oh, __half* __restrict__ ol)
{
    __shared__ __half th[32][33], tl[32][33];
    int z = blockIdx.z, b = z >> 4, h = z & 15;
    const size_t ib = (size_t)b * SEQ * QKV3 + 2048 + (size_t)h * DK;
    const size_t ob = (size_t)z * DK * SEQ;
    int r0 = blockIdx.y * 32, c0 = blockIdx.x * 32;
    int tx = threadIdx.x, ty = threadIdx.y;
#pragma unroll
    for (int i = 0; i < 32; i += 8) {
        size_t o = ib + (size_t)(r0 + ty + i) * QKV3 + c0 + tx;
        th[ty + i][tx] = ih[o];
        tl[ty + i][tx] = il[o];
    }
    __syncthreads();
#pragma unroll
    for (int i = 0; i < 32; i += 8) {
        size_t o = ob + (size_t)(c0 + ty + i) * SEQ + r0 + tx;
        oh[o] = th[tx][ty + i];
        ol[o] = tl[tx][ty + i];
    }
}

// ---------------- out = LayerNorm(X + Y), optional fp16 hi output ----------------
template<int SPLIT>
__global__ void __launch_bounds__(256) add_ln_kernel(const float* __restrict__ X,
                                                     const float* __restrict__ Y,
                                                     const float* __restrict__ gamma,
                                                     const float* __restrict__ beta,
                                                     float* __restrict__ out,
                                                     __half* __restrict__ oh)
{
    const int row = blockIdx.x;
    const int tid = threadIdx.x;
    const int lane = tid & 31, wid = tid >> 5;
    __shared__ float red[8];

    const float* xr = X + (size_t)row * D_MODEL;
    const float* yr = Y + (size_t)row * D_MODEL;
    float4 xv = *(const float4*)(xr + tid * 4);
    float4 yv = *(const float4*)(yr + tid * 4);
    float v0 = xv.x + yv.x, v1 = xv.y + yv.y, v2 = xv.z + yv.z, v3 = xv.w + yv.w;

    float s = v0 + v1 + v2 + v3;
#pragma unroll
    for (int o = 16; o > 0; o >>= 1) s += __shfl_xor_sync(0xffffffffu, s, o);
    if (lane == 0) red[wid] = s;
    __syncthreads();
    float tot = 0.f;
#pragma unroll
    for (int w = 0; w < 8; w++) tot += red[w];
    float mu = tot * (1.0f / D_MODEL);
    __syncthreads();

    float d0 = v0 - mu, d1 = v1 - mu, d2 = v2 - mu, d3 = v3 - mu;
    float sq = d0 * d0 + d1 * d1 + d2 * d2 + d3 * d3;
#pragma unroll
    for (int o = 16; o > 0; o >>= 1) sq += __shfl_xor_sync(0xffffffffu, sq, o);
    if (lane == 0) red[wid] = sq;
    __syncthreads();
    float vtot = 0.f;
#pragma unroll
    for (int w = 0; w < 8; w++) vtot += red[w];
    float inv = rsqrtf(vtot * (1.0f / D_MODEL) + EPS);

    float4 gv = *(const float4*)(gamma + tid * 4);
    float4 bv = *(const float4*)(beta + tid * 4);
    float o0 = d0 * inv * gv.x + bv.x;
    float o1 = d1 * inv * gv.y + bv.y;
    float o2 = d2 * inv * gv.z + bv.z;
    float o3 = d3 * inv * gv.w + bv.w;
    float4 o4; o4.x = o0; o4.y = o1; o4.z = o2; o4.w = o3;
    *(float4*)(out + (size_t)row * D_MODEL + tid * 4) = o4;
    if (SPLIT) {
        size_t base = (size_t)row * D_MODEL + tid * 4;
        ((__half2*)(oh + base))[0] = __halves2half2(__float2half_rn(o0), __float2half_rn(o1));
        ((__half2*)(oh + base))[1] = __halves2half2(__float2half_rn(o2), __float2half_rn(o3));
    }
}

// ---------------- host ----------------
#define GETP(var, sym) void* var; cudaGetSymbolAddress(&var, sym)
#define HF(p) ((__half*)(p))

extern "C" void kernel_launch(void* const* d_in, const int* in_sizes, int n_in,
                              void* d_out, int out_size)
{
    const float* x   = (const float*)d_in[0];
    const int*   msk = (const int*)  d_in[1];
    const float* Wq  = (const float*)d_in[2];
    const float* bq  = (const float*)d_in[3];
    const float* Wk  = (const float*)d_in[4];
    const float* bk  = (const float*)d_in[5];
    const float* Wv  = (const float*)d_in[6];
    const float* bv  = (const float*)d_in[7];
    const float* Wo  = (const float*)d_in[8];
    const float* bo  = (const float*)d_in[9];
    const float* g1  = (const float*)d_in[10];
    const float* be1 = (const float*)d_in[11];
    const float* W1  = (const float*)d_in[12];
    const float* b1  = (const float*)d_in[13];
    const float* W2  = (const float*)d_in[14];
    const float* b2  = (const float*)d_in[15];
    const float* g2  = (const float*)d_in[16];
    const float* be2 = (const float*)d_in[17];
    float* out = (float*)d_out;

    GETP(pT, g_t);      GETP(pH, g_h);     GETP(pAf, g_attn_f32);
    GETP(pSt, g_stats); GETP(pMS, g_MS);
    GETP(pxh, g_xc_h);  GETP(pxl, g_xc_l);
    GETP(pWh, g_Wqkv_h); GETP(pWl, g_Wqkv_l);
    GETP(pWoh, g_Wot_h); GETP(pWol, g_Wot_l);
    GETP(pW1h, g_W1t_h); GETP(pW1l, g_W1t_l);
    GETP(pW2h, g_W2t_h); GETP(pW2l, g_W2t_l);
    GETP(pQKVh, g_qkv_h); GETP(pQKVl, g_qkv_l);
    GETP(pVth, g_Vt_h); GETP(pVtl, g_Vt_l);
    GETP(pCh, g_ctx_h); GETP(pCl, g_ctx_l);
    GETP(pHh, g_hc_h);
    GETP(pFh, g_ff_h);

    const size_t OUT_ELEMS  = (size_t)ROWS * D_MODEL;
    const size_t ATTN_ELEMS = (size_t)HZ * SEQ * SEQ;
    float* attn = ((size_t)out_size >= OUT_ELEMS + ATTN_ELEMS) ? out + OUT_ELEMS : (float*)pAf;

    const int SM3  = 2 * (2 * 128 * 80 + 2 * 128 * 80);   // 81920 (TERMS3, BN128; >= 67584 staging)
    const int SM2  = 2 * (1 * 128 * 80 + 2 * 128 * 80);   // 61440 (TERMS2, BN128)
    const int SMCTX = 2 * (2 * 128 * 80 + 2 * 64 * 80);   // 61440
    cudaFuncSetAttribute(gemm_mm<128,0,0,0,0,3>, cudaFuncAttributeMaxDynamicSharedMemorySize, SM3);
    cudaFuncSetAttribute(gemm_mm<128,5,0,0,0,3>, cudaFuncAttributeMaxDynamicSharedMemorySize, SM3);
    cudaFuncSetAttribute(gemm_mm<128,3,1,1,0,3>, cudaFuncAttributeMaxDynamicSharedMemorySize, SM3);
    cudaFuncSetAttribute(gemm_mm<128,2,0,0,0,2>, cudaFuncAttributeMaxDynamicSharedMemorySize, SM2);
    cudaFuncSetAttribute(gemm_mm<128,0,0,0,0,2>, cudaFuncAttributeMaxDynamicSharedMemorySize, SM2);
    cudaFuncSetAttribute(ctx_mm,                 cudaFuncAttributeMaxDynamicSharedMemorySize, SMCTX);

    dim3 blk(256);
    dim3 tblk(32, 8);

    // 0: x -> split
    split_conv<<<ROWS * D_MODEL / 4 / 256, blk>>>(x, HF(pxh), HF(pxl), ROWS * D_MODEL / 4);
    // 1: QKV weights fused transpose (Wq pre-scaled by 0.125)
    transp_w3<<<dim3(32, 32, 3), tblk>>>(Wq, Wk, Wv, HF(pWh), HF(pWl));
    // 2: Wo transpose
    transp_split<<<dim3(32, 32), tblk>>>(Wo, D_MODEL, HF(pWoh), HF(pWol), D_MODEL, 1.0f);
    // 3: fused QKV GEMM (profile target A)
    gemm_mm<128,5,0,0,0,3><<<dim3(QKV3 / 128, 32, 1), blk, SM3>>>(
        HF(pxh), HF(pxl), D_MODEL, 0, HF(pWh), HF(pWl), D_MODEL, 0,
        nullptr, HF(pQKVh), HF(pQKVl), 0, QKV3, bq, bk, bv, nullptr, nullptr, D_MODEL);
    // 4: scores GEMM + per-tile stats (profile target B)
    gemm_mm<128,3,1,1,0,3><<<dim3(16, 16, HZ), blk, SM3>>>(
        HF(pQKVh), HF(pQKVl), QKV3, 0, HF(pQKVh), HF(pQKVl), QKV3, 1024,
        attn, nullptr, nullptr, (long long)SEQ * SEQ, SEQ,
        nullptr, nullptr, nullptr, msk, (float2*)pSt, DK);
    // 5: merge stats
    merge_stats<<<HZ * SEQ / 256, blk>>>((const float2*)pSt, (float2*)pMS);
    // 6: V per-head transpose
    transp_v<<<dim3(2, 64, HZ), tblk>>>(HF(pQKVh), HF(pQKVl), HF(pVth), HF(pVtl));
    // 7: ctx (softmax fused, attn normalized in place)
    ctx_mm<<<dim3(1, 16, HZ), blk, SMCTX>>>(attn, (const float2*)pMS,
                                            HF(pVth), HF(pVtl), HF(pCh), HF(pCl));
    // 8: O-proj (3-term), 9: LN1 (hi-only split out)
    gemm_mm<128,0,0,0,0,3><<<dim3(8, 32, 1), blk, SM3>>>(
        HF(pCh), HF(pCl), D_MODEL, 0, HF(pWoh), HF(pWol), D_MODEL, 0,
        (float*)pT, nullptr, nullptr, 0, D_MODEL, bo, nullptr, nullptr, nullptr, nullptr, D_MODEL);
    add_ln_kernel<1><<<ROWS, blk>>>(x, (const float*)pT, g1, be1, (float*)pH, HF(pHh));
    // 10-11: FFN weights
    transp_split<<<dim3(128, 32), tblk>>>(W1, DFF,     HF(pW1h), HF(pW1l), D_MODEL, 1.0f);
    transp_split<<<dim3(32, 128), tblk>>>(W2, D_MODEL, HF(pW2h), HF(pW2l), DFF, 1.0f);
    // 12: FF1 (2-term, hi-only out), 13: FF2 (2-term), 14: LN2
    gemm_mm<128,2,0,0,0,2><<<dim3(32, 32, 1), blk, SM2>>>(
        HF(pHh), nullptr, D_MODEL, 0, HF(pW1h), HF(pW1l), D_MODEL, 0,
        nullptr, HF(pFh), nullptr, 0, DFF, b1, nullptr, nullptr, nullptr, nullptr, D_MODEL);
    gemm_mm<128,0,0,0,0,2><<<dim3(8, 32, 1), blk, SM2>>>(
        HF(pFh), nullptr, DFF, 0, HF(pW2h), HF(pW2l), DFF, 0,
        (float*)pT, nullptr, nullptr, 0, D_MODEL, b2, nullptr, nullptr, nullptr, nullptr, DFF);
    add_ln_kernel<0><<<ROWS, blk>>>((const float*)pH, (const float*)pT, g2, be2, out, nullptr);
}

// round 8
// speedup vs baseline: 2.9230x; 1.0618x over previous
#include <cuda_runtime.h>
#include <cuda_fp16.h>
#include <math.h>

#define D_MODEL 1024
#define NHEAD   16
#define DK      64
#define DFF     4096
#define SEQ     2048
#define BATCH   2
#define ROWS    (BATCH*SEQ)
#define EPS     1e-5f
#define HZ      (BATCH*NHEAD)
#define QKV3    3072

// ---------------- scratch (no allocation allowed) ----------------
__device__ __align__(256) float g_t [(size_t)ROWS*D_MODEL];
__device__ __align__(256) float g_h [(size_t)ROWS*D_MODEL];
__device__ __align__(256) float g_attn_f32[(size_t)HZ*SEQ*SEQ];  // fallback only
__device__ __align__(256) float2 g_stats[(size_t)HZ*16*SEQ];
__device__ __align__(256) float2 g_MS[(size_t)HZ*SEQ];
__device__ __align__(256) __half g_xc_h [(size_t)ROWS*D_MODEL], g_xc_l [(size_t)ROWS*D_MODEL];
__device__ __align__(256) __half g_Wqkv_h[(size_t)QKV3*D_MODEL], g_Wqkv_l[(size_t)QKV3*D_MODEL];
__device__ __align__(256) __half g_Wot_h[(size_t)D_MODEL*D_MODEL], g_Wot_l[(size_t)D_MODEL*D_MODEL];
__device__ __align__(256) __half g_W1t_h[(size_t)D_MODEL*DFF],     g_W1t_l[(size_t)D_MODEL*DFF];
__device__ __align__(256) __half g_W2t_h[(size_t)D_MODEL*DFF],     g_W2t_l[(size_t)D_MODEL*DFF];
__device__ __align__(256) __half g_qkv_h[(size_t)ROWS*QKV3], g_qkv_l[(size_t)ROWS*QKV3];
__device__ __align__(256) __half g_Vt_h [(size_t)HZ*DK*SEQ],  g_Vt_l [(size_t)HZ*DK*SEQ];
__device__ __align__(256) __half g_ctx_h[(size_t)ROWS*D_MODEL];
__device__ __align__(256) __half g_hc_h [(size_t)ROWS*D_MODEL];
__device__ __align__(256) __half g_ff_h [(size_t)ROWS*DFF];

// ---------------- helpers ----------------
__device__ __forceinline__ unsigned s2u(const void* p){
    unsigned a;
    asm("{ .reg .u64 t; cvta.to.shared.u64 t, %1; cvt.u32.u64 %0, t; }" : "=r"(a) : "l"(p));
    return a;
}
__device__ __forceinline__ void cpa(unsigned s, const void* g){
    asm volatile("cp.async.cg.shared.global [%0], [%1], 16;" :: "r"(s), "l"(g));
}
__device__ __forceinline__ void ldmx4(unsigned* r, unsigned addr){
    asm volatile("ldmatrix.sync.aligned.m8n8.x4.shared.b16 {%0,%1,%2,%3}, [%4];"
        : "=r"(r[0]), "=r"(r[1]), "=r"(r[2]), "=r"(r[3]) : "r"(addr));
}
__device__ __forceinline__ void mma16816(float* c, const unsigned* a, unsigned b0, unsigned b1){
    asm volatile("mma.sync.aligned.m16n8k16.row.col.f32.f16.f16.f32 "
        "{%0,%1,%2,%3}, {%4,%5,%6,%7}, {%8,%9}, {%0,%1,%2,%3};"
        : "+f"(c[0]), "+f"(c[1]), "+f"(c[2]), "+f"(c[3])
        : "r"(a[0]), "r"(a[1]), "r"(a[2]), "r"(a[3]), "r"(b0), "r"(b1));
}
__device__ __forceinline__ void split_h(float v0, float v1, __half* hi, __half* lo){
    __half h0 = __float2half_rn(v0), h1 = __float2half_rn(v1);
    *(__half2*)hi = __halves2half2(h0, h1);
    if (lo)
        *(__half2*)lo = __halves2half2(__float2half_rn(v0 - __half2float(h0)),
                                       __float2half_rn(v1 - __half2float(h1)));
}

// ================= split-fp16 HMMA GEMM =================
// EPI: 0 fp32+bias | 2 f16+bias+relu (hi only) | 3 fp32+mask+row-stats | 5 f16split 3-seg bias (QKV)
// TERMS: 3 = Ah*Bh + Ah*Bl + Al*Bh (2-stage, 2 sync) ; 2 = Ah*Bh + Ah*Bl (3-stage, 1 sync)
template<int BN, int EPI, int AOFF, int BOFF, int COFF, int TERMS>
__global__ void __launch_bounds__(256) gemm_mm(
    const __half* __restrict__ Ah, const __half* __restrict__ Al, int lda, long long sAz,
    const __half* __restrict__ Bh, const __half* __restrict__ Bl, int ldb, long long sBz,
    float* __restrict__ Cf, __half* __restrict__ Chi, __half* __restrict__ Clo,
    long long sCz, int ldc,
    const float* __restrict__ bias, const float* __restrict__ bias2, const float* __restrict__ bias3,
    const int* __restrict__ mask, float2* __restrict__ stats, int K)
{
    constexpr int NT = BN / 16;
    constexpr int ABYTES = 128 * 80;
    constexpr int ASZ = (TERMS == 3 ? 2 : 1) * ABYTES;
    constexpr int BBYTES = BN * 80;
    constexpr int BUFB = ASZ + 2 * BBYTES;
    constexpr int NSTAGE = (TERMS == 3) ? 2 : 3;
    extern __shared__ __align__(128) char smem[];
    const unsigned sb = s2u(smem);
    const int tid = threadIdx.x;
    const int m0 = blockIdx.y * 128, n0 = blockIdx.x * BN, z = blockIdx.z;

    size_t ao = (AOFF == 1) ? ((size_t)(z >> 4) * SEQ * lda + (size_t)(z & 15) * DK + (size_t)sAz)
                            : (size_t)z * sAz;
    size_t bo = (BOFF == 1) ? ((size_t)(z >> 4) * SEQ * ldb + (size_t)(z & 15) * DK + (size_t)sBz)
                            : (size_t)z * sBz;
    size_t co = (COFF == 1) ? ((size_t)(z >> 4) * SEQ * ldc + (size_t)(z & 15) * DK)
                            : (size_t)z * sCz;

    const int lane = tid & 31, w = tid >> 5;
    const int warp_m = w & 3, warp_n = w >> 2;

    float acc[2][NT][4];
#pragma unroll
    for (int mt = 0; mt < 2; mt++)
#pragma unroll
        for (int nt = 0; nt < NT; nt++)
#pragma unroll
            for (int e = 0; e < 4; e++) acc[mt][nt][e] = 0.f;

    const int nchunk = K >> 5;

    auto load_tile = [&](int c, int buf) {
        unsigned sbuf = sb + buf * BUFB;
        const __half* pah = Ah + ao + (size_t)m0 * lda + c * 32;
        const __half* pal = (TERMS == 3) ? (Al + ao + (size_t)m0 * lda + c * 32) : nullptr;
#pragma unroll
        for (int i = 0; i < 2; i++) {
            int idx = tid + i * 256;
            int row = idx >> 2, ch = idx & 3;
            unsigned so = row * 80 + ch * 16;
            cpa(sbuf + so, pah + (size_t)row * lda + ch * 8);
            if (TERMS == 3) cpa(sbuf + ABYTES + so, pal + (size_t)row * lda + ch * 8);
        }
        const __half* pbh = Bh + bo + (size_t)n0 * ldb + c * 32;
        const __half* pbl = Bl + bo + (size_t)n0 * ldb + c * 32;
#pragma unroll
        for (int i = 0; i < BN / 64; i++) {
            int idx = tid + i * 256;
            int row = idx >> 2, ch = idx & 3;
            unsigned so = row * 80 + ch * 16;
            cpa(sbuf + ASZ + so,          pbh + (size_t)row * ldb + ch * 8);
            cpa(sbuf + ASZ + BBYTES + so, pbl + (size_t)row * ldb + ch * 8);
        }
    };

    auto compute = [&](unsigned sbuf) {
        unsigned sa  = sbuf + (warp_m * 32 + (lane & 15)) * 80 + (lane >> 4) * 16;
        unsigned sbb = sbuf + ASZ
                     + (warp_n * (NT * 8) + (lane & 7) + ((lane >> 4) << 3)) * 80
                     + ((lane >> 3) & 1) * 16;
#pragma unroll
        for (int ks = 0; ks < 2; ks++) {
            unsigned ah[2][4], al[2][4];
            ldmx4(ah[0], sa + ks * 32);
            ldmx4(ah[1], sa + 16 * 80 + ks * 32);
            if (TERMS == 3) {
                ldmx4(al[0], sa + ABYTES + ks * 32);
                ldmx4(al[1], sa + ABYTES + 16 * 80 + ks * 32);
            }
#pragma unroll
            for (int p = 0; p < NT / 2; p++) {
                unsigned bh[4], bl[4];
                ldmx4(bh, sbb + p * 16 * 80 + ks * 32);
                ldmx4(bl, sbb + BBYTES + p * 16 * 80 + ks * 32);
#pragma unroll
                for (int mt = 0; mt < 2; mt++)
#pragma unroll
                    for (int t = 0; t < 2; t++) {
                        float* cc = acc[mt][2 * p + t];
                        mma16816(cc, ah[mt], bh[2 * t], bh[2 * t + 1]);
                        mma16816(cc, ah[mt], bl[2 * t], bl[2 * t + 1]);
                        if (TERMS == 3) mma16816(cc, al[mt], bh[2 * t], bh[2 * t + 1]);
                    }
            }
        }
    };

    if (NSTAGE == 3) {
        load_tile(0, 0);
        asm volatile("cp.async.commit_group;");
        if (nchunk > 1) { load_tile(1, 1); asm volatile("cp.async.commit_group;"); }
        for (int c = 0; c < nchunk; c++) {
            if (c + 1 < nchunk) asm volatile("cp.async.wait_group 1;");
            else                asm volatile("cp.async.wait_group 0;");
            __syncthreads();
            if (c + 2 < nchunk) {
                load_tile(c + 2, (c + 2) % 3);
                asm volatile("cp.async.commit_group;");
            }
            compute(sb + (c % 3) * BUFB);
        }
    } else {
        load_tile(0, 0);
        asm volatile("cp.async.commit_group;");
        for (int c = 0; c < nchunk; c++) {
            if (c + 1 < nchunk) {
                load_tile(c + 1, (c + 1) & 1);
                asm volatile("cp.async.commit_group;");
                asm volatile("cp.async.wait_group 1;");
            } else {
                asm volatile("cp.async.wait_group 0;");
            }
            __syncthreads();
            compute(sb + (c & 1) * BUFB);
            __syncthreads();
        }
    }

    // -------- epilogue --------
    const int g = lane >> 2, q = lane & 3;
    if (EPI == 3) {
        __syncthreads();
        float* stg = (float*)smem;
#pragma unroll
        for (int mt = 0; mt < 2; mt++) {
            int sr = warp_m * 32 + mt * 16 + g;
#pragma unroll
            for (int nt = 0; nt < NT; nt++) {
                int sc = warp_n * (NT * 8) + nt * 8 + q * 2;
                stg[sr * 132 + sc]           = acc[mt][nt][0];
                stg[sr * 132 + sc + 1]       = acc[mt][nt][1];
                stg[(sr + 8) * 132 + sc]     = acc[mt][nt][2];
                stg[(sr + 8) * 132 + sc + 1] = acc[mt][nt][3];
            }
        }
        __syncthreads();
        const int* mrow = mask + (size_t)(z >> 4) * SEQ;
#pragma unroll
        for (int i = 0; i < 16; i++) {
            int idx = tid + i * 256, row = idx >> 5, c4 = (idx & 31) * 4;
            float4 v;
            v.x = stg[row * 132 + c4];
            v.y = stg[row * 132 + c4 + 1];
            v.z = stg[row * 132 + c4 + 2];
            v.w = stg[row * 132 + c4 + 3];
            int4 mk = *(const int4*)(mrow + n0 + c4);
            v.x = mk.x ? v.x : -1e9f;
            v.y = mk.y ? v.y : -1e9f;
            v.z = mk.z ? v.z : -1e9f;
            v.w = mk.w ? v.w : -1e9f;
            *(float4*)(Cf + co + (size_t)(m0 + row) * ldc + n0 + c4) = v;
        }
        {
            int row = tid >> 1, half = tid & 1;
            float m = -3.4e38f;
#pragma unroll 8
            for (int c2 = 0; c2 < 64; c2++) {
                float xv = stg[row * 132 + half * 64 + c2];
                if (mrow[n0 + half * 64 + c2] == 0) xv = -1e9f;
                m = fmaxf(m, xv);
            }
            float m2 = fmaxf(m, __shfl_xor_sync(0xffffffffu, m, 1));
            float s = 0.f;
#pragma unroll 8
            for (int c2 = 0; c2 < 64; c2++) {
                float xv = stg[row * 132 + half * 64 + c2];
                if (mrow[n0 + half * 64 + c2] == 0) xv = -1e9f;
                s += __expf(xv - m2);
            }
            s += __shfl_xor_sync(0xffffffffu, s, 1);
            if (half == 0)
                stats[((size_t)z * 16 + blockIdx.x) * SEQ + m0 + row] = make_float2(m2, s);
        }
        return;
    }
#pragma unroll
    for (int mt = 0; mt < 2; mt++) {
        int r0 = m0 + warp_m * 32 + mt * 16 + g;
#pragma unroll
        for (int nt = 0; nt < NT; nt++) {
            int col = n0 + warp_n * NT * 8 + nt * 8 + q * 2;
            float c0 = acc[mt][nt][0], c1 = acc[mt][nt][1];
            float c2 = acc[mt][nt][2], c3 = acc[mt][nt][3];
            if (EPI == 0) {
                float b0v = bias[col], b1v = bias[col + 1];
                float2 v0, v1;
                v0.x = c0 + b0v; v0.y = c1 + b1v;
                v1.x = c2 + b0v; v1.y = c3 + b1v;
                *(float2*)(Cf + co + (size_t)r0 * ldc + col)       = v0;
                *(float2*)(Cf + co + (size_t)(r0 + 8) * ldc + col) = v1;
            } else {
                float b0v, b1v;
                if (EPI == 5) {
                    int seg = col >> 10, cc = col & 1023;
                    const float* bp = (seg == 0) ? bias : ((seg == 1) ? bias2 : bias3);
                    float sc = (seg == 0) ? 0.125f : 1.0f;
                    b0v = bp[cc] * sc; b1v = bp[cc + 1] * sc;
                } else {
                    b0v = bias[col]; b1v = bias[col + 1];
                }
                c0 += b0v; c1 += b1v; c2 += b0v; c3 += b1v;
                if (EPI == 2) {
                    c0 = fmaxf(c0, 0.f); c1 = fmaxf(c1, 0.f);
                    c2 = fmaxf(c2, 0.f); c3 = fmaxf(c3, 0.f);
                }
                size_t o0 = co + (size_t)r0 * ldc + col;
                size_t o1 = co + (size_t)(r0 + 8) * ldc + col;
                split_h(c0, c1, Chi + o0, Clo ? Clo + o0 : nullptr);
                split_h(c2, c3, Chi + o1, Clo ? Clo + o1 : nullptr);
            }
        }
    }
}

// ---------------- merge per-tile stats -> per-row (M, 1/S) ----------------
__global__ void __launch_bounds__(256) merge_stats(const float2* __restrict__ stats,
                                                   float2* __restrict__ MS)
{
    int idx = blockIdx.x * 256 + threadIdx.x;
    int z = idx >> 11, r = idx & 2047;
    float2 t[16];
    float M = -3.4e38f;
#pragma unroll
    for (int jt = 0; jt < 16; jt++) {
        t[jt] = stats[((size_t)z * 16 + jt) * SEQ + r];
        M = fmaxf(M, t[jt].x);
    }
    float S = 0.f;
#pragma unroll
    for (int jt = 0; jt < 16; jt++) S += t[jt].y * __expf(t[jt].x - M);
    MS[(size_t)z * SEQ + r] = make_float2(M, 1.0f / S);
}

// ================= ctx: normalize raw scores in place + 2-term GEMM with Vt =================
// A hi-only (2 stages), B hi/lo (3 stages); single sync per iteration.
__global__ void __launch_bounds__(256) ctx_mm(
    float* __restrict__ attn, const float2* __restrict__ MS,
    const __half* __restrict__ Bh, const __half* __restrict__ Bl,
    __half* __restrict__ Chi)
{
    constexpr int NT = 4;
    constexpr int ABYTES = 128 * 80;           // hi only
    constexpr int BBYTES = 64 * 80;
    constexpr int BSTG = 2 * BBYTES;           // 10240 per B stage
    // layout: A stages [0,2) then B stages [2*ABYTES, +3*BSTG)
    extern __shared__ __align__(128) char smem[];
    const unsigned sb = s2u(smem);
    const unsigned sbB = sb + 2 * ABYTES;
    const int tid = threadIdx.x;
    const int m0 = blockIdx.y * 128, z = blockIdx.z;
    float* ab = attn + (size_t)z * SEQ * SEQ;
    const size_t bo = (size_t)z * DK * SEQ;
    const size_t co = (size_t)(z >> 4) * SEQ * D_MODEL + (size_t)(z & 15) * DK;

    const int lane = tid & 31, w = tid >> 5;
    const int warp_m = w & 3, warp_n = w >> 2;

    float acc[2][NT][4];
#pragma unroll
    for (int mt = 0; mt < 2; mt++)
#pragma unroll
        for (int nt = 0; nt < NT; nt++)
#pragma unroll
            for (int e = 0; e < 4; e++) acc[mt][nt][e] = 0.f;

    const int arow = tid >> 3, ac4 = tid & 7;
    float2 ms[4];
#pragma unroll
    for (int i = 0; i < 4; i++) ms[i] = MS[(size_t)z * SEQ + m0 + arow + i * 32];

    float4 ra[4];
    auto loadA = [&](int c){
#pragma unroll
        for (int i = 0; i < 4; i++)
            ra[i] = *(const float4*)(ab + (size_t)(m0 + arow + i * 32) * SEQ + c * 32 + ac4 * 4);
    };
    auto storeA = [&](int c, int buf){
        char* bp = smem + buf * ABYTES;
#pragma unroll
        for (int i = 0; i < 4; i++) {
            float4 p;
            p.x = __expf(ra[i].x - ms[i].x) * ms[i].y;
            p.y = __expf(ra[i].y - ms[i].x) * ms[i].y;
            p.z = __expf(ra[i].z - ms[i].x) * ms[i].y;
            p.w = __expf(ra[i].w - ms[i].x) * ms[i].y;
            *(float4*)(ab + (size_t)(m0 + arow + i * 32) * SEQ + c * 32 + ac4 * 4) = p;
            __half2 h0 = __halves2half2(__float2half_rn(p.x), __float2half_rn(p.y));
            __half2 h1 = __halves2half2(__float2half_rn(p.z), __float2half_rn(p.w));
            uint2 uh;
            uh.x = *(unsigned*)&h0; uh.y = *(unsigned*)&h1;
            *(uint2*)(bp + (arow + i * 32) * 80 + ac4 * 8) = uh;
        }
    };
    auto loadB = [&](int c, int buf){
        unsigned sbuf = sbB + buf * BSTG;
        int row = tid >> 2, ch = tid & 3;
        unsigned so = row * 80 + ch * 16;
        cpa(sbuf + so,          Bh + bo + (size_t)row * SEQ + c * 32 + ch * 8);
        cpa(sbuf + BBYTES + so, Bl + bo + (size_t)row * SEQ + c * 32 + ch * 8);
    };

    loadA(0);
    loadB(0, 0);
    asm volatile("cp.async.commit_group;");
    loadB(1, 1);
    asm volatile("cp.async.commit_group;");

    const int nchunk = SEQ / 32;
    for (int c = 0; c < nchunk; c++) {
        storeA(c, c & 1);
        if (c + 1 < nchunk) loadA(c + 1);
        if (c + 1 < nchunk) asm volatile("cp.async.wait_group 1;");
        else                asm volatile("cp.async.wait_group 0;");
        __syncthreads();
        if (c + 2 < nchunk) {
            loadB(c + 2, (c + 2) % 3);
            asm volatile("cp.async.commit_group;");
        }

        unsigned sa  = sb + (c & 1) * ABYTES
                     + (warp_m * 32 + (lane & 15)) * 80 + (lane >> 4) * 16;
        unsigned sbb = sbB + (c % 3) * BSTG
                     + (warp_n * 32 + (lane & 7) + ((lane >> 4) << 3)) * 80
                     + ((lane >> 3) & 1) * 16;
#pragma unroll
        for (int ks = 0; ks < 2; ks++) {
            unsigned ah[2][4];
            ldmx4(ah[0], sa + ks * 32);
            ldmx4(ah[1], sa + 16 * 80 + ks * 32);
#pragma unroll
            for (int p = 0; p < NT / 2; p++) {
                unsigned bh[4], bl[4];
                ldmx4(bh, sbb + p * 16 * 80 + ks * 32);
                ldmx4(bl, sbb + BBYTES + p * 16 * 80 + ks * 32);
#pragma unroll
                for (int mt = 0; mt < 2; mt++)
#pragma unroll
                    for (int t = 0; t < 2; t++) {
                        float* cc = acc[mt][2 * p + t];
                        mma16816(cc, ah[mt], bh[2 * t], bh[2 * t + 1]);
                        mma16816(cc, ah[mt], bl[2 * t], bl[2 * t + 1]);
                    }
            }
        }
    }

    const int g = lane >> 2, q = lane & 3;
#pragma unroll
    for (int mt = 0; mt < 2; mt++) {
        int r0 = m0 + warp_m * 32 + mt * 16 + g;
#pragma unroll
        for (int nt = 0; nt < NT; nt++) {
            int col = warp_n * 32 + nt * 8 + q * 2;
            size_t o0 = co + (size_t)r0 * D_MODEL + col;
            size_t o1 = co + (size_t)(r0 + 8) * D_MODEL + col;
            split_h(acc[mt][nt][0], acc[mt][nt][1], Chi + o0, nullptr);
            split_h(acc[mt][nt][2], acc[mt][nt][3], Chi + o1, nullptr);
        }
    }
}

// ---------------- fp32 -> fp16 hi/lo ----------------
__global__ void __launch_bounds__(256) split_conv(const float* __restrict__ in,
                                                  __half* __restrict__ oh,
                                                  __half* __restrict__ ol, int n4)
{
    int i = blockIdx.x * 256 + threadIdx.x;
    if (i >= n4) return;
    float4 v = ((const float4*)in)[i];
    __half h0 = __float2half_rn(v.x), h1 = __float2half_rn(v.y);
    __half h2 = __float2half_rn(v.z), h3 = __float2half_rn(v.w);
    ((__half2*)oh)[i * 2]     = __halves2half2(h0, h1);
    ((__half2*)oh)[i * 2 + 1] = __halves2half2(h2, h3);
    ((__half2*)ol)[i * 2]     = __halves2half2(__float2half_rn(v.x - __half2float(h0)),
                                               __float2half_rn(v.y - __half2float(h1)));
    ((__half2*)ol)[i * 2 + 1] = __halves2half2(__float2half_rn(v.z - __half2float(h2)),
                                               __float2half_rn(v.w - __half2float(h3)));
}

// ---------------- transpose fp32 [R][C] -> fp16 hi/lo [C][R], with scale ----------------
__global__ void transp_split(const float* __restrict__ in, int ild,
                             __half* __restrict__ oh, __half* __restrict__ ol,
                             int old_, float scale)
{
    __shared__ float t[32][33];
    int r0 = blockIdx.y * 32, c0 = blockIdx.x * 32;
    int tx = threadIdx.x, ty = threadIdx.y;
#pragma unroll
    for (int i = 0; i < 32; i += 8) t[ty + i][tx] = in[(size_t)(r0 + ty + i) * ild + c0 + tx] * scale;
    __syncthreads();
#pragma unroll
    for (int i = 0; i < 32; i += 8) {
        float v = t[tx][ty + i];
        __half hh = __float2half_rn(v);
        size_t o = (size_t)(c0 + ty + i) * old_ + r0 + tx;
        oh[o] = hh;
        ol[o] = __float2half_rn(v - __half2float(hh));
    }
}

// ---------------- fused QKV weight transpose ----------------
__global__ void transp_w3(const float* __restrict__ Wq, const float* __restrict__ Wk,
                          const float* __restrict__ Wv,
                          __half* __restrict__ oh, __half* __restrict__ ol)
{
    __shared__ float t[32][33];
    int z = blockIdx.z;
    const float* in = (z == 0) ? Wq : (z == 1) ? Wk : Wv;
    float scale = (z == 0) ? 0.125f : 1.0f;
    size_t ob = (size_t)z * D_MODEL * D_MODEL;
    int r0 = blockIdx.y * 32, c0 = blockIdx.x * 32;
    int tx = threadIdx.x, ty = threadIdx.y;
#pragma unroll
    for (int i = 0; i < 32; i += 8) t[ty + i][tx] = in[(size_t)(r0 + ty + i) * D_MODEL + c0 + tx] * scale;
    __syncthreads();
#pragma unroll
    for (int i = 0; i < 32; i += 8) {
        float v = t[tx][ty + i];
        __half hh = __float2half_rn(v);
        size_t o = ob + (size_t)(c0 + ty + i) * D_MODEL + r0 + tx;
        oh[o] = hh;
        ol[o] = __float2half_rn(v - __half2float(hh));
    }
}

// ---------------- per-head V transpose from split-fp16 QKV ----------------
__global__ void transp_v(const __half* __restrict__ ih, const __half* __restrict__ il,
                         __half* __restrict__ oh, __half* __restrict__ ol)
{
    __shared__ __half th[32][33], tl[32][33];
    int z = blockIdx.z, b = z >> 4, h = z & 15;
    const size_t ib = (size_t)b * SEQ * QKV3 + 2048 + (size_t)h * DK;
    const size_t ob = (size_t)z * DK * SEQ;
    int r0 = blockIdx.y * 32, c0 = blockIdx.x * 32;
    int tx = threadIdx.x, ty = threadIdx.y;
#pragma unroll
    for (int i = 0; i < 32; i += 8) {
        size_t o = ib + (size_t)(r0 + ty + i) * QKV3 + c0 + tx;
        th[ty + i][tx] = ih[o];
        tl[ty + i][tx] = il[o];
    }
    __syncthreads();
#pragma unroll
    for (int i = 0; i < 32; i += 8) {
        size_t o = ob + (size_t)(c0 + ty + i) * SEQ + r0 + tx;
        oh[o] = th[tx][ty + i];
        ol[o] = tl[tx][ty + i];
    }
}

// ---------------- out = LayerNorm(X + Y), optional fp16 hi output ----------------
template<int SPLIT>
__global__ void __launch_bounds__(256) add_ln_kernel(const float* __restrict__ X,
                                                     const float* __restrict__ Y,
                                                     const float* __restrict__ gamma,
                                                     const float* __restrict__ beta,
                                                     float* __restrict__ out,
                                                     __half* __restrict__ oh)
{
    const int row = blockIdx.x;
    const int tid = threadIdx.x;
    const int lane = tid & 31, wid = tid >> 5;
    __shared__ float red[8];

    const float* xr = X + (size_t)row * D_MODEL;
    const float* yr = Y + (size_t)row * D_MODEL;
    float4 xv = *(const float4*)(xr + tid * 4);
    float4 yv = *(const float4*)(yr + tid * 4);
    float v0 = xv.x + yv.x, v1 = xv.y + yv.y, v2 = xv.z + yv.z, v3 = xv.w + yv.w;

    float s = v0 + v1 + v2 + v3;
#pragma unroll
    for (int o = 16; o > 0; o >>= 1) s += __shfl_xor_sync(0xffffffffu, s, o);
    if (lane == 0) red[wid] = s;
    __syncthreads();
    float tot = 0.f;
#pragma unroll
    for (int w = 0; w < 8; w++) tot += red[w];
    float mu = tot * (1.0f / D_MODEL);
    __syncthreads();

    float d0 = v0 - mu, d1 = v1 - mu, d2 = v2 - mu, d3 = v3 - mu;
    float sq = d0 * d0 + d1 * d1 + d2 * d2 + d3 * d3;
#pragma unroll
    for (int o = 16; o > 0; o >>= 1) sq += __shfl_xor_sync(0xffffffffu, sq, o);
    if (lane == 0) red[wid] = sq;
    __syncthreads();
    float vtot = 0.f;
#pragma unroll
    for (int w = 0; w < 8; w++) vtot += red[w];
    float inv = rsqrtf(vtot * (1.0f / D_MODEL) + EPS);

    float4 gv = *(const float4*)(gamma + tid * 4);
    float4 bv = *(const float4*)(beta + tid * 4);
    float o0 = d0 * inv * gv.x + bv.x;
    float o1 = d1 * inv * gv.y + bv.y;
    float o2 = d2 * inv * gv.z + bv.z;
    float o3 = d3 * inv * gv.w + bv.w;
    float4 o4; o4.x = o0; o4.y = o1; o4.z = o2; o4.w = o3;
    *(float4*)(out + (size_t)row * D_MODEL + tid * 4) = o4;
    if (SPLIT) {
        size_t base = (size_t)row * D_MODEL + tid * 4;
        ((__half2*)(oh + base))[0] = __halves2half2(__float2half_rn(o0), __float2half_rn(o1));
        ((__half2*)(oh + base))[1] = __halves2half2(__float2half_rn(o2), __float2half_rn(o3));
    }
}

// ---------------- host ----------------
#define GETP(var, sym) void* var; cudaGetSymbolAddress(&var, sym)
#define HF(p) ((__half*)(p))

extern "C" void kernel_launch(void* const* d_in, const int* in_sizes, int n_in,
                              void* d_out, int out_size)
{
    const float* x   = (const float*)d_in[0];
    const int*   msk = (const int*)  d_in[1];
    const float* Wq  = (const float*)d_in[2];
    const float* bq  = (const float*)d_in[3];
    const float* Wk  = (const float*)d_in[4];
    const float* bk  = (const float*)d_in[5];
    const float* Wv  = (const float*)d_in[6];
    const float* bv  = (const float*)d_in[7];
    const float* Wo  = (const float*)d_in[8];
    const float* bo  = (const float*)d_in[9];
    const float* g1  = (const float*)d_in[10];
    const float* be1 = (const float*)d_in[11];
    const float* W1  = (const float*)d_in[12];
    const float* b1  = (const float*)d_in[13];
    const float* W2  = (const float*)d_in[14];
    const float* b2  = (const float*)d_in[15];
    const float* g2  = (const float*)d_in[16];
    const float* be2 = (const float*)d_in[17];
    float* out = (float*)d_out;

    GETP(pT, g_t);      GETP(pH, g_h);     GETP(pAf, g_attn_f32);
    GETP(pSt, g_stats); GETP(pMS, g_MS);
    GETP(pxh, g_xc_h);  GETP(pxl, g_xc_l);
    GETP(pWh, g_Wqkv_h); GETP(pWl, g_Wqkv_l);
    GETP(pWoh, g_Wot_h); GETP(pWol, g_Wot_l);
    GETP(pW1h, g_W1t_h); GETP(pW1l, g_W1t_l);
    GETP(pW2h, g_W2t_h); GETP(pW2l, g_W2t_l);
    GETP(pQKVh, g_qkv_h); GETP(pQKVl, g_qkv_l);
    GETP(pVth, g_Vt_h); GETP(pVtl, g_Vt_l);
    GETP(pCh, g_ctx_h);
    GETP(pHh, g_hc_h);
    GETP(pFh, g_ff_h);

    const size_t OUT_ELEMS  = (size_t)ROWS * D_MODEL;
    const size_t ATTN_ELEMS = (size_t)HZ * SEQ * SEQ;
    float* attn = ((size_t)out_size >= OUT_ELEMS + ATTN_ELEMS) ? out + OUT_ELEMS : (float*)pAf;

    const int SM3  = 2 * (2 * 128 * 80 + 2 * 128 * 80);       // 81920 (3-term, 2-stage)
    const int SM2  = 3 * (1 * 128 * 80 + 2 * 128 * 80);       // 92160 (2-term, 3-stage)
    const int SMCTX = 2 * (128 * 80) + 3 * (2 * 64 * 80);     // 51200
    cudaFuncSetAttribute(gemm_mm<128,5,0,0,0,3>, cudaFuncAttributeMaxDynamicSharedMemorySize, SM3);
    cudaFuncSetAttribute(gemm_mm<128,3,1,1,0,3>, cudaFuncAttributeMaxDynamicSharedMemorySize, SM3);
    cudaFuncSetAttribute(gemm_mm<128,0,0,0,0,2>, cudaFuncAttributeMaxDynamicSharedMemorySize, SM2);
    cudaFuncSetAttribute(gemm_mm<128,2,0,0,0,2>, cudaFuncAttributeMaxDynamicSharedMemorySize, SM2);
    cudaFuncSetAttribute(ctx_mm,                 cudaFuncAttributeMaxDynamicSharedMemorySize, SMCTX);

    dim3 blk(256);
    dim3 tblk(32, 8);

    // 0: x -> split
    split_conv<<<ROWS * D_MODEL / 4 / 256, blk>>>(x, HF(pxh), HF(pxl), ROWS * D_MODEL / 4);
    // 1: QKV weights fused transpose (Wq pre-scaled by 0.125)
    transp_w3<<<dim3(32, 32, 3), tblk>>>(Wq, Wk, Wv, HF(pWh), HF(pWl));
    // 2: Wo transpose
    transp_split<<<dim3(32, 32), tblk>>>(Wo, D_MODEL, HF(pWoh), HF(pWol), D_MODEL, 1.0f);
    // 3: fused QKV GEMM (3-term)
    gemm_mm<128,5,0,0,0,3><<<dim3(QKV3 / 128, 32, 1), blk, SM3>>>(
        HF(pxh), HF(pxl), D_MODEL, 0, HF(pWh), HF(pWl), D_MODEL, 0,
        nullptr, HF(pQKVh), HF(pQKVl), 0, QKV3, bq, bk, bv, nullptr, nullptr, D_MODEL);
    // 4: scores GEMM + per-tile stats (3-term)
    gemm_mm<128,3,1,1,0,3><<<dim3(16, 16, HZ), blk, SM3>>>(
        HF(pQKVh), HF(pQKVl), QKV3, 0, HF(pQKVh), HF(pQKVl), QKV3, 1024,
        attn, nullptr, nullptr, (long long)SEQ * SEQ, SEQ,
        nullptr, nullptr, nullptr, msk, (float2*)pSt, DK);
    // 5: merge stats
    merge_stats<<<HZ * SEQ / 256, blk>>>((const float2*)pSt, (float2*)pMS);
    // 6: V per-head transpose
    transp_v<<<dim3(2, 64, HZ), tblk>>>(HF(pQKVh), HF(pQKVl), HF(pVth), HF(pVtl));
    // 7: ctx (softmax fused, 2-term, hi-only out)
    ctx_mm<<<dim3(1, 16, HZ), blk, SMCTX>>>(attn, (const float2*)pMS,
                                            HF(pVth), HF(pVtl), HF(pCh));
    // 8: O-proj (2-term, 3-stage), 9: LN1
    gemm_mm<128,0,0,0,0,2><<<dim3(8, 32, 1), blk, SM2>>>(
        HF(pCh), nullptr, D_MODEL, 0, HF(pWoh), HF(pWol), D_MODEL, 0,
        (float*)pT, nullptr, nullptr, 0, D_MODEL, bo, nullptr, nullptr, nullptr, nullptr, D_MODEL);
    add_ln_kernel<1><<<ROWS, blk>>>(x, (const float*)pT, g1, be1, (float*)pH, HF(pHh));
    // 10-11: FFN weights
    transp_split<<<dim3(128, 32), tblk>>>(W1, DFF,     HF(pW1h), HF(pW1l), D_MODEL, 1.0f);
    transp_split<<<dim3(32, 128), tblk>>>(W2, D_MODEL, HF(pW2h), HF(pW2l), DFF, 1.0f);
    // 12: FF1 (2-term, 3-stage), 13: FF2 (2-term, 3-stage), 14: LN2
    gemm_mm<128,2,0,0,0,2><<<dim3(32, 32, 1), blk, SM2>>>(
        HF(pHh), nullptr, D_MODEL, 0, HF(pW1h), HF(pW1l), D_MODEL, 0,
        nullptr, HF(pFh), nullptr, 0, DFF, b1, nullptr, nullptr, nullptr, nullptr, D_MODEL);
    gemm_mm<128,0,0,0,0,2><<<dim3(8, 32, 1), blk, SM2>>>(
        HF(pFh), nullptr, DFF, 0, HF(pW2h), HF(pW2l), DFF, 0,
        (float*)pT, nullptr, nullptr, 0, D_MODEL, b2, nullptr, nullptr, nullptr, nullptr, DFF);
    add_ln_kernel<0><<<ROWS, blk>>>((const float*)pH, (const float*)pT, g2, be2, out, nullptr);
}

// round 9
// speedup vs baseline: 3.1252x; 1.0692x over previous
#include <cuda_runtime.h>
#include <cuda_fp16.h>
#include <math.h>

#define D_MODEL 1024
#define NHEAD   16
#define DK      64
#define DFF     4096
#define SEQ     2048
#define BATCH   2
#define ROWS    (BATCH*SEQ)
#define EPS     1e-5f
#define HZ      (BATCH*NHEAD)
#define QKV3    3072

// ---------------- scratch (no allocation allowed) ----------------
__device__ __align__(256) float g_t [(size_t)ROWS*D_MODEL];
__device__ __align__(256) float g_h [(size_t)ROWS*D_MODEL];
__device__ __align__(256) float g_attn_f32[(size_t)HZ*SEQ*SEQ];  // fallback only
__device__ __align__(256) float2 g_stats[(size_t)HZ*16*SEQ];
__device__ __align__(256) float2 g_MS[(size_t)HZ*SEQ];
__device__ __align__(256) __half g_xc_h [(size_t)ROWS*D_MODEL];
__device__ __align__(256) __half g_Wqkv_h[(size_t)QKV3*D_MODEL], g_Wqkv_l[(size_t)QKV3*D_MODEL];
__device__ __align__(256) __half g_Wot_h[(size_t)D_MODEL*D_MODEL], g_Wot_l[(size_t)D_MODEL*D_MODEL];
__device__ __align__(256) __half g_W1t_h[(size_t)D_MODEL*DFF],     g_W1t_l[(size_t)D_MODEL*DFF];
__device__ __align__(256) __half g_W2t_h[(size_t)D_MODEL*DFF],     g_W2t_l[(size_t)D_MODEL*DFF];
__device__ __align__(256) __half g_qkv_h[(size_t)ROWS*QKV3], g_qkv_l[(size_t)ROWS*QKV3];
__device__ __align__(256) __half g_Vt_h [(size_t)HZ*DK*SEQ],  g_Vt_l [(size_t)HZ*DK*SEQ];
__device__ __align__(256) __half g_ctx_h[(size_t)ROWS*D_MODEL];
__device__ __align__(256) __half g_hc_h [(size_t)ROWS*D_MODEL];
__device__ __align__(256) __half g_ff_h [(size_t)ROWS*DFF];

// ---------------- helpers ----------------
__device__ __forceinline__ unsigned s2u(const void* p){
    unsigned a;
    asm("{ .reg .u64 t; cvta.to.shared.u64 t, %1; cvt.u32.u64 %0, t; }" : "=r"(a) : "l"(p));
    return a;
}
__device__ __forceinline__ void cpa(unsigned s, const void* g){
    asm volatile("cp.async.cg.shared.global [%0], [%1], 16;" :: "r"(s), "l"(g));
}
__device__ __forceinline__ void ldmx4(unsigned* r, unsigned addr){
    asm volatile("ldmatrix.sync.aligned.m8n8.x4.shared.b16 {%0,%1,%2,%3}, [%4];"
        : "=r"(r[0]), "=r"(r[1]), "=r"(r[2]), "=r"(r[3]) : "r"(addr));
}
__device__ __forceinline__ void mma16816(float* c, const unsigned* a, unsigned b0, unsigned b1){
    asm volatile("mma.sync.aligned.m16n8k16.row.col.f32.f16.f16.f32 "
        "{%0,%1,%2,%3}, {%4,%5,%6,%7}, {%8,%9}, {%0,%1,%2,%3};"
        : "+f"(c[0]), "+f"(c[1]), "+f"(c[2]), "+f"(c[3])
        : "r"(a[0]), "r"(a[1]), "r"(a[2]), "r"(a[3]), "r"(b0), "r"(b1));
}
__device__ __forceinline__ void split_h(float v0, float v1, __half* hi, __half* lo){
    __half h0 = __float2half_rn(v0), h1 = __float2half_rn(v1);
    *(__half2*)hi = __halves2half2(h0, h1);
    if (lo)
        *(__half2*)lo = __halves2half2(__float2half_rn(v0 - __half2float(h0)),
                                       __float2half_rn(v1 - __half2float(h1)));
}

// ================= 2-term split-fp16 HMMA GEMM (A hi, B hi/lo; 3-stage, 1 sync/iter) =================
// EPI: 0 fp32+bias | 2 f16+bias+relu (hi only) | 3 fp32+mask+row-stats | 5 f16split 3-seg bias (QKV)
template<int BN, int EPI, int AOFF, int BOFF, int COFF>
__global__ void __launch_bounds__(256) gemm_mm(
    const __half* __restrict__ Ah, int lda, long long sAz,
    const __half* __restrict__ Bh, const __half* __restrict__ Bl, int ldb, long long sBz,
    float* __restrict__ Cf, __half* __restrict__ Chi, __half* __restrict__ Clo,
    long long sCz, int ldc,
    const float* __restrict__ bias, const float* __restrict__ bias2, const float* __restrict__ bias3,
    const int* __restrict__ mask, float2* __restrict__ stats, int K)
{
    constexpr int NT = BN / 16;
    constexpr int ABYTES = 128 * 80;
    constexpr int BBYTES = BN * 80;
    constexpr int BUFB = ABYTES + 2 * BBYTES;
    extern __shared__ __align__(128) char smem[];
    const unsigned sb = s2u(smem);
    const int tid = threadIdx.x;
    const int m0 = blockIdx.y * 128, n0 = blockIdx.x * BN, z = blockIdx.z;

    size_t ao = (AOFF == 1) ? ((size_t)(z >> 4) * SEQ * lda + (size_t)(z & 15) * DK + (size_t)sAz)
                            : (size_t)z * sAz;
    size_t bo = (BOFF == 1) ? ((size_t)(z >> 4) * SEQ * ldb + (size_t)(z & 15) * DK + (size_t)sBz)
                            : (size_t)z * sBz;
    size_t co = (COFF == 1) ? ((size_t)(z >> 4) * SEQ * ldc + (size_t)(z & 15) * DK)
                            : (size_t)z * sCz;

    const int lane = tid & 31, w = tid >> 5;
    const int warp_m = w & 3, warp_n = w >> 2;

    float acc[2][NT][4];
#pragma unroll
    for (int mt = 0; mt < 2; mt++)
#pragma unroll
        for (int nt = 0; nt < NT; nt++)
#pragma unroll
            for (int e = 0; e < 4; e++) acc[mt][nt][e] = 0.f;

    const int nchunk = K >> 5;

    auto load_tile = [&](int c, int buf) {
        unsigned sbuf = sb + buf * BUFB;
        const __half* pah = Ah + ao + (size_t)m0 * lda + c * 32;
#pragma unroll
        for (int i = 0; i < 2; i++) {
            int idx = tid + i * 256;
            int row = idx >> 2, ch = idx & 3;
            cpa(sbuf + row * 80 + ch * 16, pah + (size_t)row * lda + ch * 8);
        }
        const __half* pbh = Bh + bo + (size_t)n0 * ldb + c * 32;
        const __half* pbl = Bl + bo + (size_t)n0 * ldb + c * 32;
#pragma unroll
        for (int i = 0; i < BN / 64; i++) {
            int idx = tid + i * 256;
            int row = idx >> 2, ch = idx & 3;
            unsigned so = row * 80 + ch * 16;
            cpa(sbuf + ABYTES + so,          pbh + (size_t)row * ldb + ch * 8);
            cpa(sbuf + ABYTES + BBYTES + so, pbl + (size_t)row * ldb + ch * 8);
        }
    };

    auto compute = [&](unsigned sbuf) {
        unsigned sa  = sbuf + (warp_m * 32 + (lane & 15)) * 80 + (lane >> 4) * 16;
        unsigned sbb = sbuf + ABYTES
                     + (warp_n * (NT * 8) + (lane & 7) + ((lane >> 4) << 3)) * 80
                     + ((lane >> 3) & 1) * 16;
#pragma unroll
        for (int ks = 0; ks < 2; ks++) {
            unsigned ah[2][4];
            ldmx4(ah[0], sa + ks * 32);
            ldmx4(ah[1], sa + 16 * 80 + ks * 32);
#pragma unroll
            for (int p = 0; p < NT / 2; p++) {
                unsigned bh[4], bl[4];
                ldmx4(bh, sbb + p * 16 * 80 + ks * 32);
                ldmx4(bl, sbb + BBYTES + p * 16 * 80 + ks * 32);
#pragma unroll
                for (int mt = 0; mt < 2; mt++)
#pragma unroll
                    for (int t = 0; t < 2; t++) {
                        float* cc = acc[mt][2 * p + t];
                        mma16816(cc, ah[mt], bh[2 * t], bh[2 * t + 1]);
                        mma16816(cc, ah[mt], bl[2 * t], bl[2 * t + 1]);
                    }
            }
        }
    };

    load_tile(0, 0);
    asm volatile("cp.async.commit_group;");
    if (nchunk > 1) { load_tile(1, 1); asm volatile("cp.async.commit_group;"); }
    for (int c = 0; c < nchunk; c++) {
        if (c + 1 < nchunk) asm volatile("cp.async.wait_group 1;");
        else                asm volatile("cp.async.wait_group 0;");
        __syncthreads();
        if (c + 2 < nchunk) {
            load_tile(c + 2, (c + 2) % 3);
            asm volatile("cp.async.commit_group;");
        }
        compute(sb + (c % 3) * BUFB);
    }

    // -------- epilogue --------
    const int g = lane >> 2, q = lane & 3;
    if (EPI == 3) {
        __syncthreads();
        float* stg = (float*)smem;
#pragma unroll
        for (int mt = 0; mt < 2; mt++) {
            int sr = warp_m * 32 + mt * 16 + g;
#pragma unroll
            for (int nt = 0; nt < NT; nt++) {
                int sc = warp_n * (NT * 8) + nt * 8 + q * 2;
                stg[sr * 132 + sc]           = acc[mt][nt][0];
                stg[sr * 132 + sc + 1]       = acc[mt][nt][1];
                stg[(sr + 8) * 132 + sc]     = acc[mt][nt][2];
                stg[(sr + 8) * 132 + sc + 1] = acc[mt][nt][3];
            }
        }
        __syncthreads();
        const int* mrow = mask + (size_t)(z >> 4) * SEQ;
#pragma unroll
        for (int i = 0; i < 16; i++) {
            int idx = tid + i * 256, row = idx >> 5, c4 = (idx & 31) * 4;
            float4 v;
            v.x = stg[row * 132 + c4];
            v.y = stg[row * 132 + c4 + 1];
            v.z = stg[row * 132 + c4 + 2];
            v.w = stg[row * 132 + c4 + 3];
            int4 mk = *(const int4*)(mrow + n0 + c4);
            v.x = mk.x ? v.x : -1e9f;
            v.y = mk.y ? v.y : -1e9f;
            v.z = mk.z ? v.z : -1e9f;
            v.w = mk.w ? v.w : -1e9f;
            *(float4*)(Cf + co + (size_t)(m0 + row) * ldc + n0 + c4) = v;
        }
        {
            int row = tid >> 1, half = tid & 1;
            float m = -3.4e38f;
#pragma unroll 8
            for (int c2 = 0; c2 < 64; c2++) {
                float xv = stg[row * 132 + half * 64 + c2];
                if (mrow[n0 + half * 64 + c2] == 0) xv = -1e9f;
                m = fmaxf(m, xv);
            }
            float m2 = fmaxf(m, __shfl_xor_sync(0xffffffffu, m, 1));
            float s = 0.f;
#pragma unroll 8
            for (int c2 = 0; c2 < 64; c2++) {
                float xv = stg[row * 132 + half * 64 + c2];
                if (mrow[n0 + half * 64 + c2] == 0) xv = -1e9f;
                s += __expf(xv - m2);
            }
            s += __shfl_xor_sync(0xffffffffu, s, 1);
            if (half == 0)
                stats[((size_t)z * 16 + blockIdx.x) * SEQ + m0 + row] = make_float2(m2, s);
        }
        return;
    }
#pragma unroll
    for (int mt = 0; mt < 2; mt++) {
        int r0 = m0 + warp_m * 32 + mt * 16 + g;
#pragma unroll
        for (int nt = 0; nt < NT; nt++) {
            int col = n0 + warp_n * NT * 8 + nt * 8 + q * 2;
            float c0 = acc[mt][nt][0], c1 = acc[mt][nt][1];
            float c2 = acc[mt][nt][2], c3 = acc[mt][nt][3];
            if (EPI == 0) {
                float b0v = bias[col], b1v = bias[col + 1];
                float2 v0, v1;
                v0.x = c0 + b0v; v0.y = c1 + b1v;
                v1.x = c2 + b0v; v1.y = c3 + b1v;
                *(float2*)(Cf + co + (size_t)r0 * ldc + col)       = v0;
                *(float2*)(Cf + co + (size_t)(r0 + 8) * ldc + col) = v1;
            } else {
                float b0v, b1v;
                if (EPI == 5) {
                    int seg = col >> 10, cc = col & 1023;
                    const float* bp = (seg == 0) ? bias : ((seg == 1) ? bias2 : bias3);
                    float sc = (seg == 0) ? 0.125f : 1.0f;
                    b0v = bp[cc] * sc; b1v = bp[cc + 1] * sc;
                } else {
                    b0v = bias[col]; b1v = bias[col + 1];
                }
                c0 += b0v; c1 += b1v; c2 += b0v; c3 += b1v;
                if (EPI == 2) {
                    c0 = fmaxf(c0, 0.f); c1 = fmaxf(c1, 0.f);
                    c2 = fmaxf(c2, 0.f); c3 = fmaxf(c3, 0.f);
                }
                size_t o0 = co + (size_t)r0 * ldc + col;
                size_t o1 = co + (size_t)(r0 + 8) * ldc + col;
                split_h(c0, c1, Chi + o0, Clo ? Clo + o0 : nullptr);
                split_h(c2, c3, Chi + o1, Clo ? Clo + o1 : nullptr);
            }
        }
    }
}

// ---------------- merge per-tile stats -> per-row (M, 1/S) ----------------
__global__ void __launch_bounds__(256) merge_stats(const float2* __restrict__ stats,
                                                   float2* __restrict__ MS)
{
    int idx = blockIdx.x * 256 + threadIdx.x;
    int z = idx >> 11, r = idx & 2047;
    float2 t[16];
    float M = -3.4e38f;
#pragma unroll
    for (int jt = 0; jt < 16; jt++) {
        t[jt] = stats[((size_t)z * 16 + jt) * SEQ + r];
        M = fmaxf(M, t[jt].x);
    }
    float S = 0.f;
#pragma unroll
    for (int jt = 0; jt < 16; jt++) S += t[jt].y * __expf(t[jt].x - M);
    MS[(size_t)z * SEQ + r] = make_float2(M, 1.0f / S);
}

// ================= ctx: normalize raw scores in place + 2-term GEMM with Vt =================
__global__ void __launch_bounds__(256) ctx_mm(
    float* __restrict__ attn, const float2* __restrict__ MS,
    const __half* __restrict__ Bh, const __half* __restrict__ Bl,
    __half* __restrict__ Chi)
{
    constexpr int NT = 4;
    constexpr int ABYTES = 128 * 80;
    constexpr int BBYTES = 64 * 80;
    constexpr int BSTG = 2 * BBYTES;
    extern __shared__ __align__(128) char smem[];
    const unsigned sb = s2u(smem);
    const unsigned sbB = sb + 2 * ABYTES;
    const int tid = threadIdx.x;
    const int m0 = blockIdx.y * 128, z = blockIdx.z;
    float* ab = attn + (size_t)z * SEQ * SEQ;
    const size_t bo = (size_t)z * DK * SEQ;
    const size_t co = (size_t)(z >> 4) * SEQ * D_MODEL + (size_t)(z & 15) * DK;

    const int lane = tid & 31, w = tid >> 5;
    const int warp_m = w & 3, warp_n = w >> 2;

    float acc[2][NT][4];
#pragma unroll
    for (int mt = 0; mt < 2; mt++)
#pragma unroll
        for (int nt = 0; nt < NT; nt++)
#pragma unroll
            for (int e = 0; e < 4; e++) acc[mt][nt][e] = 0.f;

    const int arow = tid >> 3, ac4 = tid & 7;
    float2 ms[4];
#pragma unroll
    for (int i = 0; i < 4; i++) ms[i] = MS[(size_t)z * SEQ + m0 + arow + i * 32];

    float4 ra[4];
    auto loadA = [&](int c){
#pragma unroll
        for (int i = 0; i < 4; i++)
            ra[i] = *(const float4*)(ab + (size_t)(m0 + arow + i * 32) * SEQ + c * 32 + ac4 * 4);
    };
    auto storeA = [&](int c, int buf){
        char* bp = smem + buf * ABYTES;
#pragma unroll
        for (int i = 0; i < 4; i++) {
            float4 p;
            p.x = __expf(ra[i].x - ms[i].x) * ms[i].y;
            p.y = __expf(ra[i].y - ms[i].x) * ms[i].y;
            p.z = __expf(ra[i].z - ms[i].x) * ms[i].y;
            p.w = __expf(ra[i].w - ms[i].x) * ms[i].y;
            *(float4*)(ab + (size_t)(m0 + arow + i * 32) * SEQ + c * 32 + ac4 * 4) = p;
            __half2 h0 = __halves2half2(__float2half_rn(p.x), __float2half_rn(p.y));
            __half2 h1 = __halves2half2(__float2half_rn(p.z), __float2half_rn(p.w));
            uint2 uh;
            uh.x = *(unsigned*)&h0; uh.y = *(unsigned*)&h1;
            *(uint2*)(bp + (arow + i * 32) * 80 + ac4 * 8) = uh;
        }
    };
    auto loadB = [&](int c, int buf){
        unsigned sbuf = sbB + buf * BSTG;
        int row = tid >> 2, ch = tid & 3;
        unsigned so = row * 80 + ch * 16;
        cpa(sbuf + so,          Bh + bo + (size_t)row * SEQ + c * 32 + ch * 8);
        cpa(sbuf + BBYTES + so, Bl + bo + (size_t)row * SEQ + c * 32 + ch * 8);
    };

    loadA(0);
    loadB(0, 0);
    asm volatile("cp.async.commit_group;");
    loadB(1, 1);
    asm volatile("cp.async.commit_group;");

    const int nchunk = SEQ / 32;
    for (int c = 0; c < nchunk; c++) {
        storeA(c, c & 1);
        if (c + 1 < nchunk) loadA(c + 1);
        if (c + 1 < nchunk) asm volatile("cp.async.wait_group 1;");
        else                asm volatile("cp.async.wait_group 0;");
        __syncthreads();
        if (c + 2 < nchunk) {
            loadB(c + 2, (c + 2) % 3);
            asm volatile("cp.async.commit_group;");
        }

        unsigned sa  = sb + (c & 1) * ABYTES
                     + (warp_m * 32 + (lane & 15)) * 80 + (lane >> 4) * 16;
        unsigned sbb = sbB + (c % 3) * BSTG
                     + (warp_n * 32 + (lane & 7) + ((lane >> 4) << 3)) * 80
                     + ((lane >> 3) & 1) * 16;
#pragma unroll
        for (int ks = 0; ks < 2; ks++) {
            unsigned ah[2][4];
            ldmx4(ah[0], sa + ks * 32);
            ldmx4(ah[1], sa + 16 * 80 + ks * 32);
#pragma unroll
            for (int p = 0; p < NT / 2; p++) {
                unsigned bh[4], bl[4];
                ldmx4(bh, sbb + p * 16 * 80 + ks * 32);
                ldmx4(bl, sbb + BBYTES + p * 16 * 80 + ks * 32);
#pragma unroll
                for (int mt = 0; mt < 2; mt++)
#pragma unroll
                    for (int t = 0; t < 2; t++) {
                        float* cc = acc[mt][2 * p + t];
                        mma16816(cc, ah[mt], bh[2 * t], bh[2 * t + 1]);
                        mma16816(cc, ah[mt], bl[2 * t], bl[2 * t + 1]);
                    }
            }
        }
    }

    const int g = lane >> 2, q = lane & 3;
#pragma unroll
    for (int mt = 0; mt < 2; mt++) {
        int r0 = m0 + warp_m * 32 + mt * 16 + g;
#pragma unroll
        for (int nt = 0; nt < NT; nt++) {
            int col = warp_n * 32 + nt * 8 + q * 2;
            size_t o0 = co + (size_t)r0 * D_MODEL + col;
            size_t o1 = co + (size_t)(r0 + 8) * D_MODEL + col;
            split_h(acc[mt][nt][0], acc[mt][nt][1], Chi + o0, nullptr);
            split_h(acc[mt][nt][2], acc[mt][nt][3], Chi + o1, nullptr);
        }
    }
}

// ---------------- fp32 -> fp16 (hi only) ----------------
__global__ void __launch_bounds__(256) conv_h(const float* __restrict__ in,
                                              __half* __restrict__ oh, int n4)
{
    int i = blockIdx.x * 256 + threadIdx.x;
    if (i >= n4) return;
    float4 v = ((const float4*)in)[i];
    ((__half2*)oh)[i * 2]     = __halves2half2(__float2half_rn(v.x), __float2half_rn(v.y));
    ((__half2*)oh)[i * 2 + 1] = __halves2half2(__float2half_rn(v.z), __float2half_rn(v.w));
}

// ---------------- transpose fp32 [R][C] -> fp16 hi/lo [C][R], with scale ----------------
__global__ void transp_split(const float* __restrict__ in, int ild,
                             __half* __restrict__ oh, __half* __restrict__ ol,
                             int old_, float scale)
{
    __shared__ float t[32][33];
    int r0 = blockIdx.y * 32, c0 = blockIdx.x * 32;
    int tx = threadIdx.x, ty = threadIdx.y;
#pragma unroll
    for (int i = 0; i < 32; i += 8) t[ty + i][tx] = in[(size_t)(r0 + ty + i) * ild + c0 + tx] * scale;
    __syncthreads();
#pragma unroll
    for (int i = 0; i < 32; i += 8) {
        float v = t[tx][ty + i];
        __half hh = __float2half_rn(v);
        size_t o = (size_t)(c0 + ty + i) * old_ + r0 + tx;
        oh[o] = hh;
        ol[o] = __float2half_rn(v - __half2float(hh));
    }
}

// ---------------- fused QKV weight transpose ----------------
__global__ void transp_w3(const float* __restrict__ Wq, const float* __restrict__ Wk,
                          const float* __restrict__ Wv,
                          __half* __restrict__ oh, __half* __restrict__ ol)
{
    __shared__ float t[32][33];
    int z = blockIdx.z;
    const float* in = (z == 0) ? Wq : (z == 1) ? Wk : Wv;
    float scale = (z == 0) ? 0.125f : 1.0f;
    size_t ob = (size_t)z * D_MODEL * D_MODEL;
    int r0 = blockIdx.y * 32, c0 = blockIdx.x * 32;
    int tx = threadIdx.x, ty = threadIdx.y;
#pragma unroll
    for (int i = 0; i < 32; i += 8) t[ty + i][tx] = in[(size_t)(r0 + ty + i) * D_MODEL + c0 + tx] * scale;
    __syncthreads();
#pragma unroll
    for (int i = 0; i < 32; i += 8) {
        float v = t[tx][ty + i];
        __half hh = __float2half_rn(v);
        size_t o = ob + (size_t)(c0 + ty + i) * D_MODEL + r0 + tx;
        oh[o] = hh;
        ol[o] = __float2half_rn(v - __half2float(hh));
    }
}

// ---------------- per-head V transpose from split-fp16 QKV ----------------
__global__ void transp_v(const __half* __restrict__ ih, const __half* __restrict__ il,
                         __half* __restrict__ oh, __half* __restrict__ ol)
{
    __shared__ __half th[32][33], tl[32][33];
    int z = blockIdx.z, b = z >> 4, h = z & 15;
    const size_t ib = (size_t)b * SEQ * QKV3 + 2048 + (size_t)h * DK;
    const size_t ob = (size_t)z * DK * SEQ;
    int r0 = blockIdx.y * 32, c0 = blockIdx.x * 32;
    int tx = threadIdx.x, ty = threadIdx.y;
#pragma unroll
    for (int i = 0; i < 32; i += 8) {
        size_t o = ib + (size_t)(r0 + ty + i) * QKV3 + c0 + tx;
        th[ty + i][tx] = ih[o];
        tl[ty + i][tx] = il[o];
    }
    __syncthreads();
#pragma unroll
    for (int i = 0; i < 32; i += 8) {
        size_t o = ob + (size_t)(c0 + ty + i) * SEQ + r0 + tx;
        oh[o] = th[tx][ty + i];
        ol[o] = tl[tx][ty + i];
    }
}

// ---------------- out = LayerNorm(X + Y), optional fp16 hi output ----------------
template<int SPLIT>
__global__ void __launch_bounds__(256) add_ln_kernel(const float* __restrict__ X,
                                                     const float* __restrict__ Y,
                                                     const float* __restrict__ gamma,
                                                     const float* __restrict__ beta,
                                                     float* __restrict__ out,
                                                     __half* __restrict__ oh)
{
    const int row = blockIdx.x;
    const int tid = threadIdx.x;
    const int lane = tid & 31, wid = tid >> 5;
    __shared__ float red[8];

    const float* xr = X + (size_t)row * D_MODEL;
    const float* yr = Y + (size_t)row * D_MODEL;
    float4 xv = *(const float4*)(xr + tid * 4);
    float4 yv = *(const float4*)(yr + tid * 4);
    float v0 = xv.x + yv.x, v1 = xv.y + yv.y, v2 = xv.z + yv.z, v3 = xv.w + yv.w;

    float s = v0 + v1 + v2 + v3;
#pragma unroll
    for (int o = 16; o > 0; o >>= 1) s += __shfl_xor_sync(0xffffffffu, s, o);
    if (lane == 0) red[wid] = s;
    __syncthreads();
    float tot = 0.f;
#pragma unroll
    for (int w = 0; w < 8; w++) tot += red[w];
    float mu = tot * (1.0f / D_MODEL);
    __syncthreads();

    float d0 = v0 - mu, d1 = v1 - mu, d2 = v2 - mu, d3 = v3 - mu;
    float sq = d0 * d0 + d1 * d1 + d2 * d2 + d3 * d3;
#pragma unroll
    for (int o = 16; o > 0; o >>= 1) sq += __shfl_xor_sync(0xffffffffu, sq, o);
    if (lane == 0) red[wid] = sq;
    __syncthreads();
    float vtot = 0.f;
#pragma unroll
    for (int w = 0; w < 8; w++) vtot += red[w];
    float inv = rsqrtf(vtot * (1.0f / D_MODEL) + EPS);

    float4 gv = *(const float4*)(gamma + tid * 4);
    float4 bv = *(const float4*)(beta + tid * 4);
    float o0 = d0 * inv * gv.x + bv.x;
    float o1 = d1 * inv * gv.y + bv.y;
    float o2 = d2 * inv * gv.z + bv.z;
    float o3 = d3 * inv * gv.w + bv.w;
    float4 o4; o4.x = o0; o4.y = o1; o4.z = o2; o4.w = o3;
    *(float4*)(out + (size_t)row * D_MODEL + tid * 4) = o4;
    if (SPLIT) {
        size_t base = (size_t)row * D_MODEL + tid * 4;
        ((__half2*)(oh + base))[0] = __halves2half2(__float2half_rn(o0), __float2half_rn(o1));
        ((__half2*)(oh + base))[1] = __halves2half2(__float2half_rn(o2), __float2half_rn(o3));
    }
}

// ---------------- host ----------------
#define GETP(var, sym) void* var; cudaGetSymbolAddress(&var, sym)
#define HF(p) ((__half*)(p))

extern "C" void kernel_launch(void* const* d_in, const int* in_sizes, int n_in,
                              void* d_out, int out_size)
{
    const float* x   = (const float*)d_in[0];
    const int*   msk = (const int*)  d_in[1];
    const float* Wq  = (const float*)d_in[2];
    const float* bq  = (const float*)d_in[3];
    const float* Wk  = (const float*)d_in[4];
    const float* bk  = (const float*)d_in[5];
    const float* Wv  = (const float*)d_in[6];
    const float* bv  = (const float*)d_in[7];
    const float* Wo  = (const float*)d_in[8];
    const float* bo  = (const float*)d_in[9];
    const float* g1  = (const float*)d_in[10];
    const float* be1 = (const float*)d_in[11];
    const float* W1  = (const float*)d_in[12];
    const float* b1  = (const float*)d_in[13];
    const float* W2  = (const float*)d_in[14];
    const float* b2  = (const float*)d_in[15];
    const float* g2  = (const float*)d_in[16];
    const float* be2 = (const float*)d_in[17];
    float* out = (float*)d_out;

    GETP(pT, g_t);      GETP(pH, g_h);     GETP(pAf, g_attn_f32);
    GETP(pSt, g_stats); GETP(pMS, g_MS);
    GETP(pxh, g_xc_h);
    GETP(pWh, g_Wqkv_h); GETP(pWl, g_Wqkv_l);
    GETP(pWoh, g_Wot_h); GETP(pWol, g_Wot_l);
    GETP(pW1h, g_W1t_h); GETP(pW1l, g_W1t_l);
    GETP(pW2h, g_W2t_h); GETP(pW2l, g_W2t_l);
    GETP(pQKVh, g_qkv_h); GETP(pQKVl, g_qkv_l);
    GETP(pVth, g_Vt_h); GETP(pVtl, g_Vt_l);
    GETP(pCh, g_ctx_h);
    GETP(pHh, g_hc_h);
    GETP(pFh, g_ff_h);

    const size_t OUT_ELEMS  = (size_t)ROWS * D_MODEL;
    const size_t ATTN_ELEMS = (size_t)HZ * SEQ * SEQ;
    float* attn = ((size_t)out_size >= OUT_ELEMS + ATTN_ELEMS) ? out + OUT_ELEMS : (float*)pAf;

    const int SM2  = 3 * (128 * 80 + 2 * 128 * 80);           // 92160
    const int SMCTX = 2 * (128 * 80) + 3 * (2 * 64 * 80);     // 51200
    cudaFuncSetAttribute(gemm_mm<128,5,0,0,0>, cudaFuncAttributeMaxDynamicSharedMemorySize, SM2);
    cudaFuncSetAttribute(gemm_mm<128,3,1,1,0>, cudaFuncAttributeMaxDynamicSharedMemorySize, SM2);
    cudaFuncSetAttribute(gemm_mm<128,0,0,0,0>, cudaFuncAttributeMaxDynamicSharedMemorySize, SM2);
    cudaFuncSetAttribute(gemm_mm<128,2,0,0,0>, cudaFuncAttributeMaxDynamicSharedMemorySize, SM2);
    cudaFuncSetAttribute(ctx_mm,               cudaFuncAttributeMaxDynamicSharedMemorySize, SMCTX);

    dim3 blk(256);
    dim3 tblk(32, 8);

    // 0: x -> fp16 hi
    conv_h<<<ROWS * D_MODEL / 4 / 256, blk>>>(x, HF(pxh), ROWS * D_MODEL / 4);
    // 1: QKV weights fused transpose (Wq pre-scaled by 0.125)
    transp_w3<<<dim3(32, 32, 3), tblk>>>(Wq, Wk, Wv, HF(pWh), HF(pWl));
    // 2: Wo transpose
    transp_split<<<dim3(32, 32), tblk>>>(Wo, D_MODEL, HF(pWoh), HF(pWol), D_MODEL, 1.0f);
    // 3: fused QKV GEMM (2-term)
    gemm_mm<128,5,0,0,0><<<dim3(QKV3 / 128, 32, 1), blk, SM2>>>(
        HF(pxh), D_MODEL, 0, HF(pWh), HF(pWl), D_MODEL, 0,
        nullptr, HF(pQKVh), HF(pQKVl), 0, QKV3, bq, bk, bv, nullptr, nullptr, D_MODEL);
    // 4: scores GEMM + per-tile stats (2-term: Q hi x K hi/lo)
    gemm_mm<128,3,1,1,0><<<dim3(16, 16, HZ), blk, SM2>>>(
        HF(pQKVh), QKV3, 0, HF(pQKVh), HF(pQKVl), QKV3, 1024,
        attn, nullptr, nullptr, (long long)SEQ * SEQ, SEQ,
        nullptr, nullptr, nullptr, msk, (float2*)pSt, DK);
    // 5: merge stats
    merge_stats<<<HZ * SEQ / 256, blk>>>((const float2*)pSt, (float2*)pMS);
    // 6: V per-head transpose
    transp_v<<<dim3(2, 64, HZ), tblk>>>(HF(pQKVh), HF(pQKVl), HF(pVth), HF(pVtl));
    // 7: ctx (softmax fused, 2-term)
    ctx_mm<<<dim3(1, 16, HZ), blk, SMCTX>>>(attn, (const float2*)pMS,
                                            HF(pVth), HF(pVtl), HF(pCh));
    // 8: O-proj (2-term), 9: LN1
    gemm_mm<128,0,0,0,0><<<dim3(8, 32, 1), blk, SM2>>>(
        HF(pCh), D_MODEL, 0, HF(pWoh), HF(pWol), D_MODEL, 0,
        (float*)pT, nullptr, nullptr, 0, D_MODEL, bo, nullptr, nullptr, nullptr, nullptr, D_MODEL);
    add_ln_kernel<1><<<ROWS, blk>>>(x, (const float*)pT, g1, be1, (float*)pH, HF(pHh));
    // 10-11: FFN weights
    transp_split<<<dim3(128, 32), tblk>>>(W1, DFF,     HF(pW1h), HF(pW1l), D_MODEL, 1.0f);
    transp_split<<<dim3(32, 128), tblk>>>(W2, D_MODEL, HF(pW2h), HF(pW2l), DFF, 1.0f);
    // 12: FF1, 13: FF2, 14: LN2
    gemm_mm<128,2,0,0,0><<<dim3(32, 32, 1), blk, SM2>>>(
        HF(pHh), D_MODEL, 0, HF(pW1h), HF(pW1l), D_MODEL, 0,
        nullptr, HF(pFh), nullptr, 0, DFF, b1, nullptr, nullptr, nullptr, nullptr, D_MODEL);
    gemm_mm<128,0,0,0,0><<<dim3(8, 32, 1), blk, SM2>>>(
        HF(pFh), DFF, 0, HF(pW2h), HF(pW2l), DFF, 0,
        (float*)pT, nullptr, nullptr, 0, D_MODEL, b2, nullptr, nullptr, nullptr, nullptr, DFF);
    add_ln_kernel<0><<<ROWS, blk>>>((const float*)pH, (const float*)pT, g2, be2, out, nullptr);
}

// round 10
// speedup vs baseline: 3.1632x; 1.0122x over previous
#include <cuda_runtime.h>
#include <cuda_fp16.h>
#include <math.h>

#define D_MODEL 1024
#define NHEAD   16
#define DK      64
#define DFF     4096
#define SEQ     2048
#define BATCH   2
#define ROWS    (BATCH*SEQ)
#define EPS     1e-5f
#define HZ      (BATCH*NHEAD)
#define QKV3    3072

// ---------------- scratch (no allocation allowed) ----------------
__device__ __align__(256) float g_t [(size_t)ROWS*D_MODEL];
__device__ __align__(256) float g_h [(size_t)ROWS*D_MODEL];
__device__ __align__(256) float g_attn_f32[(size_t)HZ*SEQ*SEQ];  // fallback only
__device__ __align__(256) float2 g_stats[(size_t)HZ*32*SEQ];
__device__ __align__(256) float2 g_MS[(size_t)HZ*SEQ];
__device__ __align__(256) __half g_xc_h [(size_t)ROWS*D_MODEL];
__device__ __align__(256) __half g_Wqkv_h[(size_t)QKV3*D_MODEL], g_Wqkv_l[(size_t)QKV3*D_MODEL];
__device__ __align__(256) __half g_Wot_h[(size_t)D_MODEL*D_MODEL], g_Wot_l[(size_t)D_MODEL*D_MODEL];
__device__ __align__(256) __half g_W1t_h[(size_t)D_MODEL*DFF],     g_W1t_l[(size_t)D_MODEL*DFF];
__device__ __align__(256) __half g_W2t_h[(size_t)D_MODEL*DFF],     g_W2t_l[(size_t)D_MODEL*DFF];
__device__ __align__(256) __half g_qkv_h[(size_t)ROWS*QKV3], g_qkv_l[(size_t)ROWS*QKV3];
__device__ __align__(256) __half g_Vt_h [(size_t)HZ*DK*SEQ],  g_Vt_l [(size_t)HZ*DK*SEQ];
__device__ __align__(256) __half g_ctx_h[(size_t)ROWS*D_MODEL];
__device__ __align__(256) __half g_hc_h [(size_t)ROWS*D_MODEL];
__device__ __align__(256) __half g_ff_h [(size_t)ROWS*DFF];

// ---------------- helpers ----------------
__device__ __forceinline__ unsigned s2u(const void* p){
    unsigned a;
    asm("{ .reg .u64 t; cvta.to.shared.u64 t, %1; cvt.u32.u64 %0, t; }" : "=r"(a) : "l"(p));
    return a;
}
__device__ __forceinline__ void cpa(unsigned s, const void* g){
    asm volatile("cp.async.cg.shared.global [%0], [%1], 16;" :: "r"(s), "l"(g));
}
__device__ __forceinline__ void ldmx4(unsigned* r, unsigned addr){
    asm volatile("ldmatrix.sync.aligned.m8n8.x4.shared.b16 {%0,%1,%2,%3}, [%4];"
        : "=r"(r[0]), "=r"(r[1]), "=r"(r[2]), "=r"(r[3]) : "r"(addr));
}
__device__ __forceinline__ void mma16816(float* c, const unsigned* a, unsigned b0, unsigned b1){
    asm volatile("mma.sync.aligned.m16n8k16.row.col.f32.f16.f16.f32 "
        "{%0,%1,%2,%3}, {%4,%5,%6,%7}, {%8,%9}, {%0,%1,%2,%3};"
        : "+f"(c[0]), "+f"(c[1]), "+f"(c[2]), "+f"(c[3])
        : "r"(a[0]), "r"(a[1]), "r"(a[2]), "r"(a[3]), "r"(b0), "r"(b1));
}
__device__ __forceinline__ void split_h(float v0, float v1, __half* hi, __half* lo){
    __half h0 = __float2half_rn(v0), h1 = __float2half_rn(v1);
    *(__half2*)hi = __halves2half2(h0, h1);
    if (lo)
        *(__half2*)lo = __halves2half2(__float2half_rn(v0 - __half2float(h0)),
                                       __float2half_rn(v1 - __half2float(h1)));
}

// ================= 2-term split-fp16 HMMA GEMM =================
// CTA tile 128x64, 8 warps, warp tile 32x32, 3-stage cp.async, 1 sync/iter, 3 CTAs/SM.
// EPI: 0 fp32+bias | 2 f16+bias+relu (hi only) | 3 fp32+mask+row-stats | 5 f16split 3-seg bias (QKV)
template<int EPI, int AOFF, int BOFF, int COFF>
__global__ void __launch_bounds__(256, 3) gemm_mm(
    const __half* __restrict__ Ah, int lda, long long sAz,
    const __half* __restrict__ Bh, const __half* __restrict__ Bl, int ldb, long long sBz,
    float* __restrict__ Cf, __half* __restrict__ Chi, __half* __restrict__ Clo,
    long long sCz, int ldc,
    const float* __restrict__ bias, const float* __restrict__ bias2, const float* __restrict__ bias3,
    const int* __restrict__ mask, float2* __restrict__ stats, int K)
{
    constexpr int BN = 64;
    constexpr int NT = 4;
    constexpr int ABYTES = 128 * 80;   // 10240
    constexpr int BBYTES = BN * 80;    // 5120
    constexpr int BUFB = ABYTES + 2 * BBYTES;   // 20480
    extern __shared__ __align__(128) char smem[];
    const unsigned sb = s2u(smem);
    const int tid = threadIdx.x;
    const int m0 = blockIdx.y * 128, n0 = blockIdx.x * BN, z = blockIdx.z;

    size_t ao = (AOFF == 1) ? ((size_t)(z >> 4) * SEQ * lda + (size_t)(z & 15) * DK + (size_t)sAz)
                            : (size_t)z * sAz;
    size_t bo = (BOFF == 1) ? ((size_t)(z >> 4) * SEQ * ldb + (size_t)(z & 15) * DK + (size_t)sBz)
                            : (size_t)z * sBz;
    size_t co = (COFF == 1) ? ((size_t)(z >> 4) * SEQ * ldc + (size_t)(z & 15) * DK)
                            : (size_t)z * sCz;

    const int lane = tid & 31, w = tid >> 5;
    const int warp_m = w & 3, warp_n = w >> 2;   // 4 x 2 warps; warp tile 32 x 32

    float acc[2][NT][4];
#pragma unroll
    for (int mt = 0; mt < 2; mt++)
#pragma unroll
        for (int nt = 0; nt < NT; nt++)
#pragma unroll
            for (int e = 0; e < 4; e++) acc[mt][nt][e] = 0.f;

    const int nchunk = K >> 5;

    auto load_tile = [&](int c, int buf) {
        unsigned sbuf = sb + buf * BUFB;
        const __half* pah = Ah + ao + (size_t)m0 * lda + c * 32;
#pragma unroll
        for (int i = 0; i < 2; i++) {         // 128 rows x 4 chunks
            int idx = tid + i * 256;
            int row = idx >> 2, ch = idx & 3;
            cpa(sbuf + row * 80 + ch * 16, pah + (size_t)row * lda + ch * 8);
        }
        const __half* pbh = Bh + bo + (size_t)n0 * ldb + c * 32;
        const __half* pbl = Bl + bo + (size_t)n0 * ldb + c * 32;
        {                                     // 64 rows x 4 chunks = 256
            int row = tid >> 2, ch = tid & 3;
            unsigned so = row * 80 + ch * 16;
            cpa(sbuf + ABYTES + so,          pbh + (size_t)row * ldb + ch * 8);
            cpa(sbuf + ABYTES + BBYTES + so, pbl + (size_t)row * ldb + ch * 8);
        }
    };

    auto compute = [&](unsigned sbuf) {
        unsigned sa  = sbuf + (warp_m * 32 + (lane & 15)) * 80 + (lane >> 4) * 16;
        unsigned sbb = sbuf + ABYTES
                     + (warp_n * 32 + (lane & 7) + ((lane >> 4) << 3)) * 80
                     + ((lane >> 3) & 1) * 16;
#pragma unroll
        for (int ks = 0; ks < 2; ks++) {
            unsigned ah[2][4];
            ldmx4(ah[0], sa + ks * 32);
            ldmx4(ah[1], sa + 16 * 80 + ks * 32);
#pragma unroll
            for (int p = 0; p < 2; p++) {
                unsigned bh[4], bl[4];
                ldmx4(bh, sbb + p * 16 * 80 + ks * 32);
                ldmx4(bl, sbb + BBYTES + p * 16 * 80 + ks * 32);
#pragma unroll
                for (int mt = 0; mt < 2; mt++)
#pragma unroll
                    for (int t = 0; t < 2; t++) {
                        float* cc = acc[mt][2 * p + t];
                        mma16816(cc, ah[mt], bh[2 * t], bh[2 * t + 1]);
                        mma16816(cc, ah[mt], bl[2 * t], bl[2 * t + 1]);
                    }
            }
        }
    };

    load_tile(0, 0);
    asm volatile("cp.async.commit_group;");
    if (nchunk > 1) { load_tile(1, 1); asm volatile("cp.async.commit_group;"); }
    for (int c = 0; c < nchunk; c++) {
        if (c + 1 < nchunk) asm volatile("cp.async.wait_group 1;");
        else                asm volatile("cp.async.wait_group 0;");
        __syncthreads();
        if (c + 2 < nchunk) {
            load_tile(c + 2, (c + 2) % 3);
            asm volatile("cp.async.commit_group;");
        }
        compute(sb + (c % 3) * BUFB);
    }

    // -------- epilogue --------
    const int g = lane >> 2, q = lane & 3;
    if (EPI == 3) {
        __syncthreads();
        float* stg = (float*)smem;             // 128 x 64, pitch 68 (34816 B <= 61440)
#pragma unroll
        for (int mt = 0; mt < 2; mt++) {
            int sr = warp_m * 32 + mt * 16 + g;
#pragma unroll
            for (int nt = 0; nt < NT; nt++) {
                int sc = warp_n * 32 + nt * 8 + q * 2;
                stg[sr * 68 + sc]           = acc[mt][nt][0];
                stg[sr * 68 + sc + 1]       = acc[mt][nt][1];
                stg[(sr + 8) * 68 + sc]     = acc[mt][nt][2];
                stg[(sr + 8) * 68 + sc + 1] = acc[mt][nt][3];
            }
        }
        __syncthreads();
        const int* mrow = mask + (size_t)(z >> 4) * SEQ;
#pragma unroll
        for (int i = 0; i < 8; i++) {          // 128 x 64 floats / 256 thr / 4 per thr
            int idx = tid + i * 256, row = idx >> 4, c4 = (idx & 15) * 4;
            float4 v;
            v.x = stg[row * 68 + c4];
            v.y = stg[row * 68 + c4 + 1];
            v.z = stg[row * 68 + c4 + 2];
            v.w = stg[row * 68 + c4 + 3];
            int4 mk = *(const int4*)(mrow + n0 + c4);
            v.x = mk.x ? v.x : -1e9f;
            v.y = mk.y ? v.y : -1e9f;
            v.z = mk.z ? v.z : -1e9f;
            v.w = mk.w ? v.w : -1e9f;
            *(float4*)(Cf + co + (size_t)(m0 + row) * ldc + n0 + c4) = v;
        }
        {   // per-tile row stats: 2 threads per row x 32 cols each
            int row = tid >> 1, half = tid & 1;
            float m = -3.4e38f;
#pragma unroll 8
            for (int c2 = 0; c2 < 32; c2++) {
                float xv = stg[row * 68 + half * 32 + c2];
                if (mrow[n0 + half * 32 + c2] == 0) xv = -1e9f;
                m = fmaxf(m, xv);
            }
            float m2 = fmaxf(m, __shfl_xor_sync(0xffffffffu, m, 1));
            float s = 0.f;
#pragma unroll 8
            for (int c2 = 0; c2 < 32; c2++) {
                float xv = stg[row * 68 + half * 32 + c2];
                if (mrow[n0 + half * 32 + c2] == 0) xv = -1e9f;
                s += __expf(xv - m2);
            }
            s += __shfl_xor_sync(0xffffffffu, s, 1);
            if (half == 0)
                stats[((size_t)z * 32 + blockIdx.x) * SEQ + m0 + row] = make_float2(m2, s);
        }
        return;
    }
#pragma unroll
    for (int mt = 0; mt < 2; mt++) {
        int r0 = m0 + warp_m * 32 + mt * 16 + g;
#pragma unroll
        for (int nt = 0; nt < NT; nt++) {
            int col = n0 + warp_n * 32 + nt * 8 + q * 2;
            float c0 = acc[mt][nt][0], c1 = acc[mt][nt][1];
            float c2 = acc[mt][nt][2], c3 = acc[mt][nt][3];
            if (EPI == 0) {
                float b0v = bias[col], b1v = bias[col + 1];
                float2 v0, v1;
                v0.x = c0 + b0v; v0.y = c1 + b1v;
                v1.x = c2 + b0v; v1.y = c3 + b1v;
                *(float2*)(Cf + co + (size_t)r0 * ldc + col)       = v0;
                *(float2*)(Cf + co + (size_t)(r0 + 8) * ldc + col) = v1;
            } else {
                float b0v, b1v;
                if (EPI == 5) {
                    int seg = col >> 10, cc = col & 1023;
                    const float* bp = (seg == 0) ? bias : ((seg == 1) ? bias2 : bias3);
                    float sc = (seg == 0) ? 0.125f : 1.0f;
                    b0v = bp[cc] * sc; b1v = bp[cc + 1] * sc;
                } else {
                    b0v = bias[col]; b1v = bias[col + 1];
                }
                c0 += b0v; c1 += b1v; c2 += b0v; c3 += b1v;
                if (EPI == 2) {
                    c0 = fmaxf(c0, 0.f); c1 = fmaxf(c1, 0.f);
                    c2 = fmaxf(c2, 0.f); c3 = fmaxf(c3, 0.f);
                }
                size_t o0 = co + (size_t)r0 * ldc + col;
                size_t o1 = co + (size_t)(r0 + 8) * ldc + col;
                split_h(c0, c1, Chi + o0, Clo ? Clo + o0 : nullptr);
                split_h(c2, c3, Chi + o1, Clo ? Clo + o1 : nullptr);
            }
        }
    }
}

// ---------------- merge per-tile stats -> per-row (M, 1/S) ----------------
__global__ void __launch_bounds__(256) merge_stats(const float2* __restrict__ stats,
                                                   float2* __restrict__ MS)
{
    int idx = blockIdx.x * 256 + threadIdx.x;
    int z = idx >> 11, r = idx & 2047;
    const float2* sp = stats + (size_t)z * 32 * SEQ + r;
    float M = -3.4e38f;
#pragma unroll
    for (int jt = 0; jt < 32; jt++) M = fmaxf(M, sp[(size_t)jt * SEQ].x);
    float S = 0.f;
#pragma unroll
    for (int jt = 0; jt < 32; jt++) {
        float2 t = sp[(size_t)jt * SEQ];
        S += t.y * __expf(t.x - M);
    }
    MS[(size_t)z * SEQ + r] = make_float2(M, 1.0f / S);
}

// ================= ctx: normalize raw scores in place + 2-term GEMM with Vt =================
__global__ void __launch_bounds__(256, 3) ctx_mm(
    float* __restrict__ attn, const float2* __restrict__ MS,
    const __half* __restrict__ Bh, const __half* __restrict__ Bl,
    __half* __restrict__ Chi)
{
    constexpr int NT = 4;
    constexpr int ABYTES = 128 * 80;
    constexpr int BBYTES = 64 * 80;
    constexpr int BSTG = 2 * BBYTES;
    extern __shared__ __align__(128) char smem[];
    const unsigned sb = s2u(smem);
    const unsigned sbB = sb + 2 * ABYTES;
    const int tid = threadIdx.x;
    const int m0 = blockIdx.y * 128, z = blockIdx.z;
    float* ab = attn + (size_t)z * SEQ * SEQ;
    const size_t bo = (size_t)z * DK * SEQ;
    const size_t co = (size_t)(z >> 4) * SEQ * D_MODEL + (size_t)(z & 15) * DK;

    const int lane = tid & 31, w = tid >> 5;
    const int warp_m = w & 3, warp_n = w >> 2;

    float acc[2][NT][4];
#pragma unroll
    for (int mt = 0; mt < 2; mt++)
#pragma unroll
        for (int nt = 0; nt < NT; nt++)
#pragma unroll
            for (int e = 0; e < 4; e++) acc[mt][nt][e] = 0.f;

    const int arow = tid >> 3, ac4 = tid & 7;
    float2 ms[4];
#pragma unroll
    for (int i = 0; i < 4; i++) ms[i] = MS[(size_t)z * SEQ + m0 + arow + i * 32];

    float4 ra[4];
    auto loadA = [&](int c){
#pragma unroll
        for (int i = 0; i < 4; i++)
            ra[i] = *(const float4*)(ab + (size_t)(m0 + arow + i * 32) * SEQ + c * 32 + ac4 * 4);
    };
    auto storeA = [&](int c, int buf){
        char* bp = smem + buf * ABYTES;
#pragma unroll
        for (int i = 0; i < 4; i++) {
            float4 p;
            p.x = __expf(ra[i].x - ms[i].x) * ms[i].y;
            p.y = __expf(ra[i].y - ms[i].x) * ms[i].y;
            p.z = __expf(ra[i].z - ms[i].x) * ms[i].y;
            p.w = __expf(ra[i].w - ms[i].x) * ms[i].y;
            *(float4*)(ab + (size_t)(m0 + arow + i * 32) * SEQ + c * 32 + ac4 * 4) = p;
            __half2 h0 = __halves2half2(__float2half_rn(p.x), __float2half_rn(p.y));
            __half2 h1 = __halves2half2(__float2half_rn(p.z), __float2half_rn(p.w));
            uint2 uh;
            uh.x = *(unsigned*)&h0; uh.y = *(unsigned*)&h1;
            *(uint2*)(bp + (arow + i * 32) * 80 + ac4 * 8) = uh;
        }
    };
    auto loadB = [&](int c, int buf){
        unsigned sbuf = sbB + buf * BSTG;
        int row = tid >> 2, ch = tid & 3;
        unsigned so = row * 80 + ch * 16;
        cpa(sbuf + so,          Bh + bo + (size_t)row * SEQ + c * 32 + ch * 8);
        cpa(sbuf + BBYTES + so, Bl + bo + (size_t)row * SEQ + c * 32 + ch * 8);
    };

    loadA(0);
    loadB(0, 0);
    asm volatile("cp.async.commit_group;");
    loadB(1, 1);
    asm volatile("cp.async.commit_group;");

    const int nchunk = SEQ / 32;
    for (int c = 0; c < nchunk; c++) {
        storeA(c, c & 1);
        if (c + 1 < nchunk) loadA(c + 1);
        if (c + 1 < nchunk) asm volatile("cp.async.wait_group 1;");
        else                asm volatile("cp.async.wait_group 0;");
        __syncthreads();
        if (c + 2 < nchunk) {
            loadB(c + 2, (c + 2) % 3);
            asm volatile("cp.async.commit_group;");
        }

        unsigned sa  = sb + (c & 1) * ABYTES
                     + (warp_m * 32 + (lane & 15)) * 80 + (lane >> 4) * 16;
        unsigned sbb = sbB + (c % 3) * BSTG
                     + (warp_n * 32 + (lane & 7) + ((lane >> 4) << 3)) * 80
                     + ((lane >> 3) & 1) * 16;
#pragma unroll
        for (int ks = 0; ks < 2; ks++) {
            unsigned ah[2][4];
            ldmx4(ah[0], sa + ks * 32);
            ldmx4(ah[1], sa + 16 * 80 + ks * 32);
#pragma unroll
            for (int p = 0; p < 2; p++) {
                unsigned bh[4], bl[4];
                ldmx4(bh, sbb + p * 16 * 80 + ks * 32);
                ldmx4(bl, sbb + BBYTES + p * 16 * 80 + ks * 32);
#pragma unroll
                for (int mt = 0; mt < 2; mt++)
#pragma unroll
                    for (int t = 0; t < 2; t++) {
                        float* cc = acc[mt][2 * p + t];
                        mma16816(cc, ah[mt], bh[2 * t], bh[2 * t + 1]);
                        mma16816(cc, ah[mt], bl[2 * t], bl[2 * t + 1]);
                    }
            }
        }
    }

    const int g = lane >> 2, q = lane & 3;
#pragma unroll
    for (int mt = 0; mt < 2; mt++) {
        int r0 = m0 + warp_m * 32 + mt * 16 + g;
#pragma unroll
        for (int nt = 0; nt < NT; nt++) {
            int col = warp_n * 32 + nt * 8 + q * 2;
            size_t o0 = co + (size_t)r0 * D_MODEL + col;
            size_t o1 = co + (size_t)(r0 + 8) * D_MODEL + col;
            split_h(acc[mt][nt][0], acc[mt][nt][1], Chi + o0, nullptr);
            split_h(acc[mt][nt][2], acc[mt][nt][3], Chi + o1, nullptr);
        }
    }
}

// ---------------- fp32 -> fp16 (hi only) ----------------
__global__ void __launch_bounds__(256) conv_h(const float* __restrict__ in,
                                              __half* __restrict__ oh, int n4)
{
    int i = blockIdx.x * 256 + threadIdx.x;
    if (i >= n4) return;
    float4 v = ((const float4*)in)[i];
    ((__half2*)oh)[i * 2]     = __halves2half2(__float2half_rn(v.x), __float2half_rn(v.y));
    ((__half2*)oh)[i * 2 + 1] = __halves2half2(__float2half_rn(v.z), __float2half_rn(v.w));
}

// ---------------- transpose fp32 [R][C] -> fp16 hi/lo [C][R], with scale ----------------
__global__ void transp_split(const float* __restrict__ in, int ild,
                             __half* __restrict__ oh, __half* __restrict__ ol,
                             int old_, float scale)
{
    __shared__ float t[32][33];
    int r0 = blockIdx.y * 32, c0 = blockIdx.x * 32;
    int tx = threadIdx.x, ty = threadIdx.y;
#pragma unroll
    for (int i = 0; i < 32; i += 8) t[ty + i][tx] = in[(size_t)(r0 + ty + i) * ild + c0 + tx] * scale;
    __syncthreads();
#pragma unroll
    for (int i = 0; i < 32; i += 8) {
        float v = t[tx][ty + i];
        __half hh = __float2half_rn(v);
        size_t o = (size_t)(c0 + ty + i) * old_ + r0 + tx;
        oh[o] = hh;
        ol[o] = __float2half_rn(v - __half2float(hh));
    }
}

// ---------------- fused QKV weight transpose ----------------
__global__ void transp_w3(const float* __restrict__ Wq, const float* __restrict__ Wk,
                          const float* __restrict__ Wv,
                          __half* __restrict__ oh, __half* __restrict__ ol)
{
    __shared__ float t[32][33];
    int z = blockIdx.z;
    const float* in = (z == 0) ? Wq : (z == 1) ? Wk : Wv;
    float scale = (z == 0) ? 0.125f : 1.0f;
    size_t ob = (size_t)z * D_MODEL * D_MODEL;
    int r0 = blockIdx.y * 32, c0 = blockIdx.x * 32;
    int tx = threadIdx.x, ty = threadIdx.y;
#pragma unroll
    for (int i = 0; i < 32; i += 8) t[ty + i][tx] = in[(size_t)(r0 + ty + i) * D_MODEL + c0 + tx] * scale;
    __syncthreads();
#pragma unroll
    for (int i = 0; i < 32; i += 8) {
        float v = t[tx][ty + i];
        __half hh = __float2half_rn(v);
        size_t o = ob + (size_t)(c0 + ty + i) * D_MODEL + r0 + tx;
        oh[o] = hh;
        ol[o] = __float2half_rn(v - __half2float(hh));
    }
}

// ---------------- per-head V transpose from split-fp16 QKV ----------------
__global__ void transp_v(const __half* __restrict__ ih, const __half* __restrict__ il,
                         __half* __restrict__ oh, __half* __restrict__ ol)
{
    __shared__ __half th[32][33], tl[32][33];
    int z = blockIdx.z, b = z >> 4, h = z & 15;
    const size_t ib = (size_t)b * SEQ * QKV3 + 2048 + (size_t)h * DK;
    const size_t ob = (size_t)z * DK * SEQ;
    int r0 = blockIdx.y * 32, c0 = blockIdx.x * 32;
    int tx = threadIdx.x, ty = threadIdx.y;
#pragma unroll
    for (int i = 0; i < 32; i += 8) {
        size_t o = ib + (size_t)(r0 + ty + i) * QKV3 + c0 + tx;
        th[ty + i][tx] = ih[o];
        tl[ty + i][tx] = il[o];
    }
    __syncthreads();
#pragma unroll
    for (int i = 0; i < 32; i += 8) {
        size_t o = ob + (size_t)(c0 + ty + i) * SEQ + r0 + tx;
        oh[o] = th[tx][ty + i];
        ol[o] = tl[tx][ty + i];
    }
}

// ---------------- out = LayerNorm(X + Y), optional fp16 hi output ----------------
template<int SPLIT>
__global__ void __launch_bounds__(256) add_ln_kernel(const float* __restrict__ X,
                                                     const float* __restrict__ Y,
                                                     const float* __restrict__ gamma,
                                                     const float* __restrict__ beta,
                                                     float* __restrict__ out,
                                                     __half* __restrict__ oh)
{
    const int row = blockIdx.x;
    const int tid = threadIdx.x;
    const int lane = tid & 31, wid = tid >> 5;
    __shared__ float red[8];

    const float* xr = X + (size_t)row * D_MODEL;
    const float* yr = Y + (size_t)row * D_MODEL;
    float4 xv = *(const float4*)(xr + tid * 4);
    float4 yv = *(const float4*)(yr + tid * 4);
    float v0 = xv.x + yv.x, v1 = xv.y + yv.y, v2 = xv.z + yv.z, v3 = xv.w + yv.w;

    float s = v0 + v1 + v2 + v3;
#pragma unroll
    for (int o = 16; o > 0; o >>= 1) s += __shfl_xor_sync(0xffffffffu, s, o);
    if (lane == 0) red[wid] = s;
    __syncthreads();
    float tot = 0.f;
#pragma unroll
    for (int w = 0; w < 8; w++) tot += red[w];
    float mu = tot * (1.0f / D_MODEL);
    __syncthreads();

    float d0 = v0 - mu, d1 = v1 - mu, d2 = v2 - mu, d3 = v3 - mu;
    float sq = d0 * d0 + d1 * d1 + d2 * d2 + d3 * d3;
#pragma unroll
    for (int o = 16; o > 0; o >>= 1) sq += __shfl_xor_sync(0xffffffffu, sq, o);
    if (lane == 0) red[wid] = sq;
    __syncthreads();
    float vtot = 0.f;
#pragma unroll
    for (int w = 0; w < 8; w++) vtot += red[w];
    float inv = rsqrtf(vtot * (1.0f / D_MODEL) + EPS);

    float4 gv = *(const float4*)(gamma + tid * 4);
    float4 bv = *(const float4*)(beta + tid * 4);
    float o0 = d0 * inv * gv.x + bv.x;
    float o1 = d1 * inv * gv.y + bv.y;
    float o2 = d2 * inv * gv.z + bv.z;
    float o3 = d3 * inv * gv.w + bv.w;
    float4 o4; o4.x = o0; o4.y = o1; o4.z = o2; o4.w = o3;
    *(float4*)(out + (size_t)row * D_MODEL + tid * 4) = o4;
    if (SPLIT) {
        size_t base = (size_t)row * D_MODEL + tid * 4;
        ((__half2*)(oh + base))[0] = __halves2half2(__float2half_rn(o0), __float2half_rn(o1));
        ((__half2*)(oh + base))[1] = __halves2half2(__float2half_rn(o2), __float2half_rn(o3));
    }
}

// ---------------- host ----------------
#define GETP(var, sym) void* var; cudaGetSymbolAddress(&var, sym)
#define HF(p) ((__half*)(p))

extern "C" void kernel_launch(void* const* d_in, const int* in_sizes, int n_in,
                              void* d_out, int out_size)
{
    const float* x   = (const float*)d_in[0];
    const int*   msk = (const int*)  d_in[1];
    const float* Wq  = (const float*)d_in[2];
    const float* bq  = (const float*)d_in[3];
    const float* Wk  = (const float*)d_in[4];
    const float* bk  = (const float*)d_in[5];
    const float* Wv  = (const float*)d_in[6];
    const float* bv  = (const float*)d_in[7];
    const float* Wo  = (const float*)d_in[8];
    const float* bo  = (const float*)d_in[9];
    const float* g1  = (const float*)d_in[10];
    const float* be1 = (const float*)d_in[11];
    const float* W1  = (const float*)d_in[12];
    const float* b1  = (const float*)d_in[13];
    const float* W2  = (const float*)d_in[14];
    const float* b2  = (const float*)d_in[15];
    const float* g2  = (const float*)d_in[16];
    const float* be2 = (const float*)d_in[17];
    float* out = (float*)d_out;

    GETP(pT, g_t);      GETP(pH, g_h);     GETP(pAf, g_attn_f32);
    GETP(pSt, g_stats); GETP(pMS, g_MS);
    GETP(pxh, g_xc_h);
    GETP(pWh, g_Wqkv_h); GETP(pWl, g_Wqkv_l);
    GETP(pWoh, g_Wot_h); GETP(pWol, g_Wot_l);
    GETP(pW1h, g_W1t_h); GETP(pW1l, g_W1t_l);
    GETP(pW2h, g_W2t_h); GETP(pW2l, g_W2t_l);
    GETP(pQKVh, g_qkv_h); GETP(pQKVl, g_qkv_l);
    GETP(pVth, g_Vt_h); GETP(pVtl, g_Vt_l);
    GETP(pCh, g_ctx_h);
    GETP(pHh, g_hc_h);
    GETP(pFh, g_ff_h);

    const size_t OUT_ELEMS  = (size_t)ROWS * D_MODEL;
    const size_t ATTN_ELEMS = (size_t)HZ * SEQ * SEQ;
    float* attn = ((size_t)out_size >= OUT_ELEMS + ATTN_ELEMS) ? out + OUT_ELEMS : (float*)pAf;

    const int SMG  = 3 * (128 * 80 + 2 * 64 * 80);            // 61440
    const int SMCTX = 2 * (128 * 80) + 3 * (2 * 64 * 80);     // 51200
    cudaFuncSetAttribute(gemm_mm<5,0,0,0>, cudaFuncAttributeMaxDynamicSharedMemorySize, SMG);
    cudaFuncSetAttribute(gemm_mm<3,1,1,0>, cudaFuncAttributeMaxDynamicSharedMemorySize, SMG);
    cudaFuncSetAttribute(gemm_mm<0,0,0,0>, cudaFuncAttributeMaxDynamicSharedMemorySize, SMG);
    cudaFuncSetAttribute(gemm_mm<2,0,0,0>, cudaFuncAttributeMaxDynamicSharedMemorySize, SMG);
    cudaFuncSetAttribute(ctx_mm,           cudaFuncAttributeMaxDynamicSharedMemorySize, SMCTX);

    dim3 blk(256);
    dim3 tblk(32, 8);

    // 0: x -> fp16 hi
    conv_h<<<ROWS * D_MODEL / 4 / 256, blk>>>(x, HF(pxh), ROWS * D_MODEL / 4);
    // 1: QKV weights fused transpose (Wq pre-scaled by 0.125)
    transp_w3<<<dim3(32, 32, 3), tblk>>>(Wq, Wk, Wv, HF(pWh), HF(pWl));
    // 2: Wo transpose
    transp_split<<<dim3(32, 32), tblk>>>(Wo, D_MODEL, HF(pWoh), HF(pWol), D_MODEL, 1.0f);
    // 3: fused QKV GEMM (2-term)
    gemm_mm<5,0,0,0><<<dim3(QKV3 / 64, 32, 1), blk, SMG>>>(
        HF(pxh), D_MODEL, 0, HF(pWh), HF(pWl), D_MODEL, 0,
        nullptr, HF(pQKVh), HF(pQKVl), 0, QKV3, bq, bk, bv, nullptr, nullptr, D_MODEL);
    // 4: scores GEMM + per-tile stats
    gemm_mm<3,1,1,0><<<dim3(32, 16, HZ), blk, SMG>>>(
        HF(pQKVh), QKV3, 0, HF(pQKVh), HF(pQKVl), QKV3, 1024,
        attn, nullptr, nullptr, (long long)SEQ * SEQ, SEQ,
        nullptr, nullptr, nullptr, msk, (float2*)pSt, DK);
    // 5: merge stats
    merge_stats<<<HZ * SEQ / 256, blk>>>((const float2*)pSt, (float2*)pMS);
    // 6: V per-head transpose
    transp_v<<<dim3(2, 64, HZ), tblk>>>(HF(pQKVh), HF(pQKVl), HF(pVth), HF(pVtl));
    // 7: ctx (softmax fused)
    ctx_mm<<<dim3(1, 16, HZ), blk, SMCTX>>>(attn, (const float2*)pMS,
                                            HF(pVth), HF(pVtl), HF(pCh));
    // 8: O-proj, 9: LN1
    gemm_mm<0,0,0,0><<<dim3(16, 32, 1), blk, SMG>>>(
        HF(pCh), D_MODEL, 0, HF(pWoh), HF(pWol), D_MODEL, 0,
        (float*)pT, nullptr, nullptr, 0, D_MODEL, bo, nullptr, nullptr, nullptr, nullptr, D_MODEL);
    add_ln_kernel<1><<<ROWS, blk>>>(x, (const float*)pT, g1, be1, (float*)pH, HF(pHh));
    // 10-11: FFN weights
    transp_split<<<dim3(128, 32), tblk>>>(W1, DFF,     HF(pW1h), HF(pW1l), D_MODEL, 1.0f);
    transp_split<<<dim3(32, 128), tblk>>>(W2, D_MODEL, HF(pW2h), HF(pW2l), DFF, 1.0f);
    // 12: FF1, 13: FF2, 14: LN2
    gemm_mm<2,0,0,0><<<dim3(64, 32, 1), blk, SMG>>>(
        HF(pHh), D_MODEL, 0, HF(pW1h), HF(pW1l), D_MODEL, 0,
        nullptr, HF(pFh), nullptr, 0, DFF, b1, nullptr, nullptr, nullptr, nullptr, D_MODEL);
    gemm_mm<0,0,0,0><<<dim3(16, 32, 1), blk, SMG>>>(
        HF(pFh), DFF, 0, HF(pW2h), HF(pW2l), DFF, 0,
        (float*)pT, nullptr, nullptr, 0, D_MODEL, b2, nullptr, nullptr, nullptr, nullptr, DFF);
    add_ln_kernel<0><<<ROWS, blk>>>((const float*)pH, (const float*)pT, g2, be2, out, nullptr);
}